// round 11
// baseline (speedup 1.0000x reference)
#include <cuda_runtime.h>
#include <cstdint>

#define B_ 2
#define S_ 2048
#define D_ 1024
#define H_ 16
#define DK_ 64
#define DV_ 64
#define SEG_ 512
#define SL_ 128
#define L_ 768
#define NSEG_ 4

// ---------------- scratch (device globals: allocation-free) ----------------
__device__ float g_kqvf[(size_t)B_*S_*3072];       // full-seq proj, (b, s, h*192)
__device__ float g_stp [(size_t)B_*SL_*3072];      // state proj, (b, s, h*192)
__device__ float g_att1[(size_t)B_*H_*L_*64];
__device__ float g_kqv2[(size_t)B_*H_*L_*384];     // k2|q2|v2 per (b,h)
__device__ float g_a2r [(size_t)B_*NSEG_*SEG_*2048];
__device__ float g_a2e [(size_t)B_*SL_*2048];
__device__ float g_stA[(size_t)B_*SL_*D_];
__device__ float g_stB[(size_t)B_*SL_*D_];
__device__ float g_part[(size_t)4*1024*1024];
__device__ float g_WkqvF[(size_t)D_*3072];         // (d, h*192) all heads
__device__ float g_WstP [(size_t)D_*3072];
__device__ float g_W2ss [(size_t)H_*64*384];
__device__ float g_W2mid[(size_t)H_*64*384];
__device__ float g_W2se [(size_t)H_*64*384];

struct BTab { const float* p[8]; };

// ---------------- tf32 helpers ----------------
__device__ __forceinline__ uint32_t f2tf(float f) {
    uint32_t u;
    asm("cvt.rna.tf32.f32 %0, %1;" : "=r"(u) : "f"(f));
    return u;
}
__device__ __forceinline__ void mma8(float* c, const uint32_t* a, const uint32_t* b) {
    asm volatile(
        "mma.sync.aligned.m16n8k8.row.col.f32.tf32.tf32.f32 "
        "{%0,%1,%2,%3}, {%4,%5,%6,%7}, {%8,%9}, {%0,%1,%2,%3};\n"
        : "+f"(c[0]), "+f"(c[1]), "+f"(c[2]), "+f"(c[3])
        : "r"(a[0]), "r"(a[1]), "r"(a[2]), "r"(a[3]), "r"(b[0]), "r"(b[1]));
}
__device__ __forceinline__ int kperm(int k) {
    int j = k & 7;
    return (k & ~7) + ((j < 4) ? (j << 1) : ((j << 1) - 7));
}

// ---------------- batched strided tf32 tensor-core GEMM (BK=32, dyn smem) ----
template<int BM, int BN, int WM, int WN, bool TB>
__global__ void __launch_bounds__(256) gemm_t(
    const float* __restrict__ A, const float* __restrict__ Bm0, float* __restrict__ C,
    int M, int N, int K, int lda, int ldb, int ldc,
    long long aSB, long long aSH, long long bSB, long long bSH,
    long long cSB, long long cSH, int Hd, int Zr,
    int sk, int Kc, long long pcs, int useTab, BTab tab)
{
    constexpr int BK = 32;
    constexpr int KS = BK / 8;
    constexpr int MF = WM / 16;
    constexpr int NF = WN / 8;
    constexpr int WCOL = BN / WN;
    constexpr int NA4 = BM * BK / 1024;
    constexpr int NB4 = BN * BK / 1024;
    constexpr int KQ = BK / 4;
    constexpr int AW = BK + 4;

    extern __shared__ uint32_t smg[];
    uint32_t* Asb = smg;                       // [2][BM][AW]
    uint32_t* Bsb = smg + 2 * BM * AW;         // [2][BN][AW]

    int z = blockIdx.z;
    int ks = 0, zz = z;
    if (sk > 1) { ks = z / Zr; zz = z - ks * Zr; }
    int b = zz / Hd, h = zz - b * Hd;
    const float* Bm = useTab ? tab.p[blockIdx.y] : Bm0;
    A  += (long long)b * aSB + (long long)h * aSH;
    Bm += (long long)b * bSB + (long long)h * bSH;
    C  += (long long)ks * pcs + (long long)b * cSB + (long long)h * cSH;

    int row0 = blockIdx.y * BM;
    int col0 = blockIdx.x * BN;

    int kBeg = ks * Kc;
    int nk = Kc / BK;

    int tid = threadIdx.x;
    int w   = tid >> 5;
    int lane = tid & 31;
    int g = lane >> 2, q = lane & 3;
    int warpM = w / WCOL, warpN = w % WCOL;
    int wr = warpM * WM;
    int wc = warpN * WN;

    float4 ag[NA4], bg[NB4];

    {
        int kb = kBeg;
        #pragma unroll
        for (int i = 0; i < NA4; i++) {
            int f = tid + i * 256; int r = f / KQ; int c4 = (f % KQ) << 2;
            float4 v = *(const float4*)(A + (long long)(row0 + r) * lda + kb + c4);
            uint32_t* As0 = Asb + (long long)r * AW;
            As0[kperm(c4+0)] = f2tf(v.x);
            As0[kperm(c4+1)] = f2tf(v.y);
            As0[kperm(c4+2)] = f2tf(v.z);
            As0[kperm(c4+3)] = f2tf(v.w);
        }
        if (!TB) {
            #pragma unroll
            for (int i = 0; i < NB4; i++) {
                int f = tid + i * 256; int kr = f / (BN/4); int n4 = (f % (BN/4)) << 2;
                float4 v = *(const float4*)(Bm + (long long)(kb + kr) * ldb + col0 + n4);
                int kp = kperm(kr);
                Bsb[(n4+0)*AW + kp] = f2tf(v.x);
                Bsb[(n4+1)*AW + kp] = f2tf(v.y);
                Bsb[(n4+2)*AW + kp] = f2tf(v.z);
                Bsb[(n4+3)*AW + kp] = f2tf(v.w);
            }
        } else {
            #pragma unroll
            for (int i = 0; i < NB4; i++) {
                int f = tid + i * 256; int r = f / KQ; int c4 = (f % KQ) << 2;
                float4 v = *(const float4*)(Bm + (long long)(col0 + r) * ldb + kb + c4);
                uint32_t* Bs0 = Bsb + (long long)r * AW;
                Bs0[kperm(c4+0)] = f2tf(v.x);
                Bs0[kperm(c4+1)] = f2tf(v.y);
                Bs0[kperm(c4+2)] = f2tf(v.z);
                Bs0[kperm(c4+3)] = f2tf(v.w);
            }
        }
    }
    __syncthreads();

    float acc[MF][NF][4];
    #pragma unroll
    for (int i = 0; i < MF; i++)
        #pragma unroll
        for (int j = 0; j < NF; j++)
            #pragma unroll
            for (int e = 0; e < 4; e++) acc[i][j][e] = 0.f;

    int cur = 0;
    for (int t = 0; t < nk; t++) {
        if (t + 1 < nk) {
            int kb = kBeg + (t + 1) * BK;
            #pragma unroll
            for (int i = 0; i < NA4; i++) {
                int f = tid + i * 256; int r = f / KQ; int c4 = (f % KQ) << 2;
                ag[i] = *(const float4*)(A + (long long)(row0 + r) * lda + kb + c4);
            }
            if (!TB) {
                #pragma unroll
                for (int i = 0; i < NB4; i++) {
                    int f = tid + i * 256; int kr = f / (BN/4); int n4 = (f % (BN/4)) << 2;
                    bg[i] = *(const float4*)(Bm + (long long)(kb + kr) * ldb + col0 + n4);
                }
            } else {
                #pragma unroll
                for (int i = 0; i < NB4; i++) {
                    int f = tid + i * 256; int r = f / KQ; int c4 = (f % KQ) << 2;
                    bg[i] = *(const float4*)(Bm + (long long)(col0 + r) * ldb + kb + c4);
                }
            }
        }
        const uint32_t* As = Asb + (long long)cur * BM * AW;
        const uint32_t* Bs = Bsb + (long long)cur * BN * AW;
        #pragma unroll
        for (int s = 0; s < KS; s++) {
            uint32_t af[MF][4], bf[NF][2];
            #pragma unroll
            for (int i = 0; i < MF; i++) {
                uint2 lo = *(const uint2*)&As[(wr + 16*i + g    )*AW + 8*s + 2*q];
                uint2 hi = *(const uint2*)&As[(wr + 16*i + g + 8)*AW + 8*s + 2*q];
                af[i][0] = lo.x; af[i][1] = hi.x; af[i][2] = lo.y; af[i][3] = hi.y;
            }
            #pragma unroll
            for (int j = 0; j < NF; j++) {
                uint2 bb = *(const uint2*)&Bs[(wc + 8*j + g)*AW + 8*s + 2*q];
                bf[j][0] = bb.x; bf[j][1] = bb.y;
            }
            #pragma unroll
            for (int i = 0; i < MF; i++)
                #pragma unroll
                for (int j = 0; j < NF; j++)
                    mma8(acc[i][j], af[i], bf[j]);
        }
        if (t + 1 < nk) {
            int nxt = cur ^ 1;
            uint32_t* Asn = Asb + (long long)nxt * BM * AW;
            uint32_t* Bsn = Bsb + (long long)nxt * BN * AW;
            #pragma unroll
            for (int i = 0; i < NA4; i++) {
                int f = tid + i * 256; int r = f / KQ; int c4 = (f % KQ) << 2;
                uint32_t* p = Asn + (long long)r * AW;
                p[kperm(c4+0)] = f2tf(ag[i].x);
                p[kperm(c4+1)] = f2tf(ag[i].y);
                p[kperm(c4+2)] = f2tf(ag[i].z);
                p[kperm(c4+3)] = f2tf(ag[i].w);
            }
            if (!TB) {
                #pragma unroll
                for (int i = 0; i < NB4; i++) {
                    int f = tid + i * 256; int kr = f / (BN/4); int n4 = (f % (BN/4)) << 2;
                    int kp = kperm(kr);
                    Bsn[(n4+0)*AW + kp] = f2tf(bg[i].x);
                    Bsn[(n4+1)*AW + kp] = f2tf(bg[i].y);
                    Bsn[(n4+2)*AW + kp] = f2tf(bg[i].z);
                    Bsn[(n4+3)*AW + kp] = f2tf(bg[i].w);
                }
            } else {
                #pragma unroll
                for (int i = 0; i < NB4; i++) {
                    int f = tid + i * 256; int r = f / KQ; int c4 = (f % KQ) << 2;
                    uint32_t* p = Bsn + (long long)r * AW;
                    p[kperm(c4+0)] = f2tf(bg[i].x);
                    p[kperm(c4+1)] = f2tf(bg[i].y);
                    p[kperm(c4+2)] = f2tf(bg[i].z);
                    p[kperm(c4+3)] = f2tf(bg[i].w);
                }
            }
            __syncthreads();
            cur = nxt;
        }
    }

    #pragma unroll
    for (int i = 0; i < MF; i++) {
        #pragma unroll
        for (int j = 0; j < NF; j++) {
            int r0 = row0 + wr + 16*i + g;
            int c0 = col0 + wc + 8*j + 2*q;
            *(float2*)(C + (long long)r0 * ldc + c0) = make_float2(acc[i][j][0], acc[i][j][1]);
            *(float2*)(C + (long long)(r0 + 8) * ldc + c0) = make_float2(acc[i][j][2], acc[i][j][3]);
        }
    }
}

// ---------------- fused flash attention (tf32 mma, online softmax) ----------
template<int DH, bool GATHER>
__global__ void __launch_bounds__(256) flash_k(
    const float* __restrict__ b1, const float* __restrict__ b2, int ld,
    long long b1S, long long b2S, int qoff0, int koff0, int voff0,
    float* __restrict__ out0, long long o0b, float* __restrict__ out1,
    int rbOff, int nRB, long long sIn, long long sOut, int hstep)
{
    constexpr int BR = 128, BC = 64;
    constexpr int QW = DH + 4, KW = DH + 4, VW = BC + 4, SW = BC + 4;
    extern __shared__ uint32_t sm[];
    uint32_t* Qs = sm;
    uint32_t* Ks = Qs + BR * QW;
    uint32_t* Vs = Ks + BC * KW;
    uint32_t* Ss = Vs + DH * VW;

    int bh = blockIdx.y;
    int b = bh / H_, h = bh - b * H_;

    int segi = blockIdx.x / nRB;
    int rb   = blockIdx.x - segi * nRB;

    int baseIdx = hstep ? b : bh;
    int hoff = h * hstep;
    int qoff = qoff0 + hoff, koff = koff0 + hoff, voff = voff0 + hoff;

    const float* stb  = b1 + (GATHER ? segi * sIn : 0) + (long long)baseIdx * b1S;
    const float* segb = GATHER ? stb : (b2 + (long long)baseIdx * b2S);
    float* o0 = out0 + (GATHER ? segi * sOut : 0);

    int row0 = (GATHER ? (rb + rbOff) : blockIdx.x) * BR;

    const float* Qb;
    if (GATHER) {
        Qb = stb + (long long)row0 * ld;
    } else {
        if (row0 < SL_)            Qb = stb;
        else if (row0 < SL_+SEG_)  Qb = segb + (long long)(row0 - SL_) * ld;
        else                       Qb = stb;
    }

    int tid = threadIdx.x, w = tid >> 5, lane = tid & 31;
    int g = lane >> 2, q = lane & 3;
    int wr = w * 16;

    constexpr int NQ4 = BR * DH / 1024;
    #pragma unroll
    for (int i = 0; i < NQ4; i++) {
        int f = tid + i * 256; int r = f / (DH/4); int c4 = (f % (DH/4)) << 2;
        float4 v = *(const float4*)(Qb + (long long)r * ld + qoff + c4);
        Qs[r*QW + kperm(c4+0)] = f2tf(v.x);
        Qs[r*QW + kperm(c4+1)] = f2tf(v.y);
        Qs[r*QW + kperm(c4+2)] = f2tf(v.z);
        Qs[r*QW + kperm(c4+3)] = f2tf(v.w);
    }

    float Ofr[DH/8][4];
    #pragma unroll
    for (int j = 0; j < DH/8; j++)
        #pragma unroll
        for (int e = 0; e < 4; e++) Ofr[j][e] = 0.f;
    float m_a = -1e30f, m_b = -1e30f, l_a = 0.f, l_b = 0.f;
    int row_a = row0 + wr + g, row_b = row_a + 8;

    int nb = row0 / BC + 2;
    constexpr int NK4 = BC * DH / 1024;

    for (int cb = 0; cb < nb; cb++) {
        int c0 = cb * BC;
        const float* Kb;
        if (GATHER) {
            Kb = stb + (long long)c0 * ld;
        } else {
            if (c0 < SL_)            Kb = stb + (long long)c0 * ld;
            else if (c0 < SL_+SEG_)  Kb = segb + (long long)(c0 - SL_) * ld;
            else                     Kb = stb + (long long)(c0 - SL_ - SEG_) * ld;
        }
        __syncthreads();
        #pragma unroll
        for (int i = 0; i < NK4; i++) {
            int f = tid + i * 256; int r = f / (DH/4); int c4 = (f % (DH/4)) << 2;
            float4 v = *(const float4*)(Kb + (long long)r * ld + koff + c4);
            Ks[r*KW + kperm(c4+0)] = f2tf(v.x);
            Ks[r*KW + kperm(c4+1)] = f2tf(v.y);
            Ks[r*KW + kperm(c4+2)] = f2tf(v.z);
            Ks[r*KW + kperm(c4+3)] = f2tf(v.w);
        }
        #pragma unroll
        for (int i = 0; i < NK4; i++) {
            int f = tid + i * 256; int c = f / (DH/4); int d4 = (f % (DH/4)) << 2;
            float4 v = *(const float4*)(Kb + (long long)c * ld + voff + d4);
            int kp = kperm(c);
            Vs[(d4+0)*VW + kp] = f2tf(v.x);
            Vs[(d4+1)*VW + kp] = f2tf(v.y);
            Vs[(d4+2)*VW + kp] = f2tf(v.z);
            Vs[(d4+3)*VW + kp] = f2tf(v.w);
        }
        __syncthreads();

        float sfr[BC/8][4];
        #pragma unroll
        for (int j = 0; j < BC/8; j++)
            #pragma unroll
            for (int e = 0; e < 4; e++) sfr[j][e] = 0.f;
        #pragma unroll
        for (int s = 0; s < DH/8; s++) {
            uint32_t af[4];
            uint2 lo = *(const uint2*)&Qs[(wr+g  )*QW + 8*s + 2*q];
            uint2 hi = *(const uint2*)&Qs[(wr+g+8)*QW + 8*s + 2*q];
            af[0] = lo.x; af[1] = hi.x; af[2] = lo.y; af[3] = hi.y;
            #pragma unroll
            for (int j = 0; j < BC/8; j++) {
                uint2 bb = *(const uint2*)&Ks[(8*j+g)*KW + 8*s + 2*q];
                uint32_t bf[2] = {bb.x, bb.y};
                mma8(sfr[j], af, bf);
            }
        }

        bool needm = (c0 + BC - 1 > row0 + wr);
        float mb_a = -1e30f, mb_b = -1e30f;
        #pragma unroll
        for (int j = 0; j < BC/8; j++) {
            int col = c0 + 8*j + 2*q;
            float s0 = sfr[j][0]*0.125f, s1 = sfr[j][1]*0.125f;
            float s2 = sfr[j][2]*0.125f, s3 = sfr[j][3]*0.125f;
            if (needm) {
                if (col     > row_a) s0 = -1e30f;
                if (col + 1 > row_a) s1 = -1e30f;
                if (col     > row_b) s2 = -1e30f;
                if (col + 1 > row_b) s3 = -1e30f;
            }
            sfr[j][0]=s0; sfr[j][1]=s1; sfr[j][2]=s2; sfr[j][3]=s3;
            mb_a = fmaxf(mb_a, fmaxf(s0, s1));
            mb_b = fmaxf(mb_b, fmaxf(s2, s3));
        }
        mb_a = fmaxf(mb_a, __shfl_xor_sync(0xffffffffu, mb_a, 1));
        mb_a = fmaxf(mb_a, __shfl_xor_sync(0xffffffffu, mb_a, 2));
        mb_b = fmaxf(mb_b, __shfl_xor_sync(0xffffffffu, mb_b, 1));
        mb_b = fmaxf(mb_b, __shfl_xor_sync(0xffffffffu, mb_b, 2));
        float mn_a = fmaxf(m_a, mb_a), mn_b = fmaxf(m_b, mb_b);
        float ra = __expf(m_a - mn_a), rb2 = __expf(m_b - mn_b);
        float sa = 0.f, sb = 0.f;
        #pragma unroll
        for (int j = 0; j < BC/8; j++) {
            float p0 = __expf(sfr[j][0] - mn_a), p1 = __expf(sfr[j][1] - mn_a);
            float p2 = __expf(sfr[j][2] - mn_b), p3 = __expf(sfr[j][3] - mn_b);
            sa += p0 + p1; sb += p2 + p3;
            int cc = 8*j + 2*q;
            Ss[(wr+g  )*SW + kperm(cc  )] = f2tf(p0);
            Ss[(wr+g  )*SW + kperm(cc+1)] = f2tf(p1);
            Ss[(wr+g+8)*SW + kperm(cc  )] = f2tf(p2);
            Ss[(wr+g+8)*SW + kperm(cc+1)] = f2tf(p3);
        }
        sa += __shfl_xor_sync(0xffffffffu, sa, 1);
        sa += __shfl_xor_sync(0xffffffffu, sa, 2);
        sb += __shfl_xor_sync(0xffffffffu, sb, 1);
        sb += __shfl_xor_sync(0xffffffffu, sb, 2);
        l_a = l_a * ra + sa; l_b = l_b * rb2 + sb;
        m_a = mn_a; m_b = mn_b;
        #pragma unroll
        for (int j2 = 0; j2 < DH/8; j2++) {
            Ofr[j2][0] *= ra; Ofr[j2][1] *= ra;
            Ofr[j2][2] *= rb2; Ofr[j2][3] *= rb2;
        }
        __syncwarp();

        #pragma unroll
        for (int s = 0; s < BC/8; s++) {
            uint32_t af[4];
            uint2 lo = *(const uint2*)&Ss[(wr+g  )*SW + 8*s + 2*q];
            uint2 hi = *(const uint2*)&Ss[(wr+g+8)*SW + 8*s + 2*q];
            af[0] = lo.x; af[1] = hi.x; af[2] = lo.y; af[3] = hi.y;
            #pragma unroll
            for (int j2 = 0; j2 < DH/8; j2++) {
                uint2 bb = *(const uint2*)&Vs[(8*j2+g)*VW + 8*s + 2*q];
                uint32_t bf[2] = {bb.x, bb.y};
                mma8(Ofr[j2], af, bf);
            }
        }
    }

    float ia = 1.f / l_a, ib = 1.f / l_b;
    if (!GATHER) {
        float* oa = out0 + (long long)bh * L_ * DH + (long long)row_a * DH;
        float* ob = out0 + (long long)bh * L_ * DH + (long long)row_b * DH;
        #pragma unroll
        for (int j2 = 0; j2 < DH/8; j2++) {
            int col = 8*j2 + 2*q;
            *(float2*)(oa + col) = make_float2(Ofr[j2][0]*ia, Ofr[j2][1]*ia);
            *(float2*)(ob + col) = make_float2(Ofr[j2][2]*ib, Ofr[j2][3]*ib);
        }
    } else {
        #pragma unroll
        for (int rr = 0; rr < 2; rr++) {
            int s_abs = (rr == 0) ? row_a : row_b;
            float inv = (rr == 0) ? ia : ib;
            float* dst;
            if (s_abs < SL_ + SEG_) {
                int s = s_abs - SL_;
                dst = o0 + (long long)b * o0b
                    + (long long)((h << 5) + (s >> 4)) * 2048 + ((s & 15) << 7);
            } else {
                int s = s_abs - (SL_ + SEG_);
                dst = out1 + ((long long)b * SL_ + (h << 3) + (s >> 4)) * 2048
                    + ((s & 15) << 7);
            }
            #pragma unroll
            for (int j2 = 0; j2 < DH/8; j2++) {
                int col = 8*j2 + 2*q;
                float v0 = Ofr[j2][rr ? 2 : 0] * inv;
                float v1 = Ofr[j2][rr ? 3 : 1] * inv;
                *(float2*)(dst + col) = make_float2(v0, v1);
            }
        }
    }
}

// generic split-K reduce
__global__ void reduceK(float* __restrict__ C, const float* __restrict__ part,
    int sk, long long chunk, int M, int N, int ldc,
    long long cSB, long long cSH, int Hd)
{
    long long idx = (long long)blockIdx.x * blockDim.x + threadIdx.x;
    if (idx >= chunk) return;
    int n = (int)(idx % N);
    long long t = idx / N;
    int m = (int)(t % M);
    int zz = (int)(t / M);
    int b = zz / Hd, h = zz - b * Hd;
    float s = 0.f;
    for (int i = 0; i < sk; i++) s += part[(long long)i * chunk + idx];
    C[(long long)b * cSB + (long long)h * cSH + (long long)m * ldc + n] = s;
}

// pack all-head weights: dst[d][h*192 + o*64 + c] = src_o[h][d][c]
__global__ void packH(float* __restrict__ dst, const float* __restrict__ s0,
                      const float* __restrict__ s1, const float* __restrict__ s2)
{
    int idx = blockIdx.x * blockDim.x + threadIdx.x;
    const int tot = D_ * 3072;
    if (idx >= tot) return;
    int c = idx & 63;
    int o = (idx >> 6) % 3;
    int h = (idx / 192) & 15;
    int d = idx / 3072;
    const float* s = (o == 0) ? s0 : ((o == 1) ? s1 : s2);
    dst[idx] = s[((size_t)h * D_ + d) * 64 + c];
}

__global__ void pack3(float* __restrict__ dst, const float* __restrict__ s0,
                      const float* __restrict__ s1, const float* __restrict__ s2,
                      int n, int w)
{
    int idx = blockIdx.x * blockDim.x + threadIdx.x;
    int tot = n * 3 * w;
    if (idx >= tot) return;
    int c = idx % w; int o = (idx / w) % 3; int i = idx / (3 * w);
    const float* s = (o == 0) ? s0 : ((o == 1) ? s1 : s2);
    dst[idx] = s[(size_t)i * w + c];
}

__global__ void bcast_state(float* __restrict__ st, const float* __restrict__ state)
{
    int idx = blockIdx.x * blockDim.x + threadIdx.x;
    const int total = B_ * SL_ * D_;
    if (idx >= total) return;
    st[idx] = state[idx % (SL_ * D_)];
}

__global__ void copy_f(float* __restrict__ dst, const float* __restrict__ src, int n)
{
    int idx = blockIdx.x * blockDim.x + threadIdx.x;
    if (idx < n) dst[idx] = src[idx];
}

// ---------------- host ----------------
static float* s_part = nullptr;

static void G(bool tb, const float* A, const float* Bm, float* C,
              int M, int N, int K, int lda, int ldb, int ldc,
              long long aSB, long long aSH, long long bSB, long long bSH,
              long long cSB, long long cSH, int Hd, int Z, int sk = 1,
              int useTab = 0, BTab tab = {})
{
    int Kc = K / sk;
    long long pcs = 0;
    float* Cout = C;
    long long csb = cSB, csh = cSH;
    int ldc2 = ldc;
    if (sk > 1) {
        pcs = (long long)Z * M * N;
        Cout = s_part; ldc2 = N;
        csh = (long long)M * N;
        csb = (long long)Hd * M * N;
    }
    dim3 blk(256);
    const int SM_BB = (2*128*36 + 2*128*36) * 4;  // 73728 (BM=BN=128)
    const int SM_BS = (2*128*36 + 2*64*36) * 4;   // 55296 (BM=128, BN=64)
    if (N % 128 == 0) {
        dim3 grid(N / 128, (M + 127) / 128, Z * sk);
        if (tb) {
            cudaFuncSetAttribute(gemm_t<128,128,64,32,true>,
                cudaFuncAttributeMaxDynamicSharedMemorySize, SM_BB);
            gemm_t<128,128,64,32,true ><<<grid, blk, SM_BB>>>(A, Bm, Cout, M, N, K, lda, ldb, ldc2,
                aSB, aSH, bSB, bSH, csb, csh, Hd, Z, sk, Kc, pcs, useTab, tab);
        } else {
            cudaFuncSetAttribute(gemm_t<128,128,64,32,false>,
                cudaFuncAttributeMaxDynamicSharedMemorySize, SM_BB);
            gemm_t<128,128,64,32,false><<<grid, blk, SM_BB>>>(A, Bm, Cout, M, N, K, lda, ldb, ldc2,
                aSB, aSH, bSB, bSH, csb, csh, Hd, Z, sk, Kc, pcs, useTab, tab);
        }
    } else {
        dim3 grid(N / 64, (M + 127) / 128, Z * sk);
        if (tb) {
            cudaFuncSetAttribute(gemm_t<128,64,32,32,true>,
                cudaFuncAttributeMaxDynamicSharedMemorySize, SM_BS);
            gemm_t<128,64,32,32,true ><<<grid, blk, SM_BS>>>(A, Bm, Cout, M, N, K, lda, ldb, ldc2,
                aSB, aSH, bSB, bSH, csb, csh, Hd, Z, sk, Kc, pcs, useTab, tab);
        } else {
            cudaFuncSetAttribute(gemm_t<128,64,32,32,false>,
                cudaFuncAttributeMaxDynamicSharedMemorySize, SM_BS);
            gemm_t<128,64,32,32,false><<<grid, blk, SM_BS>>>(A, Bm, Cout, M, N, K, lda, ldb, ldc2,
                aSB, aSH, bSB, bSH, csb, csh, Hd, Z, sk, Kc, pcs, useTab, tab);
        }
    }
    if (sk > 1) {
        long long chunk = (long long)Z * M * N;
        reduceK<<<(unsigned)((chunk + 255) / 256), 256>>>(C, s_part, sk, chunk,
            M, N, ldc, cSB, cSH, Hd);
    }
}

extern "C" void kernel_launch(void* const* d_in, const int* in_sizes, int n_in,
                              void* d_out, int out_size)
{
    const float* x       = (const float*)d_in[0];
    const float* state   = (const float*)d_in[1];
    const float* Wk      = (const float*)d_in[2];
    const float* Wq      = (const float*)d_in[3];
    const float* Wv      = (const float*)d_in[4];
    const float* W2k     = (const float*)d_in[5];
    const float* Wout    = (const float*)d_in[6];
    const float* Wk_st   = (const float*)d_in[7];
    const float* Wq_st   = (const float*)d_in[8];
    const float* Wv_st   = (const float*)d_in[9];
    const float* W2k_ss  = (const float*)d_in[10];
    const float* W2q_ss  = (const float*)d_in[11];
    const float* W2v_ss  = (const float*)d_in[12];
    const float* W2k_se  = (const float*)d_in[13];
    const float* W2q_se  = (const float*)d_in[14];
    const float* W2v_se  = (const float*)d_in[15];
    const float* Wout_st = (const float*)d_in[16];
    float* out = (float*)d_out;

    float *kqvf,*stp,*att1,*kqv2,*a2r,*a2e,*stA,*stB;
    float *WkqvF,*WstP,*W2ss,*W2mid,*W2se;
    cudaGetSymbolAddress((void**)&kqvf, g_kqvf);
    cudaGetSymbolAddress((void**)&stp,  g_stp);
    cudaGetSymbolAddress((void**)&att1, g_att1);
    cudaGetSymbolAddress((void**)&kqv2, g_kqv2);
    cudaGetSymbolAddress((void**)&a2r,  g_a2r);
    cudaGetSymbolAddress((void**)&a2e,  g_a2e);
    cudaGetSymbolAddress((void**)&stA,  g_stA);
    cudaGetSymbolAddress((void**)&stB,  g_stB);
    cudaGetSymbolAddress((void**)&s_part, g_part);
    cudaGetSymbolAddress((void**)&WkqvF, g_WkqvF);
    cudaGetSymbolAddress((void**)&WstP,  g_WstP);
    cudaGetSymbolAddress((void**)&W2ss,  g_W2ss);
    cudaGetSymbolAddress((void**)&W2mid, g_W2mid);
    cudaGetSymbolAddress((void**)&W2se,  g_W2se);

    const int SM64  = (128*68 + 64*68 + 64*68 + 128*68) * 4;    // 104448
    const int SM128 = (128*132 + 64*132 + 128*68 + 128*68) * 4; // 171008
    cudaFuncSetAttribute(flash_k<64,false>,  cudaFuncAttributeMaxDynamicSharedMemorySize, SM64);
    cudaFuncSetAttribute(flash_k<128,true>,  cudaFuncAttributeMaxDynamicSharedMemorySize, SM128);

    bcast_state<<<(B_*SL_*D_ + 255)/256, 256>>>(stA, state);
    packH<<<(D_*3072 + 255)/256, 256>>>(WkqvF, Wk, Wq, Wv);
    packH<<<(D_*3072 + 255)/256, 256>>>(WstP, Wk_st, Wq_st, Wv_st);
    pack3<<<(H_*64*384 + 255)/256, 256>>>(W2ss,  W2k_ss, W2q_ss, W2v_ss, H_*64, 128);
    pack3<<<(H_*64*384 + 255)/256, 256>>>(W2mid, W2k,    W2k,    W2k,    H_*64, 128);

    // mega full-sequence projection: (B*S x 1024) @ (1024 x 3072)
    G(false, x, WkqvF, kqvf, B_*S_, 3072, D_, D_, 3072, 3072,
      0, 0, 0, 0, 0, 0, 1, 1);

    pack3<<<(H_*64*384 + 255)/256, 256>>>(W2se,  W2k_se, W2q_se, W2v_se, H_*64, 128);

    BTab tab2; // level-2 projections: rows 0-127 ss, 128-639 mid, 640-767 se
    tab2.p[0] = W2ss; tab2.p[1] = W2mid; tab2.p[2] = W2mid;
    tab2.p[3] = W2mid; tab2.p[4] = W2mid; tab2.p[5] = W2se;
    tab2.p[6] = W2mid; tab2.p[7] = W2mid;

    bool tailFits = (out_size >= B_*S_*D_ + B_*SL_*D_);

    for (int seg = 0; seg < NSEG_; seg++) {
        float* stc = (seg & 1) ? stB : stA;
        float* stn = (seg & 1) ? stA : stB;
        if (seg == NSEG_-1 && tailFits) stn = out + (size_t)B_*S_*D_;

        // state projection: one GEMM (B*SL x 1024) @ (1024 x 3072), split-K x2
        G(false, stc, WstP, stp, B_*SL_, 3072, D_, D_, 3072, 3072,
          0, 0, 0, 0, 0, 0, 1, 1, 2);

        // attention 1: region-mapped flash over [stp ; kqvf+segoff ; stp], hstep=192
        flash_k<64,false><<<dim3(L_/128, B_*H_), 256, SM64>>>(
            stp, kqvf + (long long)seg*SEG_*3072, 3072,
            (long long)SL_*3072, (long long)S_*3072, 64, 0, 128,
            att1, 0, nullptr, 0, L_/128, 0, 0, 192);

        // level-2 projections: single launch, per-row-block weights
        G(false, att1, nullptr, kqv2, L_, 384, DV_, DV_, 384, 384,
          (long long)H_*L_*DV_, (long long)L_*DV_, 0, (long long)64*384,
          (long long)H_*L_*384, (long long)L_*384, H_, B_*H_, 1, 1, tab2);

        // attention 2 (full, in-loop): a2 -> per-seg buffer, a2e -> a2e
        flash_k<128,true><<<dim3(L_/128 - 1, B_*H_), 256, SM128>>>(
            kqv2, nullptr, 384, (long long)L_*384, 0, 128, 0, 256,
            a2r + (long long)seg*SEG_*2048, (long long)NSEG_*SEG_*2048, a2e,
            1, L_/128 - 1, 0, 0, 0);

        // next state (split-K x8)
        G(false, a2e, Wout_st, stn, SL_, D_, 2048, 2048, D_, D_,
          (long long)SL_*2048, 0, 0, 0, (long long)SL_*D_, 0, 1, B_, 8);
    }

    // deferred: all out-segment projections in ONE batched GEMM (Z = B*NSEG)
    G(false, a2r, Wout, out, SEG_, D_, 2048, 2048, D_, D_,
      (long long)NSEG_*SEG_*2048, (long long)SEG_*2048, 0, 0,
      (long long)S_*D_, (long long)SEG_*D_, NSEG_, B_*NSEG_);

    if (!tailFits) {
        int st_elems = B_ * SL_ * D_;
        if (out_size >= B_*S_*D_ + st_elems) {
            copy_f<<<(st_elems + 255)/256, 256>>>(out + (size_t)B_*S_*D_, stA, st_elems);
        }
    }
}

// round 12
// speedup vs baseline: 1.0673x; 1.0673x over previous
#include <cuda_runtime.h>
#include <cstdint>

#define B_ 2
#define S_ 2048
#define D_ 1024
#define H_ 16
#define DK_ 64
#define DV_ 64
#define SEG_ 512
#define SL_ 128
#define L_ 768
#define NSEG_ 4

// ---------------- scratch (device globals: allocation-free) ----------------
__device__ float g_kqvf[(size_t)B_*H_*S_*192];     // full-seq K|Q|V interleaved
__device__ float g_stp [(size_t)B_*H_*SL_*192];    // state K|Q|V projection
__device__ float g_att1[(size_t)B_*H_*L_*64];
__device__ float g_kqv2[(size_t)B_*H_*L_*384];     // k2|q2|v2 interleaved
__device__ float g_a2r [(size_t)B_*NSEG_*SEG_*2048]; // gathered a2, all segments
__device__ float g_a2e [(size_t)B_*SL_*2048];      // gathered a2e, current segment
__device__ float g_stA[(size_t)B_*SL_*D_];
__device__ float g_stB[(size_t)B_*SL_*D_];
__device__ float g_part[(size_t)4*1024*1024];
__device__ float g_WkqvF[(size_t)H_*D_*192];
__device__ float g_WstP [(size_t)H_*D_*192];
__device__ float g_W2ss [(size_t)H_*64*384];
__device__ float g_W2mid[(size_t)H_*64*384];
__device__ float g_W2se [(size_t)H_*64*384];

struct BTab { const float* p[8]; };

// ---------------- tf32 helpers ----------------
__device__ __forceinline__ uint32_t f2tf(float f) {
    uint32_t u;
    asm("cvt.rna.tf32.f32 %0, %1;" : "=r"(u) : "f"(f));
    return u;
}
__device__ __forceinline__ void mma8(float* c, const uint32_t* a, const uint32_t* b) {
    asm volatile(
        "mma.sync.aligned.m16n8k8.row.col.f32.tf32.tf32.f32 "
        "{%0,%1,%2,%3}, {%4,%5,%6,%7}, {%8,%9}, {%0,%1,%2,%3};\n"
        : "+f"(c[0]), "+f"(c[1]), "+f"(c[2]), "+f"(c[3])
        : "r"(a[0]), "r"(a[1]), "r"(a[2]), "r"(a[3]), "r"(b[0]), "r"(b[1]));
}
__device__ __forceinline__ int kperm(int k) {
    int j = k & 7;
    return (k & ~7) + ((j < 4) ? (j << 1) : ((j << 1) - 7));
}

// ---------------- batched strided tf32 tensor-core GEMM (BK=16) ----------------
template<int BM, int BN, int WM, int WN, bool TB>
__global__ void __launch_bounds__(256) gemm_t(
    const float* __restrict__ A, const float* __restrict__ Bm0, float* __restrict__ C,
    int M, int N, int K, int lda, int ldb, int ldc,
    long long aSB, long long aSH, long long bSB, long long bSH,
    long long cSB, long long cSH, int Hd, int Zr,
    int sk, int Kc, long long pcs, int useTab, BTab tab)
{
    constexpr int BK = 16;
    constexpr int KS = BK / 8;
    constexpr int MF = WM / 16;
    constexpr int NF = WN / 8;
    constexpr int WCOL = BN / WN;
    constexpr int NA4 = BM * BK / 1024;
    constexpr int NB4 = BN * BK / 1024;
    constexpr int KQ = BK / 4;

    int z = blockIdx.z;
    int ks = 0, zz = z;
    if (sk > 1) { ks = z / Zr; zz = z - ks * Zr; }
    int b = zz / Hd, h = zz - b * Hd;
    const float* Bm = useTab ? tab.p[blockIdx.y] : Bm0;
    A  += (long long)b * aSB + (long long)h * aSH;
    Bm += (long long)b * bSB + (long long)h * bSH;
    C  += (long long)ks * pcs + (long long)b * cSB + (long long)h * cSH;

    int row0 = blockIdx.y * BM;
    int col0 = blockIdx.x * BN;

    int kBeg = ks * Kc;
    int nk = Kc / BK;

    __shared__ uint32_t As[2][BM][BK + 4];
    __shared__ uint32_t Bs[2][BN][BK + 4];

    int tid = threadIdx.x;
    int w   = tid >> 5;
    int lane = tid & 31;
    int g = lane >> 2, q = lane & 3;
    int warpM = w / WCOL, warpN = w % WCOL;
    int wr = warpM * WM;
    int wc = warpN * WN;

    float4 ag[NA4], bg[NB4];

    {
        int kb = kBeg;
        #pragma unroll
        for (int i = 0; i < NA4; i++) {
            int f = tid + i * 256; int r = f / KQ; int c4 = (f % KQ) << 2;
            float4 v = *(const float4*)(A + (long long)(row0 + r) * lda + kb + c4);
            As[0][r][kperm(c4+0)] = f2tf(v.x);
            As[0][r][kperm(c4+1)] = f2tf(v.y);
            As[0][r][kperm(c4+2)] = f2tf(v.z);
            As[0][r][kperm(c4+3)] = f2tf(v.w);
        }
        if (!TB) {
            #pragma unroll
            for (int i = 0; i < NB4; i++) {
                int f = tid + i * 256; int kr = f / (BN/4); int n4 = (f % (BN/4)) << 2;
                float4 v = *(const float4*)(Bm + (long long)(kb + kr) * ldb + col0 + n4);
                int kp = kperm(kr);
                Bs[0][n4+0][kp] = f2tf(v.x);
                Bs[0][n4+1][kp] = f2tf(v.y);
                Bs[0][n4+2][kp] = f2tf(v.z);
                Bs[0][n4+3][kp] = f2tf(v.w);
            }
        } else {
            #pragma unroll
            for (int i = 0; i < NB4; i++) {
                int f = tid + i * 256; int r = f / KQ; int c4 = (f % KQ) << 2;
                float4 v = *(const float4*)(Bm + (long long)(col0 + r) * ldb + kb + c4);
                Bs[0][r][kperm(c4+0)] = f2tf(v.x);
                Bs[0][r][kperm(c4+1)] = f2tf(v.y);
                Bs[0][r][kperm(c4+2)] = f2tf(v.z);
                Bs[0][r][kperm(c4+3)] = f2tf(v.w);
            }
        }
    }
    __syncthreads();

    float acc[MF][NF][4];
    #pragma unroll
    for (int i = 0; i < MF; i++)
        #pragma unroll
        for (int j = 0; j < NF; j++)
            #pragma unroll
            for (int e = 0; e < 4; e++) acc[i][j][e] = 0.f;

    int cur = 0;
    for (int t = 0; t < nk; t++) {
        if (t + 1 < nk) {
            int kb = kBeg + (t + 1) * BK;
            #pragma unroll
            for (int i = 0; i < NA4; i++) {
                int f = tid + i * 256; int r = f / KQ; int c4 = (f % KQ) << 2;
                ag[i] = *(const float4*)(A + (long long)(row0 + r) * lda + kb + c4);
            }
            if (!TB) {
                #pragma unroll
                for (int i = 0; i < NB4; i++) {
                    int f = tid + i * 256; int kr = f / (BN/4); int n4 = (f % (BN/4)) << 2;
                    bg[i] = *(const float4*)(Bm + (long long)(kb + kr) * ldb + col0 + n4);
                }
            } else {
                #pragma unroll
                for (int i = 0; i < NB4; i++) {
                    int f = tid + i * 256; int r = f / KQ; int c4 = (f % KQ) << 2;
                    bg[i] = *(const float4*)(Bm + (long long)(col0 + r) * ldb + kb + c4);
                }
            }
        }
        #pragma unroll
        for (int s = 0; s < KS; s++) {
            uint32_t af[MF][4], bf[NF][2];
            #pragma unroll
            for (int i = 0; i < MF; i++) {
                uint2 lo = *(const uint2*)&As[cur][wr + 16*i + g    ][8*s + 2*q];
                uint2 hi = *(const uint2*)&As[cur][wr + 16*i + g + 8][8*s + 2*q];
                af[i][0] = lo.x; af[i][1] = hi.x; af[i][2] = lo.y; af[i][3] = hi.y;
            }
            #pragma unroll
            for (int j = 0; j < NF; j++) {
                uint2 bb = *(const uint2*)&Bs[cur][wc + 8*j + g][8*s + 2*q];
                bf[j][0] = bb.x; bf[j][1] = bb.y;
            }
            #pragma unroll
            for (int i = 0; i < MF; i++)
                #pragma unroll
                for (int j = 0; j < NF; j++)
                    mma8(acc[i][j], af[i], bf[j]);
        }
        if (t + 1 < nk) {
            int nxt = cur ^ 1;
            #pragma unroll
            for (int i = 0; i < NA4; i++) {
                int f = tid + i * 256; int r = f / KQ; int c4 = (f % KQ) << 2;
                As[nxt][r][kperm(c4+0)] = f2tf(ag[i].x);
                As[nxt][r][kperm(c4+1)] = f2tf(ag[i].y);
                As[nxt][r][kperm(c4+2)] = f2tf(ag[i].z);
                As[nxt][r][kperm(c4+3)] = f2tf(ag[i].w);
            }
            if (!TB) {
                #pragma unroll
                for (int i = 0; i < NB4; i++) {
                    int f = tid + i * 256; int kr = f / (BN/4); int n4 = (f % (BN/4)) << 2;
                    int kp = kperm(kr);
                    Bs[nxt][n4+0][kp] = f2tf(bg[i].x);
                    Bs[nxt][n4+1][kp] = f2tf(bg[i].y);
                    Bs[nxt][n4+2][kp] = f2tf(bg[i].z);
                    Bs[nxt][n4+3][kp] = f2tf(bg[i].w);
                }
            } else {
                #pragma unroll
                for (int i = 0; i < NB4; i++) {
                    int f = tid + i * 256; int r = f / KQ; int c4 = (f % KQ) << 2;
                    Bs[nxt][r][kperm(c4+0)] = f2tf(bg[i].x);
                    Bs[nxt][r][kperm(c4+1)] = f2tf(bg[i].y);
                    Bs[nxt][r][kperm(c4+2)] = f2tf(bg[i].z);
                    Bs[nxt][r][kperm(c4+3)] = f2tf(bg[i].w);
                }
            }
            __syncthreads();
            cur = nxt;
        }
    }

    #pragma unroll
    for (int i = 0; i < MF; i++) {
        #pragma unroll
        for (int j = 0; j < NF; j++) {
            int r0 = row0 + wr + 16*i + g;
            int c0 = col0 + wc + 8*j + 2*q;
            *(float2*)(C + (long long)r0 * ldc + c0) = make_float2(acc[i][j][0], acc[i][j][1]);
            *(float2*)(C + (long long)(r0 + 8) * ldc + c0) = make_float2(acc[i][j][2], acc[i][j][3]);
        }
    }
}

// ---------------- fused flash attention (tf32 mma, online softmax) ----------
// GATHER=0 (attn1): region-mapped inputs [state; segment; state]; dense out0.
// GATHER=1 (attn2): dense input b1; row0=(rb+rbOff)*BR; a2 rows -> out0 (+b*o0b),
//                   a2e rows -> out1.
template<int DH, bool GATHER>
__global__ void __launch_bounds__(256) flash_k(
    const float* __restrict__ b1, const float* __restrict__ b2, int ld,
    long long b1S, long long b2S, int qoff, int koff, int voff,
    float* __restrict__ out0, long long o0b, float* __restrict__ out1,
    int rbOff, int nRB)
{
    constexpr int BR = 128, BC = 64;
    constexpr int QW = DH + 4, KW = DH + 4, VW = BC + 4, SW = BC + 4;
    extern __shared__ uint32_t sm[];
    uint32_t* Qs = sm;
    uint32_t* Ks = Qs + BR * QW;
    uint32_t* Vs = Ks + BC * KW;
    uint32_t* Ss = Vs + DH * VW;

    int bh = blockIdx.y;
    int b = bh / H_, h = bh - b * H_;

    const float* stb  = b1 + (long long)bh * b1S;
    const float* segb = GATHER ? stb : (b2 + (long long)bh * b2S);

    int rb = blockIdx.x;
    int row0 = (GATHER ? (rb + rbOff) : rb) * BR;

    const float* Qb;
    if (GATHER) {
        Qb = stb + (long long)row0 * ld;
    } else {
        if (row0 < SL_)            Qb = stb;
        else if (row0 < SL_+SEG_)  Qb = segb + (long long)(row0 - SL_) * ld;
        else                       Qb = stb;
    }

    int tid = threadIdx.x, w = tid >> 5, lane = tid & 31;
    int g = lane >> 2, q = lane & 3;
    int wr = w * 16;

    constexpr int NQ4 = BR * DH / 1024;
    #pragma unroll
    for (int i = 0; i < NQ4; i++) {
        int f = tid + i * 256; int r = f / (DH/4); int c4 = (f % (DH/4)) << 2;
        float4 v = *(const float4*)(Qb + (long long)r * ld + qoff + c4);
        Qs[r*QW + kperm(c4+0)] = f2tf(v.x);
        Qs[r*QW + kperm(c4+1)] = f2tf(v.y);
        Qs[r*QW + kperm(c4+2)] = f2tf(v.z);
        Qs[r*QW + kperm(c4+3)] = f2tf(v.w);
    }

    float Ofr[DH/8][4];
    #pragma unroll
    for (int j = 0; j < DH/8; j++)
        #pragma unroll
        for (int e = 0; e < 4; e++) Ofr[j][e] = 0.f;
    float m_a = -1e30f, m_b = -1e30f, l_a = 0.f, l_b = 0.f;
    int row_a = row0 + wr + g, row_b = row_a + 8;

    int nb = row0 / BC + 2;
    constexpr int NK4 = BC * DH / 1024;

    for (int cb = 0; cb < nb; cb++) {
        int c0 = cb * BC;
        const float* Kb;
        if (GATHER) {
            Kb = stb + (long long)c0 * ld;
        } else {
            if (c0 < SL_)            Kb = stb + (long long)c0 * ld;
            else if (c0 < SL_+SEG_)  Kb = segb + (long long)(c0 - SL_) * ld;
            else                     Kb = stb + (long long)(c0 - SL_ - SEG_) * ld;
        }
        __syncthreads();
        #pragma unroll
        for (int i = 0; i < NK4; i++) {
            int f = tid + i * 256; int r = f / (DH/4); int c4 = (f % (DH/4)) << 2;
            float4 v = *(const float4*)(Kb + (long long)r * ld + koff + c4);
            Ks[r*KW + kperm(c4+0)] = f2tf(v.x);
            Ks[r*KW + kperm(c4+1)] = f2tf(v.y);
            Ks[r*KW + kperm(c4+2)] = f2tf(v.z);
            Ks[r*KW + kperm(c4+3)] = f2tf(v.w);
        }
        #pragma unroll
        for (int i = 0; i < NK4; i++) {
            int f = tid + i * 256; int c = f / (DH/4); int d4 = (f % (DH/4)) << 2;
            float4 v = *(const float4*)(Kb + (long long)c * ld + voff + d4);
            int kp = kperm(c);
            Vs[(d4+0)*VW + kp] = f2tf(v.x);
            Vs[(d4+1)*VW + kp] = f2tf(v.y);
            Vs[(d4+2)*VW + kp] = f2tf(v.z);
            Vs[(d4+3)*VW + kp] = f2tf(v.w);
        }
        __syncthreads();

        float sfr[BC/8][4];
        #pragma unroll
        for (int j = 0; j < BC/8; j++)
            #pragma unroll
            for (int e = 0; e < 4; e++) sfr[j][e] = 0.f;
        #pragma unroll
        for (int s = 0; s < DH/8; s++) {
            uint32_t af[4];
            uint2 lo = *(const uint2*)&Qs[(wr+g  )*QW + 8*s + 2*q];
            uint2 hi = *(const uint2*)&Qs[(wr+g+8)*QW + 8*s + 2*q];
            af[0] = lo.x; af[1] = hi.x; af[2] = lo.y; af[3] = hi.y;
            #pragma unroll
            for (int j = 0; j < BC/8; j++) {
                uint2 bb = *(const uint2*)&Ks[(8*j+g)*KW + 8*s + 2*q];
                uint32_t bf[2] = {bb.x, bb.y};
                mma8(sfr[j], af, bf);
            }
        }

        bool needm = (c0 + BC - 1 > row0 + wr);
        float mb_a = -1e30f, mb_b = -1e30f;
        #pragma unroll
        for (int j = 0; j < BC/8; j++) {
            int col = c0 + 8*j + 2*q;
            float s0 = sfr[j][0]*0.125f, s1 = sfr[j][1]*0.125f;
            float s2 = sfr[j][2]*0.125f, s3 = sfr[j][3]*0.125f;
            if (needm) {
                if (col     > row_a) s0 = -1e30f;
                if (col + 1 > row_a) s1 = -1e30f;
                if (col     > row_b) s2 = -1e30f;
                if (col + 1 > row_b) s3 = -1e30f;
            }
            sfr[j][0]=s0; sfr[j][1]=s1; sfr[j][2]=s2; sfr[j][3]=s3;
            mb_a = fmaxf(mb_a, fmaxf(s0, s1));
            mb_b = fmaxf(mb_b, fmaxf(s2, s3));
        }
        mb_a = fmaxf(mb_a, __shfl_xor_sync(0xffffffffu, mb_a, 1));
        mb_a = fmaxf(mb_a, __shfl_xor_sync(0xffffffffu, mb_a, 2));
        mb_b = fmaxf(mb_b, __shfl_xor_sync(0xffffffffu, mb_b, 1));
        mb_b = fmaxf(mb_b, __shfl_xor_sync(0xffffffffu, mb_b, 2));
        float mn_a = fmaxf(m_a, mb_a), mn_b = fmaxf(m_b, mb_b);
        float ra = __expf(m_a - mn_a), rb2 = __expf(m_b - mn_b);
        float sa = 0.f, sb = 0.f;
        #pragma unroll
        for (int j = 0; j < BC/8; j++) {
            float p0 = __expf(sfr[j][0] - mn_a), p1 = __expf(sfr[j][1] - mn_a);
            float p2 = __expf(sfr[j][2] - mn_b), p3 = __expf(sfr[j][3] - mn_b);
            sa += p0 + p1; sb += p2 + p3;
            int cc = 8*j + 2*q;
            Ss[(wr+g  )*SW + kperm(cc  )] = f2tf(p0);
            Ss[(wr+g  )*SW + kperm(cc+1)] = f2tf(p1);
            Ss[(wr+g+8)*SW + kperm(cc  )] = f2tf(p2);
            Ss[(wr+g+8)*SW + kperm(cc+1)] = f2tf(p3);
        }
        sa += __shfl_xor_sync(0xffffffffu, sa, 1);
        sa += __shfl_xor_sync(0xffffffffu, sa, 2);
        sb += __shfl_xor_sync(0xffffffffu, sb, 1);
        sb += __shfl_xor_sync(0xffffffffu, sb, 2);
        l_a = l_a * ra + sa; l_b = l_b * rb2 + sb;
        m_a = mn_a; m_b = mn_b;
        #pragma unroll
        for (int j2 = 0; j2 < DH/8; j2++) {
            Ofr[j2][0] *= ra; Ofr[j2][1] *= ra;
            Ofr[j2][2] *= rb2; Ofr[j2][3] *= rb2;
        }
        __syncwarp();

        #pragma unroll
        for (int s = 0; s < BC/8; s++) {
            uint32_t af[4];
            uint2 lo = *(const uint2*)&Ss[(wr+g  )*SW + 8*s + 2*q];
            uint2 hi = *(const uint2*)&Ss[(wr+g+8)*SW + 8*s + 2*q];
            af[0] = lo.x; af[1] = hi.x; af[2] = lo.y; af[3] = hi.y;
            #pragma unroll
            for (int j2 = 0; j2 < DH/8; j2++) {
                uint2 bb = *(const uint2*)&Vs[(8*j2+g)*VW + 8*s + 2*q];
                uint32_t bf[2] = {bb.x, bb.y};
                mma8(Ofr[j2], af, bf);
            }
        }
    }

    float ia = 1.f / l_a, ib = 1.f / l_b;
    if (!GATHER) {
        float* oa = out0 + (long long)bh * L_ * DH + (long long)row_a * DH;
        float* ob = out0 + (long long)bh * L_ * DH + (long long)row_b * DH;
        #pragma unroll
        for (int j2 = 0; j2 < DH/8; j2++) {
            int col = 8*j2 + 2*q;
            *(float2*)(oa + col) = make_float2(Ofr[j2][0]*ia, Ofr[j2][1]*ia);
            *(float2*)(ob + col) = make_float2(Ofr[j2][2]*ib, Ofr[j2][3]*ib);
        }
    } else {
        #pragma unroll
        for (int rr = 0; rr < 2; rr++) {
            int s_abs = (rr == 0) ? row_a : row_b;
            float inv = (rr == 0) ? ia : ib;
            float* dst;
            if (s_abs < SL_ + SEG_) {
                int s = s_abs - SL_;
                dst = out0 + (long long)b * o0b
                    + (long long)((h << 5) + (s >> 4)) * 2048 + ((s & 15) << 7);
            } else {
                int s = s_abs - (SL_ + SEG_);
                dst = out1 + ((long long)b * SL_ + (h << 3) + (s >> 4)) * 2048
                    + ((s & 15) << 7);
            }
            #pragma unroll
            for (int j2 = 0; j2 < DH/8; j2++) {
                int col = 8*j2 + 2*q;
                float v0 = Ofr[j2][rr ? 2 : 0] * inv;
                float v1 = Ofr[j2][rr ? 3 : 1] * inv;
                *(float2*)(dst + col) = make_float2(v0, v1);
            }
        }
    }
}

// generic split-K reduce
__global__ void reduceK(float* __restrict__ C, const float* __restrict__ part,
    int sk, long long chunk, int M, int N, int ldc,
    long long cSB, long long cSH, int Hd)
{
    long long idx = (long long)blockIdx.x * blockDim.x + threadIdx.x;
    if (idx >= chunk) return;
    int n = (int)(idx % N);
    long long t = idx / N;
    int m = (int)(t % M);
    int zz = (int)(t / M);
    int b = zz / Hd, h = zz - b * Hd;
    float s = 0.f;
    for (int i = 0; i < sk; i++) s += part[(long long)i * chunk + idx];
    C[(long long)b * cSB + (long long)h * cSH + (long long)m * ldc + n] = s;
}

__global__ void pack3(float* __restrict__ dst, const float* __restrict__ s0,
                      const float* __restrict__ s1, const float* __restrict__ s2,
                      int n, int w)
{
    int idx = blockIdx.x * blockDim.x + threadIdx.x;
    int tot = n * 3 * w;
    if (idx >= tot) return;
    int c = idx % w; int o = (idx / w) % 3; int i = idx / (3 * w);
    const float* s = (o == 0) ? s0 : ((o == 1) ? s1 : s2);
    dst[idx] = s[(size_t)i * w + c];
}

__global__ void bcast_state(float* __restrict__ st, const float* __restrict__ state)
{
    int idx = blockIdx.x * blockDim.x + threadIdx.x;
    const int total = B_ * SL_ * D_;
    if (idx >= total) return;
    st[idx] = state[idx % (SL_ * D_)];
}

__global__ void copy_f(float* __restrict__ dst, const float* __restrict__ src, int n)
{
    int idx = blockIdx.x * blockDim.x + threadIdx.x;
    if (idx < n) dst[idx] = src[idx];
}

// ---------------- host ----------------
static float* s_part = nullptr;

static void G(bool tb, const float* A, const float* Bm, float* C,
              int M, int N, int K, int lda, int ldb, int ldc,
              long long aSB, long long aSH, long long bSB, long long bSH,
              long long cSB, long long cSH, int Hd, int Z, int sk = 1,
              int useTab = 0, BTab tab = {}, cudaStream_t st = 0)
{
    int Kc = K / sk;
    long long pcs = 0;
    float* Cout = C;
    long long csb = cSB, csh = cSH;
    int ldc2 = ldc;
    if (sk > 1) {
        pcs = (long long)Z * M * N;
        Cout = s_part; ldc2 = N;
        csh = (long long)M * N;
        csb = (long long)Hd * M * N;
    }
    dim3 blk(256);
    if (N % 128 == 0) {
        dim3 grid(N / 128, (M + 127) / 128, Z * sk);
        if (tb) gemm_t<128,128,64,32,true ><<<grid, blk, 0, st>>>(A, Bm, Cout, M, N, K, lda, ldb, ldc2,
            aSB, aSH, bSB, bSH, csb, csh, Hd, Z, sk, Kc, pcs, useTab, tab);
        else    gemm_t<128,128,64,32,false><<<grid, blk, 0, st>>>(A, Bm, Cout, M, N, K, lda, ldb, ldc2,
            aSB, aSH, bSB, bSH, csb, csh, Hd, Z, sk, Kc, pcs, useTab, tab);
    } else {
        dim3 grid(N / 64, (M + 127) / 128, Z * sk);
        if (tb) gemm_t<128,64,32,32,true ><<<grid, blk, 0, st>>>(A, Bm, Cout, M, N, K, lda, ldb, ldc2,
            aSB, aSH, bSB, bSH, csb, csh, Hd, Z, sk, Kc, pcs, useTab, tab);
        else    gemm_t<128,64,32,32,false><<<grid, blk, 0, st>>>(A, Bm, Cout, M, N, K, lda, ldb, ldc2,
            aSB, aSH, bSB, bSH, csb, csh, Hd, Z, sk, Kc, pcs, useTab, tab);
    }
    if (sk > 1) {
        long long chunk = (long long)Z * M * N;
        reduceK<<<(unsigned)((chunk + 255) / 256), 256, 0, st>>>(C, s_part, sk, chunk,
            M, N, ldc, cSB, cSH, Hd);
    }
}

extern "C" void kernel_launch(void* const* d_in, const int* in_sizes, int n_in,
                              void* d_out, int out_size)
{
    const float* x       = (const float*)d_in[0];
    const float* state   = (const float*)d_in[1];
    const float* Wk      = (const float*)d_in[2];
    const float* Wq      = (const float*)d_in[3];
    const float* Wv      = (const float*)d_in[4];
    const float* W2k     = (const float*)d_in[5];
    const float* Wout    = (const float*)d_in[6];
    const float* Wk_st   = (const float*)d_in[7];
    const float* Wq_st   = (const float*)d_in[8];
    const float* Wv_st   = (const float*)d_in[9];
    const float* W2k_ss  = (const float*)d_in[10];
    const float* W2q_ss  = (const float*)d_in[11];
    const float* W2v_ss  = (const float*)d_in[12];
    const float* W2k_se  = (const float*)d_in[13];
    const float* W2q_se  = (const float*)d_in[14];
    const float* W2v_se  = (const float*)d_in[15];
    const float* Wout_st = (const float*)d_in[16];
    float* out = (float*)d_out;

    float *kqvf,*stp,*att1,*kqv2,*a2r,*a2e,*stA,*stB;
    float *WkqvF,*WstP,*W2ss,*W2mid,*W2se;
    cudaGetSymbolAddress((void**)&kqvf, g_kqvf);
    cudaGetSymbolAddress((void**)&stp,  g_stp);
    cudaGetSymbolAddress((void**)&att1, g_att1);
    cudaGetSymbolAddress((void**)&kqv2, g_kqv2);
    cudaGetSymbolAddress((void**)&a2r,  g_a2r);
    cudaGetSymbolAddress((void**)&a2e,  g_a2e);
    cudaGetSymbolAddress((void**)&stA,  g_stA);
    cudaGetSymbolAddress((void**)&stB,  g_stB);
    cudaGetSymbolAddress((void**)&s_part, g_part);
    cudaGetSymbolAddress((void**)&WkqvF, g_WkqvF);
    cudaGetSymbolAddress((void**)&WstP,  g_WstP);
    cudaGetSymbolAddress((void**)&W2ss,  g_W2ss);
    cudaGetSymbolAddress((void**)&W2mid, g_W2mid);
    cudaGetSymbolAddress((void**)&W2se,  g_W2se);

    const int SM64  = (128*68 + 64*68 + 64*68 + 128*68) * 4;    // 104448
    const int SM128 = (128*132 + 64*132 + 128*68 + 128*68) * 4; // 171008
    cudaFuncSetAttribute(flash_k<64,false>,  cudaFuncAttributeMaxDynamicSharedMemorySize, SM64);
    cudaFuncSetAttribute(flash_k<128,true>,  cudaFuncAttributeMaxDynamicSharedMemorySize, SM128);

    // lazy-created side stream + fork/join events (created on first, eager call;
    // identical launch topology every call)
    static cudaStream_t s2 = nullptr;
    static cudaEvent_t evF[NSEG_];
    static cudaEvent_t evJ = nullptr;
    if (!s2) {
        cudaStreamCreateWithFlags(&s2, cudaStreamNonBlocking);
        for (int i = 0; i < NSEG_; i++)
            cudaEventCreateWithFlags(&evF[i], cudaEventDisableTiming);
        cudaEventCreateWithFlags(&evJ, cudaEventDisableTiming);
    }

    bcast_state<<<(B_*SL_*D_ + 255)/256, 256>>>(stA, state);
    pack3<<<(H_*D_*192 + 255)/256, 256>>>(WkqvF, Wk, Wq, Wv, H_*D_, 64);
    pack3<<<(H_*D_*192 + 255)/256, 256>>>(WstP, Wk_st, Wq_st, Wv_st, H_*D_, 64);
    pack3<<<(H_*64*384 + 255)/256, 256>>>(W2ss,  W2k_ss, W2q_ss, W2v_ss, H_*64, 128);
    pack3<<<(H_*64*384 + 255)/256, 256>>>(W2mid, W2k,    W2k,    W2k,    H_*64, 128);
    pack3<<<(H_*64*384 + 255)/256, 256>>>(W2se,  W2k_se, W2q_se, W2v_se, H_*64, 128);

    // full-sequence K|Q|V projection (per (b,h) batched, R7 shapes)
    G(false, x, WkqvF, kqvf, S_, 192, D_, D_, 192, 192,
      (long long)S_*D_, 0, 0, (long long)D_*192,
      (long long)H_*S_*192, (long long)S_*192, H_, B_*H_);

    BTab tab2; // level-2 projections: rows 0-127 ss, 128-639 mid, 640-767 se
    tab2.p[0] = W2ss; tab2.p[1] = W2mid; tab2.p[2] = W2mid;
    tab2.p[3] = W2mid; tab2.p[4] = W2mid; tab2.p[5] = W2se;
    tab2.p[6] = W2mid; tab2.p[7] = W2mid;

    bool tailFits = (out_size >= B_*S_*D_ + B_*SL_*D_);

    for (int seg = 0; seg < NSEG_; seg++) {
        float* stc = (seg & 1) ? stB : stA;
        float* stn = (seg & 1) ? stA : stB;
        if (seg == NSEG_-1 && tailFits) stn = out + (size_t)B_*S_*D_;

        // state K|Q|V projection -> stp (split-K x2)
        G(false, stc, WstP, stp, SL_, 192, D_, D_, 192, 192,
          (long long)SL_*D_, 0, 0, (long long)D_*192,
          (long long)H_*SL_*192, (long long)SL_*192, H_, B_*H_, 2);

        // attention 1: region-mapped flash over [stp ; kqvf+segoff ; stp]
        flash_k<64,false><<<dim3(L_/128, B_*H_), 256, SM64>>>(
            stp, kqvf + (long long)seg*SEG_*192, 192,
            (long long)SL_*192, (long long)S_*192, 64, 0, 128,
            att1, 0, nullptr, 0, L_/128);

        // level-2 projections: single launch, per-row-block weights
        G(false, att1, nullptr, kqv2, L_, 384, DV_, DV_, 384, 384,
          (long long)H_*L_*DV_, (long long)L_*DV_, 0, (long long)64*384,
          (long long)H_*L_*384, (long long)L_*384, H_, B_*H_, 1, 1, tab2);

        // attention 2 (full): a2 -> per-seg buffer, a2e -> a2e
        flash_k<128,true><<<dim3(L_/128 - 1, B_*H_), 256, SM128>>>(
            kqv2, nullptr, 384, (long long)L_*384, 0, 128, 0, 256,
            a2r + (long long)seg*SEG_*2048, (long long)NSEG_*SEG_*2048, a2e,
            1, L_/128 - 1);

        // fork: out-segment GEMM runs on side stream, overlapping next segment
        cudaEventRecord(evF[seg], 0);
        cudaStreamWaitEvent(s2, evF[seg], 0);
        G(false, a2r + (long long)seg*SEG_*2048, Wout, out + (size_t)seg*SEG_*D_,
          SEG_, D_, 2048, 2048, D_, D_,
          (long long)NSEG_*SEG_*2048, 0, 0, 0, (long long)S_*D_, 0, 1, B_,
          1, 0, BTab{}, s2);

        // critical path: next state (split-K x8)
        G(false, a2e, Wout_st, stn, SL_, D_, 2048, 2048, D_, D_,
          (long long)SL_*2048, 0, 0, 0, (long long)SL_*D_, 0, 1, B_, 8);
    }

    // join side stream back into origin stream (required to close the capture fork)
    cudaEventRecord(evJ, s2);
    cudaStreamWaitEvent(0, evJ, 0);

    if (!tailFits) {
        int st_elems = B_ * SL_ * D_;
        if (out_size >= B_*S_*D_ + st_elems) {
            copy_f<<<(st_elems + 255)/256, 256>>>(out + (size_t)B_*S_*D_, stA, st_elems);
        }
    }
}

// round 13
// speedup vs baseline: 1.1345x; 1.0629x over previous
#include <cuda_runtime.h>
#include <cstdint>

#define B_ 2
#define S_ 2048
#define D_ 1024
#define H_ 16
#define DK_ 64
#define DV_ 64
#define SEG_ 512
#define SL_ 128
#define L_ 768
#define NSEG_ 4

// ---------------- scratch (device globals: allocation-free) ----------------
__device__ float g_kqvf[(size_t)B_*H_*S_*192];
__device__ float g_stp [(size_t)B_*H_*SL_*192];
__device__ float g_att1[(size_t)B_*H_*L_*64];
__device__ float g_kqv2[(size_t)NSEG_*B_*H_*L_*384];   // per-seg (WAR-free for s2)
__device__ float g_a2r [(size_t)B_*NSEG_*SEG_*2048];
__device__ float g_a2e [(size_t)B_*SL_*2048];
__device__ float g_stA[(size_t)B_*SL_*D_];
__device__ float g_stB[(size_t)B_*SL_*D_];
__device__ float g_part[(size_t)4*1024*1024];
__device__ float g_pO [(size_t)2*B_*H_*SL_*128];       // split-KV partial O
__device__ float g_pm [(size_t)2*B_*H_*SL_];
__device__ float g_pl [(size_t)2*B_*H_*SL_];
__device__ float g_WkqvF[(size_t)H_*D_*192];
__device__ float g_WstP [(size_t)H_*D_*192];
__device__ float g_W2ss [(size_t)H_*64*384];
__device__ float g_W2mid[(size_t)H_*64*384];
__device__ float g_W2se [(size_t)H_*64*384];

struct BTab { const float* p[8]; };

// ---------------- tf32 helpers ----------------
__device__ __forceinline__ uint32_t f2tf(float f) {
    uint32_t u;
    asm("cvt.rna.tf32.f32 %0, %1;" : "=r"(u) : "f"(f));
    return u;
}
__device__ __forceinline__ void mma8(float* c, const uint32_t* a, const uint32_t* b) {
    asm volatile(
        "mma.sync.aligned.m16n8k8.row.col.f32.tf32.tf32.f32 "
        "{%0,%1,%2,%3}, {%4,%5,%6,%7}, {%8,%9}, {%0,%1,%2,%3};\n"
        : "+f"(c[0]), "+f"(c[1]), "+f"(c[2]), "+f"(c[3])
        : "r"(a[0]), "r"(a[1]), "r"(a[2]), "r"(a[3]), "r"(b[0]), "r"(b[1]));
}
__device__ __forceinline__ int kperm(int k) {
    int j = k & 7;
    return (k & ~7) + ((j < 4) ? (j << 1) : ((j << 1) - 7));
}

// ---------------- batched strided tf32 tensor-core GEMM (BK=16) ----------------
template<int BM, int BN, int WM, int WN, bool TB>
__global__ void __launch_bounds__(256) gemm_t(
    const float* __restrict__ A, const float* __restrict__ Bm0, float* __restrict__ C,
    int M, int N, int K, int lda, int ldb, int ldc,
    long long aSB, long long aSH, long long bSB, long long bSH,
    long long cSB, long long cSH, int Hd, int Zr,
    int sk, int Kc, long long pcs, int useTab, BTab tab)
{
    constexpr int BK = 16;
    constexpr int KS = BK / 8;
    constexpr int MF = WM / 16;
    constexpr int NF = WN / 8;
    constexpr int WCOL = BN / WN;
    constexpr int NA4 = BM * BK / 1024;
    constexpr int NB4 = BN * BK / 1024;
    constexpr int KQ = BK / 4;

    int z = blockIdx.z;
    int ks = 0, zz = z;
    if (sk > 1) { ks = z / Zr; zz = z - ks * Zr; }
    int b = zz / Hd, h = zz - b * Hd;
    const float* Bm = useTab ? tab.p[blockIdx.y] : Bm0;
    A  += (long long)b * aSB + (long long)h * aSH;
    Bm += (long long)b * bSB + (long long)h * bSH;
    C  += (long long)ks * pcs + (long long)b * cSB + (long long)h * cSH;

    int row0 = blockIdx.y * BM;
    int col0 = blockIdx.x * BN;

    int kBeg = ks * Kc;
    int nk = Kc / BK;

    __shared__ uint32_t As[2][BM][BK + 4];
    __shared__ uint32_t Bs[2][BN][BK + 4];

    int tid = threadIdx.x;
    int w   = tid >> 5;
    int lane = tid & 31;
    int g = lane >> 2, q = lane & 3;
    int warpM = w / WCOL, warpN = w % WCOL;
    int wr = warpM * WM;
    int wc = warpN * WN;

    float4 ag[NA4], bg[NB4];

    {
        int kb = kBeg;
        #pragma unroll
        for (int i = 0; i < NA4; i++) {
            int f = tid + i * 256; int r = f / KQ; int c4 = (f % KQ) << 2;
            float4 v = *(const float4*)(A + (long long)(row0 + r) * lda + kb + c4);
            As[0][r][kperm(c4+0)] = f2tf(v.x);
            As[0][r][kperm(c4+1)] = f2tf(v.y);
            As[0][r][kperm(c4+2)] = f2tf(v.z);
            As[0][r][kperm(c4+3)] = f2tf(v.w);
        }
        if (!TB) {
            #pragma unroll
            for (int i = 0; i < NB4; i++) {
                int f = tid + i * 256; int kr = f / (BN/4); int n4 = (f % (BN/4)) << 2;
                float4 v = *(const float4*)(Bm + (long long)(kb + kr) * ldb + col0 + n4);
                int kp = kperm(kr);
                Bs[0][n4+0][kp] = f2tf(v.x);
                Bs[0][n4+1][kp] = f2tf(v.y);
                Bs[0][n4+2][kp] = f2tf(v.z);
                Bs[0][n4+3][kp] = f2tf(v.w);
            }
        } else {
            #pragma unroll
            for (int i = 0; i < NB4; i++) {
                int f = tid + i * 256; int r = f / KQ; int c4 = (f % KQ) << 2;
                float4 v = *(const float4*)(Bm + (long long)(col0 + r) * ldb + kb + c4);
                Bs[0][r][kperm(c4+0)] = f2tf(v.x);
                Bs[0][r][kperm(c4+1)] = f2tf(v.y);
                Bs[0][r][kperm(c4+2)] = f2tf(v.z);
                Bs[0][r][kperm(c4+3)] = f2tf(v.w);
            }
        }
    }
    __syncthreads();

    float acc[MF][NF][4];
    #pragma unroll
    for (int i = 0; i < MF; i++)
        #pragma unroll
        for (int j = 0; j < NF; j++)
            #pragma unroll
            for (int e = 0; e < 4; e++) acc[i][j][e] = 0.f;

    int cur = 0;
    for (int t = 0; t < nk; t++) {
        if (t + 1 < nk) {
            int kb = kBeg + (t + 1) * BK;
            #pragma unroll
            for (int i = 0; i < NA4; i++) {
                int f = tid + i * 256; int r = f / KQ; int c4 = (f % KQ) << 2;
                ag[i] = *(const float4*)(A + (long long)(row0 + r) * lda + kb + c4);
            }
            if (!TB) {
                #pragma unroll
                for (int i = 0; i < NB4; i++) {
                    int f = tid + i * 256; int kr = f / (BN/4); int n4 = (f % (BN/4)) << 2;
                    bg[i] = *(const float4*)(Bm + (long long)(kb + kr) * ldb + col0 + n4);
                }
            } else {
                #pragma unroll
                for (int i = 0; i < NB4; i++) {
                    int f = tid + i * 256; int r = f / KQ; int c4 = (f % KQ) << 2;
                    bg[i] = *(const float4*)(Bm + (long long)(col0 + r) * ldb + kb + c4);
                }
            }
        }
        #pragma unroll
        for (int s = 0; s < KS; s++) {
            uint32_t af[MF][4], bf[NF][2];
            #pragma unroll
            for (int i = 0; i < MF; i++) {
                uint2 lo = *(const uint2*)&As[cur][wr + 16*i + g    ][8*s + 2*q];
                uint2 hi = *(const uint2*)&As[cur][wr + 16*i + g + 8][8*s + 2*q];
                af[i][0] = lo.x; af[i][1] = hi.x; af[i][2] = lo.y; af[i][3] = hi.y;
            }
            #pragma unroll
            for (int j = 0; j < NF; j++) {
                uint2 bb = *(const uint2*)&Bs[cur][wc + 8*j + g][8*s + 2*q];
                bf[j][0] = bb.x; bf[j][1] = bb.y;
            }
            #pragma unroll
            for (int i = 0; i < MF; i++)
                #pragma unroll
                for (int j = 0; j < NF; j++)
                    mma8(acc[i][j], af[i], bf[j]);
        }
        if (t + 1 < nk) {
            int nxt = cur ^ 1;
            #pragma unroll
            for (int i = 0; i < NA4; i++) {
                int f = tid + i * 256; int r = f / KQ; int c4 = (f % KQ) << 2;
                As[nxt][r][kperm(c4+0)] = f2tf(ag[i].x);
                As[nxt][r][kperm(c4+1)] = f2tf(ag[i].y);
                As[nxt][r][kperm(c4+2)] = f2tf(ag[i].z);
                As[nxt][r][kperm(c4+3)] = f2tf(ag[i].w);
            }
            if (!TB) {
                #pragma unroll
                for (int i = 0; i < NB4; i++) {
                    int f = tid + i * 256; int kr = f / (BN/4); int n4 = (f % (BN/4)) << 2;
                    int kp = kperm(kr);
                    Bs[nxt][n4+0][kp] = f2tf(bg[i].x);
                    Bs[nxt][n4+1][kp] = f2tf(bg[i].y);
                    Bs[nxt][n4+2][kp] = f2tf(bg[i].z);
                    Bs[nxt][n4+3][kp] = f2tf(bg[i].w);
                }
            } else {
                #pragma unroll
                for (int i = 0; i < NB4; i++) {
                    int f = tid + i * 256; int r = f / KQ; int c4 = (f % KQ) << 2;
                    Bs[nxt][r][kperm(c4+0)] = f2tf(bg[i].x);
                    Bs[nxt][r][kperm(c4+1)] = f2tf(bg[i].y);
                    Bs[nxt][r][kperm(c4+2)] = f2tf(bg[i].z);
                    Bs[nxt][r][kperm(c4+3)] = f2tf(bg[i].w);
                }
            }
            __syncthreads();
            cur = nxt;
        }
    }

    #pragma unroll
    for (int i = 0; i < MF; i++) {
        #pragma unroll
        for (int j = 0; j < NF; j++) {
            int r0 = row0 + wr + 16*i + g;
            int c0 = col0 + wc + 8*j + 2*q;
            *(float2*)(C + (long long)r0 * ldc + c0) = make_float2(acc[i][j][0], acc[i][j][1]);
            *(float2*)(C + (long long)(r0 + 8) * ldc + c0) = make_float2(acc[i][j][2], acc[i][j][3]);
        }
    }
}

// ---------------- fused flash attention (tf32 mma, online softmax) ----------
// GATHER=0 (attn1): region-mapped inputs; dense out0.
// GATHER=1 (attn2): row0=(blockIdx.x+rbOff)*BR; a2 rows -> out0 (+b*o0b),
//   a2e rows -> out1. If pO != nullptr: split-KV partial mode — blockIdx.z
//   selects a half of the column-tile range; unnormalized O and (m,l) are
//   written to pO/pm/pl (layout [split][bh][rloc][...]); no gather output.
template<int DH, bool GATHER>
__global__ void __launch_bounds__(256) flash_k(
    const float* __restrict__ b1, const float* __restrict__ b2, int ld,
    long long b1S, long long b2S, int qoff, int koff, int voff,
    float* __restrict__ out0, long long o0b, float* __restrict__ out1,
    int rbOff, float* __restrict__ pO, float* __restrict__ pm, float* __restrict__ pl)
{
    constexpr int BR = 128, BC = 64;
    constexpr int QW = DH + 4, KW = DH + 4, VW = BC + 4, SW = BC + 4;
    extern __shared__ uint32_t sm[];
    uint32_t* Qs = sm;
    uint32_t* Ks = Qs + BR * QW;
    uint32_t* Vs = Ks + BC * KW;
    uint32_t* Ss = Vs + DH * VW;

    int bh = blockIdx.y;
    int b = bh / H_, h = bh - b * H_;

    const float* stb  = b1 + (long long)bh * b1S;
    const float* segb = GATHER ? stb : (b2 + (long long)bh * b2S);

    int row0 = (GATHER ? ((int)blockIdx.x + rbOff) : (int)blockIdx.x) * BR;

    const float* Qb;
    if (GATHER) {
        Qb = stb + (long long)row0 * ld;
    } else {
        if (row0 < SL_)            Qb = stb;
        else if (row0 < SL_+SEG_)  Qb = segb + (long long)(row0 - SL_) * ld;
        else                       Qb = stb;
    }

    int tid = threadIdx.x, w = tid >> 5, lane = tid & 31;
    int g = lane >> 2, q = lane & 3;
    int wr = w * 16;

    constexpr int NQ4 = BR * DH / 1024;
    #pragma unroll
    for (int i = 0; i < NQ4; i++) {
        int f = tid + i * 256; int r = f / (DH/4); int c4 = (f % (DH/4)) << 2;
        float4 v = *(const float4*)(Qb + (long long)r * ld + qoff + c4);
        Qs[r*QW + kperm(c4+0)] = f2tf(v.x);
        Qs[r*QW + kperm(c4+1)] = f2tf(v.y);
        Qs[r*QW + kperm(c4+2)] = f2tf(v.z);
        Qs[r*QW + kperm(c4+3)] = f2tf(v.w);
    }

    float Ofr[DH/8][4];
    #pragma unroll
    for (int j = 0; j < DH/8; j++)
        #pragma unroll
        for (int e = 0; e < 4; e++) Ofr[j][e] = 0.f;
    float m_a = -1e30f, m_b = -1e30f, l_a = 0.f, l_b = 0.f;
    int row_a = row0 + wr + g, row_b = row_a + 8;

    int nb = row0 / BC + 2;
    int cb0 = 0, cb1 = nb;
    if (pO) {
        int half = (nb + 1) >> 1;
        cb0 = blockIdx.z * half;
        cb1 = cb0 + half; if (cb1 > nb) cb1 = nb;
    }
    constexpr int NK4 = BC * DH / 1024;

    for (int cb = cb0; cb < cb1; cb++) {
        int c0 = cb * BC;
        const float* Kb;
        if (GATHER) {
            Kb = stb + (long long)c0 * ld;
        } else {
            if (c0 < SL_)            Kb = stb + (long long)c0 * ld;
            else if (c0 < SL_+SEG_)  Kb = segb + (long long)(c0 - SL_) * ld;
            else                     Kb = stb + (long long)(c0 - SL_ - SEG_) * ld;
        }
        __syncthreads();
        #pragma unroll
        for (int i = 0; i < NK4; i++) {
            int f = tid + i * 256; int r = f / (DH/4); int c4 = (f % (DH/4)) << 2;
            float4 v = *(const float4*)(Kb + (long long)r * ld + koff + c4);
            Ks[r*KW + kperm(c4+0)] = f2tf(v.x);
            Ks[r*KW + kperm(c4+1)] = f2tf(v.y);
            Ks[r*KW + kperm(c4+2)] = f2tf(v.z);
            Ks[r*KW + kperm(c4+3)] = f2tf(v.w);
        }
        #pragma unroll
        for (int i = 0; i < NK4; i++) {
            int f = tid + i * 256; int c = f / (DH/4); int d4 = (f % (DH/4)) << 2;
            float4 v = *(const float4*)(Kb + (long long)c * ld + voff + d4);
            int kp = kperm(c);
            Vs[(d4+0)*VW + kp] = f2tf(v.x);
            Vs[(d4+1)*VW + kp] = f2tf(v.y);
            Vs[(d4+2)*VW + kp] = f2tf(v.z);
            Vs[(d4+3)*VW + kp] = f2tf(v.w);
        }
        __syncthreads();

        float sfr[BC/8][4];
        #pragma unroll
        for (int j = 0; j < BC/8; j++)
            #pragma unroll
            for (int e = 0; e < 4; e++) sfr[j][e] = 0.f;
        #pragma unroll
        for (int s = 0; s < DH/8; s++) {
            uint32_t af[4];
            uint2 lo = *(const uint2*)&Qs[(wr+g  )*QW + 8*s + 2*q];
            uint2 hi = *(const uint2*)&Qs[(wr+g+8)*QW + 8*s + 2*q];
            af[0] = lo.x; af[1] = hi.x; af[2] = lo.y; af[3] = hi.y;
            #pragma unroll
            for (int j = 0; j < BC/8; j++) {
                uint2 bb = *(const uint2*)&Ks[(8*j+g)*KW + 8*s + 2*q];
                uint32_t bf[2] = {bb.x, bb.y};
                mma8(sfr[j], af, bf);
            }
        }

        bool needm = (c0 + BC - 1 > row0 + wr);
        float mb_a = -1e30f, mb_b = -1e30f;
        #pragma unroll
        for (int j = 0; j < BC/8; j++) {
            int col = c0 + 8*j + 2*q;
            float s0 = sfr[j][0]*0.125f, s1 = sfr[j][1]*0.125f;
            float s2 = sfr[j][2]*0.125f, s3 = sfr[j][3]*0.125f;
            if (needm) {
                if (col     > row_a) s0 = -1e30f;
                if (col + 1 > row_a) s1 = -1e30f;
                if (col     > row_b) s2 = -1e30f;
                if (col + 1 > row_b) s3 = -1e30f;
            }
            sfr[j][0]=s0; sfr[j][1]=s1; sfr[j][2]=s2; sfr[j][3]=s3;
            mb_a = fmaxf(mb_a, fmaxf(s0, s1));
            mb_b = fmaxf(mb_b, fmaxf(s2, s3));
        }
        mb_a = fmaxf(mb_a, __shfl_xor_sync(0xffffffffu, mb_a, 1));
        mb_a = fmaxf(mb_a, __shfl_xor_sync(0xffffffffu, mb_a, 2));
        mb_b = fmaxf(mb_b, __shfl_xor_sync(0xffffffffu, mb_b, 1));
        mb_b = fmaxf(mb_b, __shfl_xor_sync(0xffffffffu, mb_b, 2));
        float mn_a = fmaxf(m_a, mb_a), mn_b = fmaxf(m_b, mb_b);
        float ra = __expf(m_a - mn_a), rb2 = __expf(m_b - mn_b);
        float sa = 0.f, sb = 0.f;
        #pragma unroll
        for (int j = 0; j < BC/8; j++) {
            float p0 = __expf(sfr[j][0] - mn_a), p1 = __expf(sfr[j][1] - mn_a);
            float p2 = __expf(sfr[j][2] - mn_b), p3 = __expf(sfr[j][3] - mn_b);
            sa += p0 + p1; sb += p2 + p3;
            int cc = 8*j + 2*q;
            Ss[(wr+g  )*SW + kperm(cc  )] = f2tf(p0);
            Ss[(wr+g  )*SW + kperm(cc+1)] = f2tf(p1);
            Ss[(wr+g+8)*SW + kperm(cc  )] = f2tf(p2);
            Ss[(wr+g+8)*SW + kperm(cc+1)] = f2tf(p3);
        }
        sa += __shfl_xor_sync(0xffffffffu, sa, 1);
        sa += __shfl_xor_sync(0xffffffffu, sa, 2);
        sb += __shfl_xor_sync(0xffffffffu, sb, 1);
        sb += __shfl_xor_sync(0xffffffffu, sb, 2);
        l_a = l_a * ra + sa; l_b = l_b * rb2 + sb;
        m_a = mn_a; m_b = mn_b;
        #pragma unroll
        for (int j2 = 0; j2 < DH/8; j2++) {
            Ofr[j2][0] *= ra; Ofr[j2][1] *= ra;
            Ofr[j2][2] *= rb2; Ofr[j2][3] *= rb2;
        }
        __syncwarp();

        #pragma unroll
        for (int s = 0; s < BC/8; s++) {
            uint32_t af[4];
            uint2 lo = *(const uint2*)&Ss[(wr+g  )*SW + 8*s + 2*q];
            uint2 hi = *(const uint2*)&Ss[(wr+g+8)*SW + 8*s + 2*q];
            af[0] = lo.x; af[1] = hi.x; af[2] = lo.y; af[3] = hi.y;
            #pragma unroll
            for (int j2 = 0; j2 < DH/8; j2++) {
                uint2 bb = *(const uint2*)&Vs[(8*j2+g)*VW + 8*s + 2*q];
                uint32_t bf[2] = {bb.x, bb.y};
                mma8(Ofr[j2], af, bf);
            }
        }
    }

    if (pO) {
        // partial epilogue: unnormalized O + (m, l), layout [split][bh][rloc]
        long long base = ((long long)blockIdx.z * (B_*H_) + bh) * BR;
        #pragma unroll
        for (int rr = 0; rr < 2; rr++) {
            int rloc = wr + g + (rr ? 8 : 0);
            float* dst = pO + (base + rloc) * DH;
            #pragma unroll
            for (int j2 = 0; j2 < DH/8; j2++) {
                int col = 8*j2 + 2*q;
                *(float2*)(dst + col) =
                    make_float2(Ofr[j2][rr ? 2 : 0], Ofr[j2][rr ? 3 : 1]);
            }
        }
        if (q == 0) {
            pm[base + wr + g    ] = m_a;  pl[base + wr + g    ] = l_a;
            pm[base + wr + g + 8] = m_b;  pl[base + wr + g + 8] = l_b;
        }
        return;
    }

    float ia = 1.f / l_a, ib = 1.f / l_b;
    if (!GATHER) {
        float* oa = out0 + (long long)bh * L_ * DH + (long long)row_a * DH;
        float* ob = out0 + (long long)bh * L_ * DH + (long long)row_b * DH;
        #pragma unroll
        for (int j2 = 0; j2 < DH/8; j2++) {
            int col = 8*j2 + 2*q;
            *(float2*)(oa + col) = make_float2(Ofr[j2][0]*ia, Ofr[j2][1]*ia);
            *(float2*)(ob + col) = make_float2(Ofr[j2][2]*ib, Ofr[j2][3]*ib);
        }
    } else {
        #pragma unroll
        for (int rr = 0; rr < 2; rr++) {
            int s_abs = (rr == 0) ? row_a : row_b;
            float inv = (rr == 0) ? ia : ib;
            float* dst;
            if (s_abs < SL_ + SEG_) {
                int s = s_abs - SL_;
                dst = out0 + (long long)b * o0b
                    + (long long)((h << 5) + (s >> 4)) * 2048 + ((s & 15) << 7);
            } else {
                int s = s_abs - (SL_ + SEG_);
                dst = out1 + ((long long)b * SL_ + (h << 3) + (s >> 4)) * 2048
                    + ((s & 15) << 7);
            }
            #pragma unroll
            for (int j2 = 0; j2 < DH/8; j2++) {
                int col = 8*j2 + 2*q;
                float v0 = Ofr[j2][rr ? 2 : 0] * inv;
                float v1 = Ofr[j2][rr ? 3 : 1] * inv;
                *(float2*)(dst + col) = make_float2(v0, v1);
            }
        }
    }
}

// merge 2 split-KV partials -> gathered a2e layout
__global__ void mergeKV(float* __restrict__ a2e, const float* __restrict__ pO,
                        const float* __restrict__ pm, const float* __restrict__ pl)
{
    int idx = blockIdx.x * blockDim.x + threadIdx.x;
    const int tot = B_ * H_ * SL_ * 128;
    if (idx >= tot) return;
    int col = idx & 127;
    int r   = (idx >> 7) & 127;
    int bh  = idx >> 14;
    int b = bh / H_, h = bh - b * H_;
    const int P = B_ * H_ * SL_;
    float m0 = pm[bh * SL_ + r], m1 = pm[P + bh * SL_ + r];
    float l0 = pl[bh * SL_ + r], l1 = pl[P + bh * SL_ + r];
    float M  = fmaxf(m0, m1);
    float w0 = __expf(m0 - M), w1 = __expf(m1 - M);
    float O0 = pO[((long long)bh * SL_ + r) * 128 + col];
    float O1 = pO[(long long)P * 128 + ((long long)bh * SL_ + r) * 128 + col];
    float o = (w0 * O0 + w1 * O1) / (w0 * l0 + w1 * l1);
    a2e[((long long)(b * SL_ + (h << 3) + (r >> 4))) * 2048 + ((r & 15) << 7) + col] = o;
}

// generic split-K reduce
__global__ void reduceK(float* __restrict__ C, const float* __restrict__ part,
    int sk, long long chunk, int M, int N, int ldc,
    long long cSB, long long cSH, int Hd)
{
    long long idx = (long long)blockIdx.x * blockDim.x + threadIdx.x;
    if (idx >= chunk) return;
    int n = (int)(idx % N);
    long long t = idx / N;
    int m = (int)(t % M);
    int zz = (int)(t / M);
    int b = zz / Hd, h = zz - b * Hd;
    float s = 0.f;
    for (int i = 0; i < sk; i++) s += part[(long long)i * chunk + idx];
    C[(long long)b * cSB + (long long)h * cSH + (long long)m * ldc + n] = s;
}

__global__ void pack3(float* __restrict__ dst, const float* __restrict__ s0,
                      const float* __restrict__ s1, const float* __restrict__ s2,
                      int n, int w)
{
    int idx = blockIdx.x * blockDim.x + threadIdx.x;
    int tot = n * 3 * w;
    if (idx >= tot) return;
    int c = idx % w; int o = (idx / w) % 3; int i = idx / (3 * w);
    const float* s = (o == 0) ? s0 : ((o == 1) ? s1 : s2);
    dst[idx] = s[(size_t)i * w + c];
}

__global__ void bcast_state(float* __restrict__ st, const float* __restrict__ state)
{
    int idx = blockIdx.x * blockDim.x + threadIdx.x;
    const int total = B_ * SL_ * D_;
    if (idx >= total) return;
    st[idx] = state[idx % (SL_ * D_)];
}

__global__ void copy_f(float* __restrict__ dst, const float* __restrict__ src, int n)
{
    int idx = blockIdx.x * blockDim.x + threadIdx.x;
    if (idx < n) dst[idx] = src[idx];
}

// ---------------- host ----------------
static float* s_part = nullptr;

static void G(bool tb, const float* A, const float* Bm, float* C,
              int M, int N, int K, int lda, int ldb, int ldc,
              long long aSB, long long aSH, long long bSB, long long bSH,
              long long cSB, long long cSH, int Hd, int Z, int sk = 1,
              int useTab = 0, BTab tab = {}, cudaStream_t st = 0)
{
    int Kc = K / sk;
    long long pcs = 0;
    float* Cout = C;
    long long csb = cSB, csh = cSH;
    int ldc2 = ldc;
    if (sk > 1) {
        pcs = (long long)Z * M * N;
        Cout = s_part; ldc2 = N;
        csh = (long long)M * N;
        csb = (long long)Hd * M * N;
    }
    dim3 blk(256);
    if (N % 128 == 0) {
        dim3 grid(N / 128, (M + 127) / 128, Z * sk);
        if (tb) gemm_t<128,128,64,32,true ><<<grid, blk, 0, st>>>(A, Bm, Cout, M, N, K, lda, ldb, ldc2,
            aSB, aSH, bSB, bSH, csb, csh, Hd, Z, sk, Kc, pcs, useTab, tab);
        else    gemm_t<128,128,64,32,false><<<grid, blk, 0, st>>>(A, Bm, Cout, M, N, K, lda, ldb, ldc2,
            aSB, aSH, bSB, bSH, csb, csh, Hd, Z, sk, Kc, pcs, useTab, tab);
    } else {
        dim3 grid(N / 64, (M + 127) / 128, Z * sk);
        if (tb) gemm_t<128,64,32,32,true ><<<grid, blk, 0, st>>>(A, Bm, Cout, M, N, K, lda, ldb, ldc2,
            aSB, aSH, bSB, bSH, csb, csh, Hd, Z, sk, Kc, pcs, useTab, tab);
        else    gemm_t<128,64,32,32,false><<<grid, blk, 0, st>>>(A, Bm, Cout, M, N, K, lda, ldb, ldc2,
            aSB, aSH, bSB, bSH, csb, csh, Hd, Z, sk, Kc, pcs, useTab, tab);
    }
    if (sk > 1) {
        long long chunk = (long long)Z * M * N;
        reduceK<<<(unsigned)((chunk + 255) / 256), 256, 0, st>>>(C, s_part, sk, chunk,
            M, N, ldc, cSB, cSH, Hd);
    }
}

extern "C" void kernel_launch(void* const* d_in, const int* in_sizes, int n_in,
                              void* d_out, int out_size)
{
    const float* x       = (const float*)d_in[0];
    const float* state   = (const float*)d_in[1];
    const float* Wk      = (const float*)d_in[2];
    const float* Wq      = (const float*)d_in[3];
    const float* Wv      = (const float*)d_in[4];
    const float* W2k     = (const float*)d_in[5];
    const float* Wout    = (const float*)d_in[6];
    const float* Wk_st   = (const float*)d_in[7];
    const float* Wq_st   = (const float*)d_in[8];
    const float* Wv_st   = (const float*)d_in[9];
    const float* W2k_ss  = (const float*)d_in[10];
    const float* W2q_ss  = (const float*)d_in[11];
    const float* W2v_ss  = (const float*)d_in[12];
    const float* W2k_se  = (const float*)d_in[13];
    const float* W2q_se  = (const float*)d_in[14];
    const float* W2v_se  = (const float*)d_in[15];
    const float* Wout_st = (const float*)d_in[16];
    float* out = (float*)d_out;

    float *kqvf,*stp,*att1,*kqv2,*a2r,*a2e,*stA,*stB,*pO,*pm,*pl;
    float *WkqvF,*WstP,*W2ss,*W2mid,*W2se;
    cudaGetSymbolAddress((void**)&kqvf, g_kqvf);
    cudaGetSymbolAddress((void**)&stp,  g_stp);
    cudaGetSymbolAddress((void**)&att1, g_att1);
    cudaGetSymbolAddress((void**)&kqv2, g_kqv2);
    cudaGetSymbolAddress((void**)&a2r,  g_a2r);
    cudaGetSymbolAddress((void**)&a2e,  g_a2e);
    cudaGetSymbolAddress((void**)&stA,  g_stA);
    cudaGetSymbolAddress((void**)&stB,  g_stB);
    cudaGetSymbolAddress((void**)&s_part, g_part);
    cudaGetSymbolAddress((void**)&pO, g_pO);
    cudaGetSymbolAddress((void**)&pm, g_pm);
    cudaGetSymbolAddress((void**)&pl, g_pl);
    cudaGetSymbolAddress((void**)&WkqvF, g_WkqvF);
    cudaGetSymbolAddress((void**)&WstP,  g_WstP);
    cudaGetSymbolAddress((void**)&W2ss,  g_W2ss);
    cudaGetSymbolAddress((void**)&W2mid, g_W2mid);
    cudaGetSymbolAddress((void**)&W2se,  g_W2se);

    const int SM64  = (128*68 + 64*68 + 64*68 + 128*68) * 4;    // 104448
    const int SM128 = (128*132 + 64*132 + 128*68 + 128*68) * 4; // 171008
    cudaFuncSetAttribute(flash_k<64,false>,  cudaFuncAttributeMaxDynamicSharedMemorySize, SM64);
    cudaFuncSetAttribute(flash_k<128,true>,  cudaFuncAttributeMaxDynamicSharedMemorySize, SM128);

    static cudaStream_t s2 = nullptr;
    static cudaEvent_t evF[NSEG_];
    static cudaEvent_t evJ = nullptr;
    if (!s2) {
        cudaStreamCreateWithFlags(&s2, cudaStreamNonBlocking);
        for (int i = 0; i < NSEG_; i++)
            cudaEventCreateWithFlags(&evF[i], cudaEventDisableTiming);
        cudaEventCreateWithFlags(&evJ, cudaEventDisableTiming);
    }

    bcast_state<<<(B_*SL_*D_ + 255)/256, 256>>>(stA, state);
    pack3<<<(H_*D_*192 + 255)/256, 256>>>(WkqvF, Wk, Wq, Wv, H_*D_, 64);
    pack3<<<(H_*D_*192 + 255)/256, 256>>>(WstP, Wk_st, Wq_st, Wv_st, H_*D_, 64);
    pack3<<<(H_*64*384 + 255)/256, 256>>>(W2ss,  W2k_ss, W2q_ss, W2v_ss, H_*64, 128);
    pack3<<<(H_*64*384 + 255)/256, 256>>>(W2mid, W2k,    W2k,    W2k,    H_*64, 128);
    pack3<<<(H_*64*384 + 255)/256, 256>>>(W2se,  W2k_se, W2q_se, W2v_se, H_*64, 128);

    // full-sequence K|Q|V projection (per (b,h) batched)
    G(false, x, WkqvF, kqvf, S_, 192, D_, D_, 192, 192,
      (long long)S_*D_, 0, 0, (long long)D_*192,
      (long long)H_*S_*192, (long long)S_*192, H_, B_*H_);

    BTab tab2; // level-2 projections: rows 0-127 ss, 128-639 mid, 640-767 se
    tab2.p[0] = W2ss; tab2.p[1] = W2mid; tab2.p[2] = W2mid;
    tab2.p[3] = W2mid; tab2.p[4] = W2mid; tab2.p[5] = W2se;
    tab2.p[6] = W2mid; tab2.p[7] = W2mid;

    bool tailFits = (out_size >= B_*S_*D_ + B_*SL_*D_);
    const long long KQV2SEG = (long long)B_*H_*L_*384;

    for (int seg = 0; seg < NSEG_; seg++) {
        float* stc = (seg & 1) ? stB : stA;
        float* stn = (seg & 1) ? stA : stB;
        if (seg == NSEG_-1 && tailFits) stn = out + (size_t)B_*S_*D_;
        float* kqv2s = kqv2 + (long long)seg * KQV2SEG;

        // state K|Q|V projection -> stp (split-K x2)
        G(false, stc, WstP, stp, SL_, 192, D_, D_, 192, 192,
          (long long)SL_*D_, 0, 0, (long long)D_*192,
          (long long)H_*SL_*192, (long long)SL_*192, H_, B_*H_, 2);

        // attention 1: region-mapped flash over [stp ; kqvf+segoff ; stp]
        flash_k<64,false><<<dim3(L_/128, B_*H_), 256, SM64>>>(
            stp, kqvf + (long long)seg*SEG_*192, 192,
            (long long)SL_*192, (long long)S_*192, 64, 0, 128,
            att1, 0, nullptr, 0, nullptr, nullptr, nullptr);

        // level-2 projections into per-seg kqv2 buffer
        G(false, att1, nullptr, kqv2s, L_, 384, DV_, DV_, 384, 384,
          (long long)H_*L_*DV_, (long long)L_*DV_, 0, (long long)64*384,
          (long long)H_*L_*384, (long long)L_*384, H_, B_*H_, 1, 1, tab2);

        // fork: a2r row-blocks (rows 128-639) + out-GEMM on side stream
        cudaEventRecord(evF[seg], 0);
        cudaStreamWaitEvent(s2, evF[seg], 0);
        flash_k<128,true><<<dim3(4, B_*H_), 256, SM128, s2>>>(
            kqv2s, nullptr, 384, (long long)L_*384, 0, 128, 0, 256,
            a2r + (long long)seg*SEG_*2048, (long long)NSEG_*SEG_*2048, a2e,
            1, nullptr, nullptr, nullptr);
        G(false, a2r + (long long)seg*SEG_*2048, Wout, out + (size_t)seg*SEG_*D_,
          SEG_, D_, 2048, 2048, D_, D_,
          (long long)NSEG_*SEG_*2048, 0, 0, 0, (long long)S_*D_, 0, 1, B_,
          1, 0, BTab{}, s2);

        // critical path: split-KV flash for a2e rows (640-767), then merge
        flash_k<128,true><<<dim3(1, B_*H_, 2), 256, SM128>>>(
            kqv2s, nullptr, 384, (long long)L_*384, 0, 128, 0, 256,
            a2r + (long long)seg*SEG_*2048, (long long)NSEG_*SEG_*2048, a2e,
            5, pO, pm, pl);
        mergeKV<<<(B_*H_*SL_*128 + 255)/256, 256>>>(a2e, pO, pm, pl);

        // next state (split-K x8)
        G(false, a2e, Wout_st, stn, SL_, D_, 2048, 2048, D_, D_,
          (long long)SL_*2048, 0, 0, 0, (long long)SL_*D_, 0, 1, B_, 8);
    }

    // join side stream back into origin stream
    cudaEventRecord(evJ, s2);
    cudaStreamWaitEvent(0, evJ, 0);

    if (!tailFits) {
        int st_elems = B_ * SL_ * D_;
        if (out_size >= B_*S_*D_ + st_elems) {
            copy_f<<<(st_elems + 255)/256, 256>>>(out + (size_t)B_*S_*D_, stA, st_elems);
        }
    }
}

// round 14
// speedup vs baseline: 1.1892x; 1.0482x over previous
#include <cuda_runtime.h>
#include <cstdint>

#define B_ 2
#define S_ 2048
#define D_ 1024
#define H_ 16
#define DK_ 64
#define DV_ 64
#define SEG_ 512
#define SL_ 128
#define L_ 768
#define NSEG_ 4

// ---------------- scratch (device globals: allocation-free) ----------------
__device__ float g_kqvf[(size_t)B_*H_*S_*192];
__device__ float g_stp [(size_t)B_*H_*SL_*192];
__device__ float g_att1[(size_t)B_*H_*L_*64];
__device__ float g_kqv2[(size_t)NSEG_*B_*H_*L_*384];
__device__ float g_a2r [(size_t)B_*NSEG_*SEG_*2048];
__device__ float g_a2e [(size_t)B_*SL_*2048];
__device__ float g_stA[(size_t)B_*SL_*D_];
__device__ float g_stB[(size_t)B_*SL_*D_];
__device__ float g_part[(size_t)4*1024*1024];
__device__ float g_pO [(size_t)4*1024*1024];     // split partial O (flash1/flash2e)
__device__ float g_pm [(size_t)64*1024];
__device__ float g_pl [(size_t)64*1024];
__device__ float g_WkqvF[(size_t)H_*D_*192];
__device__ float g_WstP [(size_t)H_*D_*192];
__device__ float g_W2ss [(size_t)H_*64*384];
__device__ float g_W2mid[(size_t)H_*64*384];
__device__ float g_W2se [(size_t)H_*64*384];

struct BTab { const float* p[8]; };

// ---------------- tf32 helpers ----------------
__device__ __forceinline__ uint32_t f2tf(float f) {
    uint32_t u;
    asm("cvt.rna.tf32.f32 %0, %1;" : "=r"(u) : "f"(f));
    return u;
}
__device__ __forceinline__ void mma8(float* c, const uint32_t* a, const uint32_t* b) {
    asm volatile(
        "mma.sync.aligned.m16n8k8.row.col.f32.tf32.tf32.f32 "
        "{%0,%1,%2,%3}, {%4,%5,%6,%7}, {%8,%9}, {%0,%1,%2,%3};\n"
        : "+f"(c[0]), "+f"(c[1]), "+f"(c[2]), "+f"(c[3])
        : "r"(a[0]), "r"(a[1]), "r"(a[2]), "r"(a[3]), "r"(b[0]), "r"(b[1]));
}
__device__ __forceinline__ int kperm(int k) {
    int j = k & 7;
    return (k & ~7) + ((j < 4) ? (j << 1) : ((j << 1) - 7));
}

// ---------------- batched strided tf32 tensor-core GEMM (BK=16) ----------------
template<int BM, int BN, int WM, int WN, bool TB>
__global__ void __launch_bounds__(256) gemm_t(
    const float* __restrict__ A, const float* __restrict__ Bm0, float* __restrict__ C,
    int M, int N, int K, int lda, int ldb, int ldc,
    long long aSB, long long aSH, long long bSB, long long bSH,
    long long cSB, long long cSH, int Hd, int Zr,
    int sk, int Kc, long long pcs, int useTab, BTab tab)
{
    constexpr int BK = 16;
    constexpr int KS = BK / 8;
    constexpr int MF = WM / 16;
    constexpr int NF = WN / 8;
    constexpr int WCOL = BN / WN;
    constexpr int NA4 = BM * BK / 1024;
    constexpr int NB4 = BN * BK / 1024;
    constexpr int KQ = BK / 4;

    int z = blockIdx.z;
    int ks = 0, zz = z;
    if (sk > 1) { ks = z / Zr; zz = z - ks * Zr; }
    int b = zz / Hd, h = zz - b * Hd;
    const float* Bm = useTab ? tab.p[blockIdx.y] : Bm0;
    A  += (long long)b * aSB + (long long)h * aSH;
    Bm += (long long)b * bSB + (long long)h * bSH;
    C  += (long long)ks * pcs + (long long)b * cSB + (long long)h * cSH;

    int row0 = blockIdx.y * BM;
    int col0 = blockIdx.x * BN;

    int kBeg = ks * Kc;
    int nk = Kc / BK;

    __shared__ uint32_t As[2][BM][BK + 4];
    __shared__ uint32_t Bs[2][BN][BK + 4];

    int tid = threadIdx.x;
    int w   = tid >> 5;
    int lane = tid & 31;
    int g = lane >> 2, q = lane & 3;
    int warpM = w / WCOL, warpN = w % WCOL;
    int wr = warpM * WM;
    int wc = warpN * WN;

    float4 ag[NA4], bg[NB4];

    {
        int kb = kBeg;
        #pragma unroll
        for (int i = 0; i < NA4; i++) {
            int f = tid + i * 256; int r = f / KQ; int c4 = (f % KQ) << 2;
            float4 v = *(const float4*)(A + (long long)(row0 + r) * lda + kb + c4);
            As[0][r][kperm(c4+0)] = f2tf(v.x);
            As[0][r][kperm(c4+1)] = f2tf(v.y);
            As[0][r][kperm(c4+2)] = f2tf(v.z);
            As[0][r][kperm(c4+3)] = f2tf(v.w);
        }
        if (!TB) {
            #pragma unroll
            for (int i = 0; i < NB4; i++) {
                int f = tid + i * 256; int kr = f / (BN/4); int n4 = (f % (BN/4)) << 2;
                float4 v = *(const float4*)(Bm + (long long)(kb + kr) * ldb + col0 + n4);
                int kp = kperm(kr);
                Bs[0][n4+0][kp] = f2tf(v.x);
                Bs[0][n4+1][kp] = f2tf(v.y);
                Bs[0][n4+2][kp] = f2tf(v.z);
                Bs[0][n4+3][kp] = f2tf(v.w);
            }
        } else {
            #pragma unroll
            for (int i = 0; i < NB4; i++) {
                int f = tid + i * 256; int r = f / KQ; int c4 = (f % KQ) << 2;
                float4 v = *(const float4*)(Bm + (long long)(col0 + r) * ldb + kb + c4);
                Bs[0][r][kperm(c4+0)] = f2tf(v.x);
                Bs[0][r][kperm(c4+1)] = f2tf(v.y);
                Bs[0][r][kperm(c4+2)] = f2tf(v.z);
                Bs[0][r][kperm(c4+3)] = f2tf(v.w);
            }
        }
    }
    __syncthreads();

    float acc[MF][NF][4];
    #pragma unroll
    for (int i = 0; i < MF; i++)
        #pragma unroll
        for (int j = 0; j < NF; j++)
            #pragma unroll
            for (int e = 0; e < 4; e++) acc[i][j][e] = 0.f;

    int cur = 0;
    for (int t = 0; t < nk; t++) {
        if (t + 1 < nk) {
            int kb = kBeg + (t + 1) * BK;
            #pragma unroll
            for (int i = 0; i < NA4; i++) {
                int f = tid + i * 256; int r = f / KQ; int c4 = (f % KQ) << 2;
                ag[i] = *(const float4*)(A + (long long)(row0 + r) * lda + kb + c4);
            }
            if (!TB) {
                #pragma unroll
                for (int i = 0; i < NB4; i++) {
                    int f = tid + i * 256; int kr = f / (BN/4); int n4 = (f % (BN/4)) << 2;
                    bg[i] = *(const float4*)(Bm + (long long)(kb + kr) * ldb + col0 + n4);
                }
            } else {
                #pragma unroll
                for (int i = 0; i < NB4; i++) {
                    int f = tid + i * 256; int r = f / KQ; int c4 = (f % KQ) << 2;
                    bg[i] = *(const float4*)(Bm + (long long)(col0 + r) * ldb + kb + c4);
                }
            }
        }
        #pragma unroll
        for (int s = 0; s < KS; s++) {
            uint32_t af[MF][4], bf[NF][2];
            #pragma unroll
            for (int i = 0; i < MF; i++) {
                uint2 lo = *(const uint2*)&As[cur][wr + 16*i + g    ][8*s + 2*q];
                uint2 hi = *(const uint2*)&As[cur][wr + 16*i + g + 8][8*s + 2*q];
                af[i][0] = lo.x; af[i][1] = hi.x; af[i][2] = lo.y; af[i][3] = hi.y;
            }
            #pragma unroll
            for (int j = 0; j < NF; j++) {
                uint2 bb = *(const uint2*)&Bs[cur][wc + 8*j + g][8*s + 2*q];
                bf[j][0] = bb.x; bf[j][1] = bb.y;
            }
            #pragma unroll
            for (int i = 0; i < MF; i++)
                #pragma unroll
                for (int j = 0; j < NF; j++)
                    mma8(acc[i][j], af[i], bf[j]);
        }
        if (t + 1 < nk) {
            int nxt = cur ^ 1;
            #pragma unroll
            for (int i = 0; i < NA4; i++) {
                int f = tid + i * 256; int r = f / KQ; int c4 = (f % KQ) << 2;
                As[nxt][r][kperm(c4+0)] = f2tf(ag[i].x);
                As[nxt][r][kperm(c4+1)] = f2tf(ag[i].y);
                As[nxt][r][kperm(c4+2)] = f2tf(ag[i].z);
                As[nxt][r][kperm(c4+3)] = f2tf(ag[i].w);
            }
            if (!TB) {
                #pragma unroll
                for (int i = 0; i < NB4; i++) {
                    int f = tid + i * 256; int kr = f / (BN/4); int n4 = (f % (BN/4)) << 2;
                    int kp = kperm(kr);
                    Bs[nxt][n4+0][kp] = f2tf(bg[i].x);
                    Bs[nxt][n4+1][kp] = f2tf(bg[i].y);
                    Bs[nxt][n4+2][kp] = f2tf(bg[i].z);
                    Bs[nxt][n4+3][kp] = f2tf(bg[i].w);
                }
            } else {
                #pragma unroll
                for (int i = 0; i < NB4; i++) {
                    int f = tid + i * 256; int r = f / KQ; int c4 = (f % KQ) << 2;
                    Bs[nxt][r][kperm(c4+0)] = f2tf(bg[i].x);
                    Bs[nxt][r][kperm(c4+1)] = f2tf(bg[i].y);
                    Bs[nxt][r][kperm(c4+2)] = f2tf(bg[i].z);
                    Bs[nxt][r][kperm(c4+3)] = f2tf(bg[i].w);
                }
            }
            __syncthreads();
            cur = nxt;
        }
    }

    #pragma unroll
    for (int i = 0; i < MF; i++) {
        #pragma unroll
        for (int j = 0; j < NF; j++) {
            int r0 = row0 + wr + 16*i + g;
            int c0 = col0 + wc + 8*j + 2*q;
            *(float2*)(C + (long long)r0 * ldc + c0) = make_float2(acc[i][j][0], acc[i][j][1]);
            *(float2*)(C + (long long)(r0 + 8) * ldc + c0) = make_float2(acc[i][j][2], acc[i][j][3]);
        }
    }
}

// ---------------- fused flash attention (tf32 mma, online softmax) ----------
// Partial mode (pO != nullptr): blockIdx.z = split id of nSplit over the
// column-tile range; writes unnormalized O and (m,l) at
// [split][bh][pRows] rows indexed by (global_row - pSub). Splits that see only
// masked tiles keep m = -1e30 -> zero weight in merge.
template<int DH, bool GATHER>
__global__ void __launch_bounds__(256) flash_k(
    const float* __restrict__ b1, const float* __restrict__ b2, int ld,
    long long b1S, long long b2S, int qoff, int koff, int voff,
    float* __restrict__ out0, long long o0b, float* __restrict__ out1,
    int rbOff, float* __restrict__ pO, float* __restrict__ pm, float* __restrict__ pl,
    int nSplit, int pRows, int pSub)
{
    constexpr int BR = 128, BC = 64;
    constexpr int QW = DH + 4, KW = DH + 4, VW = BC + 4, SW = BC + 4;
    extern __shared__ uint32_t sm[];
    uint32_t* Qs = sm;
    uint32_t* Ks = Qs + BR * QW;
    uint32_t* Vs = Ks + BC * KW;
    uint32_t* Ss = Vs + DH * VW;

    int bh = blockIdx.y;
    int b = bh / H_, h = bh - b * H_;

    const float* stb  = b1 + (long long)bh * b1S;
    const float* segb = GATHER ? stb : (b2 + (long long)bh * b2S);

    int row0 = (GATHER ? ((int)blockIdx.x + rbOff) : (int)blockIdx.x) * BR;

    const float* Qb;
    if (GATHER) {
        Qb = stb + (long long)row0 * ld;
    } else {
        if (row0 < SL_)            Qb = stb;
        else if (row0 < SL_+SEG_)  Qb = segb + (long long)(row0 - SL_) * ld;
        else                       Qb = stb;
    }

    int tid = threadIdx.x, w = tid >> 5, lane = tid & 31;
    int g = lane >> 2, q = lane & 3;
    int wr = w * 16;

    constexpr int NQ4 = BR * DH / 1024;
    #pragma unroll
    for (int i = 0; i < NQ4; i++) {
        int f = tid + i * 256; int r = f / (DH/4); int c4 = (f % (DH/4)) << 2;
        float4 v = *(const float4*)(Qb + (long long)r * ld + qoff + c4);
        Qs[r*QW + kperm(c4+0)] = f2tf(v.x);
        Qs[r*QW + kperm(c4+1)] = f2tf(v.y);
        Qs[r*QW + kperm(c4+2)] = f2tf(v.z);
        Qs[r*QW + kperm(c4+3)] = f2tf(v.w);
    }

    float Ofr[DH/8][4];
    #pragma unroll
    for (int j = 0; j < DH/8; j++)
        #pragma unroll
        for (int e = 0; e < 4; e++) Ofr[j][e] = 0.f;
    float m_a = -1e30f, m_b = -1e30f, l_a = 0.f, l_b = 0.f;
    int row_a = row0 + wr + g, row_b = row_a + 8;

    int nb = row0 / BC + 2;
    int cb0 = 0, cb1 = nb;
    if (pO) {
        int half = (nb + nSplit - 1) / nSplit;
        cb0 = blockIdx.z * half;
        cb1 = cb0 + half; if (cb1 > nb) cb1 = nb;
    }
    constexpr int NK4 = BC * DH / 1024;

    for (int cb = cb0; cb < cb1; cb++) {
        int c0 = cb * BC;
        const float* Kb;
        if (GATHER) {
            Kb = stb + (long long)c0 * ld;
        } else {
            if (c0 < SL_)            Kb = stb + (long long)c0 * ld;
            else if (c0 < SL_+SEG_)  Kb = segb + (long long)(c0 - SL_) * ld;
            else                     Kb = stb + (long long)(c0 - SL_ - SEG_) * ld;
        }
        __syncthreads();
        #pragma unroll
        for (int i = 0; i < NK4; i++) {
            int f = tid + i * 256; int r = f / (DH/4); int c4 = (f % (DH/4)) << 2;
            float4 v = *(const float4*)(Kb + (long long)r * ld + koff + c4);
            Ks[r*KW + kperm(c4+0)] = f2tf(v.x);
            Ks[r*KW + kperm(c4+1)] = f2tf(v.y);
            Ks[r*KW + kperm(c4+2)] = f2tf(v.z);
            Ks[r*KW + kperm(c4+3)] = f2tf(v.w);
        }
        #pragma unroll
        for (int i = 0; i < NK4; i++) {
            int f = tid + i * 256; int c = f / (DH/4); int d4 = (f % (DH/4)) << 2;
            float4 v = *(const float4*)(Kb + (long long)c * ld + voff + d4);
            int kp = kperm(c);
            Vs[(d4+0)*VW + kp] = f2tf(v.x);
            Vs[(d4+1)*VW + kp] = f2tf(v.y);
            Vs[(d4+2)*VW + kp] = f2tf(v.z);
            Vs[(d4+3)*VW + kp] = f2tf(v.w);
        }
        __syncthreads();

        float sfr[BC/8][4];
        #pragma unroll
        for (int j = 0; j < BC/8; j++)
            #pragma unroll
            for (int e = 0; e < 4; e++) sfr[j][e] = 0.f;
        #pragma unroll
        for (int s = 0; s < DH/8; s++) {
            uint32_t af[4];
            uint2 lo = *(const uint2*)&Qs[(wr+g  )*QW + 8*s + 2*q];
            uint2 hi = *(const uint2*)&Qs[(wr+g+8)*QW + 8*s + 2*q];
            af[0] = lo.x; af[1] = hi.x; af[2] = lo.y; af[3] = hi.y;
            #pragma unroll
            for (int j = 0; j < BC/8; j++) {
                uint2 bb = *(const uint2*)&Ks[(8*j+g)*KW + 8*s + 2*q];
                uint32_t bf[2] = {bb.x, bb.y};
                mma8(sfr[j], af, bf);
            }
        }

        bool needm = (c0 + BC - 1 > row0 + wr);
        float mb_a = -1e30f, mb_b = -1e30f;
        #pragma unroll
        for (int j = 0; j < BC/8; j++) {
            int col = c0 + 8*j + 2*q;
            float s0 = sfr[j][0]*0.125f, s1 = sfr[j][1]*0.125f;
            float s2 = sfr[j][2]*0.125f, s3 = sfr[j][3]*0.125f;
            if (needm) {
                if (col     > row_a) s0 = -1e30f;
                if (col + 1 > row_a) s1 = -1e30f;
                if (col     > row_b) s2 = -1e30f;
                if (col + 1 > row_b) s3 = -1e30f;
            }
            sfr[j][0]=s0; sfr[j][1]=s1; sfr[j][2]=s2; sfr[j][3]=s3;
            mb_a = fmaxf(mb_a, fmaxf(s0, s1));
            mb_b = fmaxf(mb_b, fmaxf(s2, s3));
        }
        mb_a = fmaxf(mb_a, __shfl_xor_sync(0xffffffffu, mb_a, 1));
        mb_a = fmaxf(mb_a, __shfl_xor_sync(0xffffffffu, mb_a, 2));
        mb_b = fmaxf(mb_b, __shfl_xor_sync(0xffffffffu, mb_b, 1));
        mb_b = fmaxf(mb_b, __shfl_xor_sync(0xffffffffu, mb_b, 2));
        float mn_a = fmaxf(m_a, mb_a), mn_b = fmaxf(m_b, mb_b);
        float ra = __expf(m_a - mn_a), rb2 = __expf(m_b - mn_b);
        float sa = 0.f, sb = 0.f;
        #pragma unroll
        for (int j = 0; j < BC/8; j++) {
            float p0 = __expf(sfr[j][0] - mn_a), p1 = __expf(sfr[j][1] - mn_a);
            float p2 = __expf(sfr[j][2] - mn_b), p3 = __expf(sfr[j][3] - mn_b);
            sa += p0 + p1; sb += p2 + p3;
            int cc = 8*j + 2*q;
            Ss[(wr+g  )*SW + kperm(cc  )] = f2tf(p0);
            Ss[(wr+g  )*SW + kperm(cc+1)] = f2tf(p1);
            Ss[(wr+g+8)*SW + kperm(cc  )] = f2tf(p2);
            Ss[(wr+g+8)*SW + kperm(cc+1)] = f2tf(p3);
        }
        sa += __shfl_xor_sync(0xffffffffu, sa, 1);
        sa += __shfl_xor_sync(0xffffffffu, sa, 2);
        sb += __shfl_xor_sync(0xffffffffu, sb, 1);
        sb += __shfl_xor_sync(0xffffffffu, sb, 2);
        l_a = l_a * ra + sa; l_b = l_b * rb2 + sb;
        m_a = mn_a; m_b = mn_b;
        #pragma unroll
        for (int j2 = 0; j2 < DH/8; j2++) {
            Ofr[j2][0] *= ra; Ofr[j2][1] *= ra;
            Ofr[j2][2] *= rb2; Ofr[j2][3] *= rb2;
        }
        __syncwarp();

        #pragma unroll
        for (int s = 0; s < BC/8; s++) {
            uint32_t af[4];
            uint2 lo = *(const uint2*)&Ss[(wr+g  )*SW + 8*s + 2*q];
            uint2 hi = *(const uint2*)&Ss[(wr+g+8)*SW + 8*s + 2*q];
            af[0] = lo.x; af[1] = hi.x; af[2] = lo.y; af[3] = hi.y;
            #pragma unroll
            for (int j2 = 0; j2 < DH/8; j2++) {
                uint2 bb = *(const uint2*)&Vs[(8*j2+g)*VW + 8*s + 2*q];
                uint32_t bf[2] = {bb.x, bb.y};
                mma8(Ofr[j2], af, bf);
            }
        }
    }

    if (pO) {
        #pragma unroll
        for (int rr = 0; rr < 2; rr++) {
            int pr = ((rr == 0) ? row_a : row_b) - pSub;
            long long base = ((long long)blockIdx.z * (B_*H_) + bh) * pRows + pr;
            float* dst = pO + base * DH;
            #pragma unroll
            for (int j2 = 0; j2 < DH/8; j2++) {
                int col = 8*j2 + 2*q;
                *(float2*)(dst + col) =
                    make_float2(Ofr[j2][rr ? 2 : 0], Ofr[j2][rr ? 3 : 1]);
            }
            if (q == 0) {
                pm[base] = (rr == 0) ? m_a : m_b;
                pl[base] = (rr == 0) ? l_a : l_b;
            }
        }
        return;
    }

    float ia = 1.f / l_a, ib = 1.f / l_b;
    if (!GATHER) {
        float* oa = out0 + (long long)bh * L_ * DH + (long long)row_a * DH;
        float* ob = out0 + (long long)bh * L_ * DH + (long long)row_b * DH;
        #pragma unroll
        for (int j2 = 0; j2 < DH/8; j2++) {
            int col = 8*j2 + 2*q;
            *(float2*)(oa + col) = make_float2(Ofr[j2][0]*ia, Ofr[j2][1]*ia);
            *(float2*)(ob + col) = make_float2(Ofr[j2][2]*ib, Ofr[j2][3]*ib);
        }
    } else {
        #pragma unroll
        for (int rr = 0; rr < 2; rr++) {
            int s_abs = (rr == 0) ? row_a : row_b;
            float inv = (rr == 0) ? ia : ib;
            float* dst;
            if (s_abs < SL_ + SEG_) {
                int s = s_abs - SL_;
                dst = out0 + (long long)b * o0b
                    + (long long)((h << 5) + (s >> 4)) * 2048 + ((s & 15) << 7);
            } else {
                int s = s_abs - (SL_ + SEG_);
                dst = out1 + ((long long)b * SL_ + (h << 3) + (s >> 4)) * 2048
                    + ((s & 15) << 7);
            }
            #pragma unroll
            for (int j2 = 0; j2 < DH/8; j2++) {
                int col = 8*j2 + 2*q;
                float v0 = Ofr[j2][rr ? 2 : 0] * inv;
                float v1 = Ofr[j2][rr ? 3 : 1] * inv;
                *(float2*)(dst + col) = make_float2(v0, v1);
            }
        }
    }
}

// merge 4 split-KV partials (DH=128) -> gathered a2e layout
__global__ void mergeKV(float* __restrict__ a2e, const float* __restrict__ pO,
                        const float* __restrict__ pm, const float* __restrict__ pl)
{
    int idx = blockIdx.x * blockDim.x + threadIdx.x;
    const int tot = B_ * H_ * SL_ * 128;
    if (idx >= tot) return;
    int col = idx & 127;
    int r   = (idx >> 7) & 127;
    int bh  = idx >> 14;
    int b = bh / H_, h = bh - b * H_;
    const int P = B_ * H_ * SL_;
    float M = -1e30f;
    #pragma unroll
    for (int s = 0; s < 4; s++) M = fmaxf(M, pm[s*P + bh*SL_ + r]);
    float num = 0.f, den = 0.f;
    #pragma unroll
    for (int s = 0; s < 4; s++) {
        float wgt = __expf(pm[s*P + bh*SL_ + r] - M);
        den += wgt * pl[s*P + bh*SL_ + r];
        num += wgt * pO[((long long)s*P + (long long)bh*SL_ + r) * 128 + col];
    }
    a2e[((long long)(b * SL_ + (h << 3) + (r >> 4))) * 2048 + ((r & 15) << 7) + col]
        = num / den;
}

// merge 2 split-KV partials (DH=64) -> dense att1
__global__ void merge1(float* __restrict__ att1, const float* __restrict__ pO,
                       const float* __restrict__ pm, const float* __restrict__ pl)
{
    int idx = blockIdx.x * blockDim.x + threadIdx.x;
    const int tot = B_ * H_ * L_ * 64;
    if (idx >= tot) return;
    int col = idx & 63;
    int r   = (idx >> 6) % L_;
    int bh  = idx / (L_ * 64);
    const int P = B_ * H_ * L_;
    float m0 = pm[bh*L_ + r], m1 = pm[P + bh*L_ + r];
    float M = fmaxf(m0, m1);
    float w0 = __expf(m0 - M), w1 = __expf(m1 - M);
    float O0 = pO[((long long)bh*L_ + r) * 64 + col];
    float O1 = pO[((long long)P + (long long)bh*L_ + r) * 64 + col];
    att1[((long long)bh*L_ + r) * 64 + col]
        = (w0*O0 + w1*O1) / (w0*pl[bh*L_ + r] + w1*pl[P + bh*L_ + r]);
}

// generic split-K reduce
__global__ void reduceK(float* __restrict__ C, const float* __restrict__ part,
    int sk, long long chunk, int M, int N, int ldc,
    long long cSB, long long cSH, int Hd)
{
    long long idx = (long long)blockIdx.x * blockDim.x + threadIdx.x;
    if (idx >= chunk) return;
    int n = (int)(idx % N);
    long long t = idx / N;
    int m = (int)(t % M);
    int zz = (int)(t / M);
    int b = zz / Hd, h = zz - b * Hd;
    float s = 0.f;
    for (int i = 0; i < sk; i++) s += part[(long long)i * chunk + idx];
    C[(long long)b * cSB + (long long)h * cSH + (long long)m * ldc + n] = s;
}

__global__ void pack3(float* __restrict__ dst, const float* __restrict__ s0,
                      const float* __restrict__ s1, const float* __restrict__ s2,
                      int n, int w)
{
    int idx = blockIdx.x * blockDim.x + threadIdx.x;
    int tot = n * 3 * w;
    if (idx >= tot) return;
    int c = idx % w; int o = (idx / w) % 3; int i = idx / (3 * w);
    const float* s = (o == 0) ? s0 : ((o == 1) ? s1 : s2);
    dst[idx] = s[(size_t)i * w + c];
}

__global__ void bcast_state(float* __restrict__ st, const float* __restrict__ state)
{
    int idx = blockIdx.x * blockDim.x + threadIdx.x;
    const int total = B_ * SL_ * D_;
    if (idx >= total) return;
    st[idx] = state[idx % (SL_ * D_)];
}

__global__ void copy_f(float* __restrict__ dst, const float* __restrict__ src, int n)
{
    int idx = blockIdx.x * blockDim.x + threadIdx.x;
    if (idx < n) dst[idx] = src[idx];
}

// ---------------- host ----------------
static float* s_part = nullptr;

static void G(bool tb, const float* A, const float* Bm, float* C,
              int M, int N, int K, int lda, int ldb, int ldc,
              long long aSB, long long aSH, long long bSB, long long bSH,
              long long cSB, long long cSH, int Hd, int Z, int sk = 1,
              int useTab = 0, BTab tab = {}, cudaStream_t st = 0)
{
    int Kc = K / sk;
    long long pcs = 0;
    float* Cout = C;
    long long csb = cSB, csh = cSH;
    int ldc2 = ldc;
    if (sk > 1) {
        pcs = (long long)Z * M * N;
        Cout = s_part; ldc2 = N;
        csh = (long long)M * N;
        csb = (long long)Hd * M * N;
    }
    dim3 blk(256);
    if (N % 128 == 0) {
        dim3 grid(N / 128, (M + 127) / 128, Z * sk);
        if (tb) gemm_t<128,128,64,32,true ><<<grid, blk, 0, st>>>(A, Bm, Cout, M, N, K, lda, ldb, ldc2,
            aSB, aSH, bSB, bSH, csb, csh, Hd, Z, sk, Kc, pcs, useTab, tab);
        else    gemm_t<128,128,64,32,false><<<grid, blk, 0, st>>>(A, Bm, Cout, M, N, K, lda, ldb, ldc2,
            aSB, aSH, bSB, bSH, csb, csh, Hd, Z, sk, Kc, pcs, useTab, tab);
    } else {
        dim3 grid(N / 64, (M + 127) / 128, Z * sk);
        if (tb) gemm_t<128,64,32,32,true ><<<grid, blk, 0, st>>>(A, Bm, Cout, M, N, K, lda, ldb, ldc2,
            aSB, aSH, bSB, bSH, csb, csh, Hd, Z, sk, Kc, pcs, useTab, tab);
        else    gemm_t<128,64,32,32,false><<<grid, blk, 0, st>>>(A, Bm, Cout, M, N, K, lda, ldb, ldc2,
            aSB, aSH, bSB, bSH, csb, csh, Hd, Z, sk, Kc, pcs, useTab, tab);
    }
    if (sk > 1) {
        long long chunk = (long long)Z * M * N;
        reduceK<<<(unsigned)((chunk + 255) / 256), 256, 0, st>>>(C, s_part, sk, chunk,
            M, N, ldc, cSB, cSH, Hd);
    }
}

extern "C" void kernel_launch(void* const* d_in, const int* in_sizes, int n_in,
                              void* d_out, int out_size)
{
    const float* x       = (const float*)d_in[0];
    const float* state   = (const float*)d_in[1];
    const float* Wk      = (const float*)d_in[2];
    const float* Wq      = (const float*)d_in[3];
    const float* Wv      = (const float*)d_in[4];
    const float* W2k     = (const float*)d_in[5];
    const float* Wout    = (const float*)d_in[6];
    const float* Wk_st   = (const float*)d_in[7];
    const float* Wq_st   = (const float*)d_in[8];
    const float* Wv_st   = (const float*)d_in[9];
    const float* W2k_ss  = (const float*)d_in[10];
    const float* W2q_ss  = (const float*)d_in[11];
    const float* W2v_ss  = (const float*)d_in[12];
    const float* W2k_se  = (const float*)d_in[13];
    const float* W2q_se  = (const float*)d_in[14];
    const float* W2v_se  = (const float*)d_in[15];
    const float* Wout_st = (const float*)d_in[16];
    float* out = (float*)d_out;

    float *kqvf,*stp,*att1,*kqv2,*a2r,*a2e,*stA,*stB,*pO,*pm,*pl;
    float *WkqvF,*WstP,*W2ss,*W2mid,*W2se;
    cudaGetSymbolAddress((void**)&kqvf, g_kqvf);
    cudaGetSymbolAddress((void**)&stp,  g_stp);
    cudaGetSymbolAddress((void**)&att1, g_att1);
    cudaGetSymbolAddress((void**)&kqv2, g_kqv2);
    cudaGetSymbolAddress((void**)&a2r,  g_a2r);
    cudaGetSymbolAddress((void**)&a2e,  g_a2e);
    cudaGetSymbolAddress((void**)&stA,  g_stA);
    cudaGetSymbolAddress((void**)&stB,  g_stB);
    cudaGetSymbolAddress((void**)&s_part, g_part);
    cudaGetSymbolAddress((void**)&pO, g_pO);
    cudaGetSymbolAddress((void**)&pm, g_pm);
    cudaGetSymbolAddress((void**)&pl, g_pl);
    cudaGetSymbolAddress((void**)&WkqvF, g_WkqvF);
    cudaGetSymbolAddress((void**)&WstP,  g_WstP);
    cudaGetSymbolAddress((void**)&W2ss,  g_W2ss);
    cudaGetSymbolAddress((void**)&W2mid, g_W2mid);
    cudaGetSymbolAddress((void**)&W2se,  g_W2se);

    const int SM64  = (128*68 + 64*68 + 64*68 + 128*68) * 4;    // 104448
    const int SM128 = (128*132 + 64*132 + 128*68 + 128*68) * 4; // 171008
    cudaFuncSetAttribute(flash_k<64,false>,  cudaFuncAttributeMaxDynamicSharedMemorySize, SM64);
    cudaFuncSetAttribute(flash_k<128,true>,  cudaFuncAttributeMaxDynamicSharedMemorySize, SM128);

    static cudaStream_t s2 = nullptr;
    static cudaEvent_t evF[NSEG_];
    static cudaEvent_t evJ = nullptr;
    if (!s2) {
        cudaStreamCreateWithFlags(&s2, cudaStreamNonBlocking);
        for (int i = 0; i < NSEG_; i++)
            cudaEventCreateWithFlags(&evF[i], cudaEventDisableTiming);
        cudaEventCreateWithFlags(&evJ, cudaEventDisableTiming);
    }

    BTab tab2; // level-2 projections: rows 0-127 ss, 128-639 mid, 640-767 se
    tab2.p[0] = W2ss; tab2.p[1] = W2mid; tab2.p[2] = W2mid;
    tab2.p[3] = W2mid; tab2.p[4] = W2mid; tab2.p[5] = W2se;
    tab2.p[6] = W2mid; tab2.p[7] = W2mid;

    bool tailFits = (out_size >= B_*S_*D_ + B_*SL_*D_);
    const long long KQV2SEG = (long long)B_*H_*L_*384;

    // launches 0-4; index 5 = flash1 of seg 0 (ncu -s 5 -c 1 target)
    bcast_state<<<(B_*SL_*D_ + 255)/256, 256>>>(stA, state);           // 0
    pack3<<<(H_*D_*192 + 255)/256, 256>>>(WkqvF, Wk, Wq, Wv, H_*D_, 64);   // 1
    pack3<<<(H_*D_*192 + 255)/256, 256>>>(WstP, Wk_st, Wq_st, Wv_st, H_*D_, 64); // 2
    G(false, x, WkqvF, kqvf, S_, 192, D_, D_, 192, 192,                // 3
      (long long)S_*D_, 0, 0, (long long)D_*192,
      (long long)H_*S_*192, (long long)S_*192, H_, B_*H_);

    for (int seg = 0; seg < NSEG_; seg++) {
        float* stc = (seg & 1) ? stB : stA;
        float* stn = (seg & 1) ? stA : stB;
        if (seg == NSEG_-1 && tailFits) stn = out + (size_t)B_*S_*D_;
        float* kqv2s = kqv2 + (long long)seg * KQV2SEG;

        // state K|Q|V projection -> stp (single launch)         seg0: index 4
        G(false, stc, WstP, stp, SL_, 192, D_, D_, 192, 192,
          (long long)SL_*D_, 0, 0, (long long)D_*192,
          (long long)H_*SL_*192, (long long)SL_*192, H_, B_*H_);

        // attention 1: split-KV z=2 partial                     seg0: index 5
        flash_k<64,false><<<dim3(L_/128, B_*H_, 2), 256, SM64>>>(
            stp, kqvf + (long long)seg*SEG_*192, 192,
            (long long)SL_*192, (long long)S_*192, 64, 0, 128,
            nullptr, 0, nullptr, 0, pO, pm, pl, 2, L_, 0);

        if (seg == 0) {  // lvl2 weight packs (once; between flash1 and merge1)
            pack3<<<(H_*64*384 + 255)/256, 256>>>(W2ss,  W2k_ss, W2q_ss, W2v_ss, H_*64, 128);
            pack3<<<(H_*64*384 + 255)/256, 256>>>(W2mid, W2k,    W2k,    W2k,    H_*64, 128);
            pack3<<<(H_*64*384 + 255)/256, 256>>>(W2se,  W2k_se, W2q_se, W2v_se, H_*64, 128);
        }

        merge1<<<(B_*H_*L_*64 + 255)/256, 256>>>(att1, pO, pm, pl);

        // level-2 projections into per-seg kqv2 buffer
        G(false, att1, nullptr, kqv2s, L_, 384, DV_, DV_, 384, 384,
          (long long)H_*L_*DV_, (long long)L_*DV_, 0, (long long)64*384,
          (long long)H_*L_*384, (long long)L_*384, H_, B_*H_, 1, 1, tab2);

        // fork: a2r row-blocks + out-GEMM on side stream
        cudaEventRecord(evF[seg], 0);
        cudaStreamWaitEvent(s2, evF[seg], 0);
        flash_k<128,true><<<dim3(4, B_*H_), 256, SM128, s2>>>(
            kqv2s, nullptr, 384, (long long)L_*384, 0, 128, 0, 256,
            a2r + (long long)seg*SEG_*2048, (long long)NSEG_*SEG_*2048, a2e,
            1, nullptr, nullptr, nullptr, 0, 0, 0);
        G(false, a2r + (long long)seg*SEG_*2048, Wout, out + (size_t)seg*SEG_*D_,
          SEG_, D_, 2048, 2048, D_, D_,
          (long long)NSEG_*SEG_*2048, 0, 0, 0, (long long)S_*D_, 0, 1, B_,
          1, 0, BTab{}, s2);

        // critical path: split-KV z=4 flash for a2e rows, then merge
        flash_k<128,true><<<dim3(1, B_*H_, 4), 256, SM128>>>(
            kqv2s, nullptr, 384, (long long)L_*384, 0, 128, 0, 256,
            a2r + (long long)seg*SEG_*2048, (long long)NSEG_*SEG_*2048, a2e,
            5, pO, pm, pl, 4, SL_, 640);
        mergeKV<<<(B_*H_*SL_*128 + 255)/256, 256>>>(a2e, pO, pm, pl);

        // next state (split-K x8)
        G(false, a2e, Wout_st, stn, SL_, D_, 2048, 2048, D_, D_,
          (long long)SL_*2048, 0, 0, 0, (long long)SL_*D_, 0, 1, B_, 8);
    }

    // join side stream back into origin stream
    cudaEventRecord(evJ, s2);
    cudaStreamWaitEvent(0, evJ, 0);

    if (!tailFits) {
        int st_elems = B_ * SL_ * D_;
        if (out_size >= B_*S_*D_ + st_elems) {
            copy_f<<<(st_elems + 255)/256, 256>>>(out + (size_t)B_*S_*D_, stA, st_elems);
        }
    }
}

// round 15
// speedup vs baseline: 1.2053x; 1.0135x over previous
#include <cuda_runtime.h>
#include <cstdint>

#define B_ 2
#define S_ 2048
#define D_ 1024
#define H_ 16
#define DK_ 64
#define DV_ 64
#define SEG_ 512
#define SL_ 128
#define L_ 768
#define NSEG_ 4

// ---------------- scratch (device globals: allocation-free) ----------------
__device__ float g_kqvf[(size_t)B_*H_*S_*192];
__device__ float g_stp [(size_t)B_*H_*SL_*192];
__device__ float g_att1[(size_t)B_*H_*L_*64];
__device__ float g_kqv2[(size_t)NSEG_*B_*H_*L_*384];
__device__ float g_a2r [(size_t)B_*NSEG_*SEG_*2048];
__device__ float g_a2e [(size_t)B_*SL_*2048];
__device__ float g_stA[(size_t)B_*SL_*D_];
__device__ float g_stB[(size_t)B_*SL_*D_];
__device__ float g_part[(size_t)4*1024*1024];
__device__ float g_pO [(size_t)4*1024*1024];
__device__ float g_pm [(size_t)64*1024];
__device__ float g_pl [(size_t)64*1024];
__device__ float g_WkqvF[(size_t)H_*D_*192];
__device__ float g_WstP [(size_t)H_*D_*192];
__device__ float g_W2ss [(size_t)H_*64*384];
__device__ float g_W2mid[(size_t)H_*64*384];
__device__ float g_W2se [(size_t)H_*64*384];

struct BTab { const float* p[8]; };

// ---------------- tf32 helpers ----------------
__device__ __forceinline__ uint32_t f2tf(float f) {
    uint32_t u;
    asm("cvt.rna.tf32.f32 %0, %1;" : "=r"(u) : "f"(f));
    return u;
}
__device__ __forceinline__ uint4 f2tf4(float4 v) {
    uint4 u;
    u.x = f2tf(v.x); u.y = f2tf(v.y); u.z = f2tf(v.z); u.w = f2tf(v.w);
    return u;
}
__device__ __forceinline__ void mma8(float* c, const uint32_t* a, const uint32_t* b) {
    asm volatile(
        "mma.sync.aligned.m16n8k8.row.col.f32.tf32.tf32.f32 "
        "{%0,%1,%2,%3}, {%4,%5,%6,%7}, {%8,%9}, {%0,%1,%2,%3};\n"
        : "+f"(c[0]), "+f"(c[1]), "+f"(c[2]), "+f"(c[3])
        : "r"(a[0]), "r"(a[1]), "r"(a[2]), "r"(a[3]), "r"(b[0]), "r"(b[1]));
}
// NOTE: k-slot permutation removed. Natural storage + fragment reads at
// [8s + 2q] give hardware k-positions (q, q+4) physical slots (2q, 2q+1)
// CONSISTENTLY for both mma operands -> dot product unchanged (k-order
// invariance). Enables STS.128 tile stores and STS.64 S-stores.

// ---------------- batched strided tf32 tensor-core GEMM (BK=16) ----------------
template<int BM, int BN, int WM, int WN, bool TB>
__global__ void __launch_bounds__(256) gemm_t(
    const float* __restrict__ A, const float* __restrict__ Bm0, float* __restrict__ C,
    int M, int N, int K, int lda, int ldb, int ldc,
    long long aSB, long long aSH, long long bSB, long long bSH,
    long long cSB, long long cSH, int Hd, int Zr,
    int sk, int Kc, long long pcs, int useTab, BTab tab)
{
    constexpr int BK = 16;
    constexpr int KS = BK / 8;
    constexpr int MF = WM / 16;
    constexpr int NF = WN / 8;
    constexpr int WCOL = BN / WN;
    constexpr int NA4 = BM * BK / 1024;
    constexpr int NB4 = BN * BK / 1024;
    constexpr int KQ = BK / 4;

    int z = blockIdx.z;
    int ks = 0, zz = z;
    if (sk > 1) { ks = z / Zr; zz = z - ks * Zr; }
    int b = zz / Hd, h = zz - b * Hd;
    const float* Bm = useTab ? tab.p[blockIdx.y] : Bm0;
    A  += (long long)b * aSB + (long long)h * aSH;
    Bm += (long long)b * bSB + (long long)h * bSH;
    C  += (long long)ks * pcs + (long long)b * cSB + (long long)h * cSH;

    int row0 = blockIdx.y * BM;
    int col0 = blockIdx.x * BN;

    int kBeg = ks * Kc;
    int nk = Kc / BK;

    __shared__ uint32_t As[2][BM][BK + 4];
    __shared__ uint32_t Bs[2][BN][BK + 4];

    int tid = threadIdx.x;
    int w   = tid >> 5;
    int lane = tid & 31;
    int g = lane >> 2, q = lane & 3;
    int warpM = w / WCOL, warpN = w % WCOL;
    int wr = warpM * WM;
    int wc = warpN * WN;

    float4 ag[NA4], bg[NB4];

    {
        int kb = kBeg;
        #pragma unroll
        for (int i = 0; i < NA4; i++) {
            int f = tid + i * 256; int r = f / KQ; int c4 = (f % KQ) << 2;
            float4 v = *(const float4*)(A + (long long)(row0 + r) * lda + kb + c4);
            *(uint4*)&As[0][r][c4] = f2tf4(v);
        }
        if (!TB) {
            #pragma unroll
            for (int i = 0; i < NB4; i++) {
                int f = tid + i * 256; int kr = f / (BN/4); int n4 = (f % (BN/4)) << 2;
                float4 v = *(const float4*)(Bm + (long long)(kb + kr) * ldb + col0 + n4);
                Bs[0][n4+0][kr] = f2tf(v.x);
                Bs[0][n4+1][kr] = f2tf(v.y);
                Bs[0][n4+2][kr] = f2tf(v.z);
                Bs[0][n4+3][kr] = f2tf(v.w);
            }
        } else {
            #pragma unroll
            for (int i = 0; i < NB4; i++) {
                int f = tid + i * 256; int r = f / KQ; int c4 = (f % KQ) << 2;
                float4 v = *(const float4*)(Bm + (long long)(col0 + r) * ldb + kb + c4);
                *(uint4*)&Bs[0][r][c4] = f2tf4(v);
            }
        }
    }
    __syncthreads();

    float acc[MF][NF][4];
    #pragma unroll
    for (int i = 0; i < MF; i++)
        #pragma unroll
        for (int j = 0; j < NF; j++)
            #pragma unroll
            for (int e = 0; e < 4; e++) acc[i][j][e] = 0.f;

    int cur = 0;
    for (int t = 0; t < nk; t++) {
        if (t + 1 < nk) {
            int kb = kBeg + (t + 1) * BK;
            #pragma unroll
            for (int i = 0; i < NA4; i++) {
                int f = tid + i * 256; int r = f / KQ; int c4 = (f % KQ) << 2;
                ag[i] = *(const float4*)(A + (long long)(row0 + r) * lda + kb + c4);
            }
            if (!TB) {
                #pragma unroll
                for (int i = 0; i < NB4; i++) {
                    int f = tid + i * 256; int kr = f / (BN/4); int n4 = (f % (BN/4)) << 2;
                    bg[i] = *(const float4*)(Bm + (long long)(kb + kr) * ldb + col0 + n4);
                }
            } else {
                #pragma unroll
                for (int i = 0; i < NB4; i++) {
                    int f = tid + i * 256; int r = f / KQ; int c4 = (f % KQ) << 2;
                    bg[i] = *(const float4*)(Bm + (long long)(col0 + r) * ldb + kb + c4);
                }
            }
        }
        #pragma unroll
        for (int s = 0; s < KS; s++) {
            uint32_t af[MF][4], bf[NF][2];
            #pragma unroll
            for (int i = 0; i < MF; i++) {
                uint2 lo = *(const uint2*)&As[cur][wr + 16*i + g    ][8*s + 2*q];
                uint2 hi = *(const uint2*)&As[cur][wr + 16*i + g + 8][8*s + 2*q];
                af[i][0] = lo.x; af[i][1] = hi.x; af[i][2] = lo.y; af[i][3] = hi.y;
            }
            #pragma unroll
            for (int j = 0; j < NF; j++) {
                uint2 bb = *(const uint2*)&Bs[cur][wc + 8*j + g][8*s + 2*q];
                bf[j][0] = bb.x; bf[j][1] = bb.y;
            }
            #pragma unroll
            for (int i = 0; i < MF; i++)
                #pragma unroll
                for (int j = 0; j < NF; j++)
                    mma8(acc[i][j], af[i], bf[j]);
        }
        if (t + 1 < nk) {
            int nxt = cur ^ 1;
            #pragma unroll
            for (int i = 0; i < NA4; i++) {
                int f = tid + i * 256; int r = f / KQ; int c4 = (f % KQ) << 2;
                *(uint4*)&As[nxt][r][c4] = f2tf4(ag[i]);
            }
            if (!TB) {
                #pragma unroll
                for (int i = 0; i < NB4; i++) {
                    int f = tid + i * 256; int kr = f / (BN/4); int n4 = (f % (BN/4)) << 2;
                    Bs[nxt][n4+0][kr] = f2tf(bg[i].x);
                    Bs[nxt][n4+1][kr] = f2tf(bg[i].y);
                    Bs[nxt][n4+2][kr] = f2tf(bg[i].z);
                    Bs[nxt][n4+3][kr] = f2tf(bg[i].w);
                }
            } else {
                #pragma unroll
                for (int i = 0; i < NB4; i++) {
                    int f = tid + i * 256; int r = f / KQ; int c4 = (f % KQ) << 2;
                    *(uint4*)&Bs[nxt][r][c4] = f2tf4(bg[i]);
                }
            }
            __syncthreads();
            cur = nxt;
        }
    }

    #pragma unroll
    for (int i = 0; i < MF; i++) {
        #pragma unroll
        for (int j = 0; j < NF; j++) {
            int r0 = row0 + wr + 16*i + g;
            int c0 = col0 + wc + 8*j + 2*q;
            *(float2*)(C + (long long)r0 * ldc + c0) = make_float2(acc[i][j][0], acc[i][j][1]);
            *(float2*)(C + (long long)(r0 + 8) * ldc + c0) = make_float2(acc[i][j][2], acc[i][j][3]);
        }
    }
}

// ---------------- fused flash attention (tf32 mma, online softmax) ----------
template<int DH, bool GATHER>
__global__ void __launch_bounds__(256) flash_k(
    const float* __restrict__ b1, const float* __restrict__ b2, int ld,
    long long b1S, long long b2S, int qoff, int koff, int voff,
    float* __restrict__ out0, long long o0b, float* __restrict__ out1,
    int rbOff, float* __restrict__ pO, float* __restrict__ pm, float* __restrict__ pl,
    int nSplit, int pRows, int pSub)
{
    constexpr int BR = 128, BC = 64;
    constexpr int QW = DH + 4, KW = DH + 4, VW = BC + 4, SW = BC + 4;
    extern __shared__ uint32_t sm[];
    uint32_t* Qs = sm;
    uint32_t* Ks = Qs + BR * QW;
    uint32_t* Vs = Ks + BC * KW;
    uint32_t* Ss = Vs + DH * VW;

    int bh = blockIdx.y;
    int b = bh / H_, h = bh - b * H_;

    const float* stb  = b1 + (long long)bh * b1S;
    const float* segb = GATHER ? stb : (b2 + (long long)bh * b2S);

    int row0 = (GATHER ? ((int)blockIdx.x + rbOff) : (int)blockIdx.x) * BR;

    const float* Qb;
    if (GATHER) {
        Qb = stb + (long long)row0 * ld;
    } else {
        if (row0 < SL_)            Qb = stb;
        else if (row0 < SL_+SEG_)  Qb = segb + (long long)(row0 - SL_) * ld;
        else                       Qb = stb;
    }

    int tid = threadIdx.x, w = tid >> 5, lane = tid & 31;
    int g = lane >> 2, q = lane & 3;
    int wr = w * 16;

    constexpr int NQ4 = BR * DH / 1024;
    #pragma unroll
    for (int i = 0; i < NQ4; i++) {
        int f = tid + i * 256; int r = f / (DH/4); int c4 = (f % (DH/4)) << 2;
        float4 v = *(const float4*)(Qb + (long long)r * ld + qoff + c4);
        *(uint4*)&Qs[r*QW + c4] = f2tf4(v);
    }

    float Ofr[DH/8][4];
    #pragma unroll
    for (int j = 0; j < DH/8; j++)
        #pragma unroll
        for (int e = 0; e < 4; e++) Ofr[j][e] = 0.f;
    float m_a = -1e30f, m_b = -1e30f, l_a = 0.f, l_b = 0.f;
    int row_a = row0 + wr + g, row_b = row_a + 8;

    int nb = row0 / BC + 2;
    int cb0 = 0, cb1 = nb;
    if (pO) {
        int half = (nb + nSplit - 1) / nSplit;
        cb0 = blockIdx.z * half;
        cb1 = cb0 + half; if (cb1 > nb) cb1 = nb;
    }
    constexpr int NK4 = BC * DH / 1024;

    for (int cb = cb0; cb < cb1; cb++) {
        int c0 = cb * BC;
        const float* Kb;
        if (GATHER) {
            Kb = stb + (long long)c0 * ld;
        } else {
            if (c0 < SL_)            Kb = stb + (long long)c0 * ld;
            else if (c0 < SL_+SEG_)  Kb = segb + (long long)(c0 - SL_) * ld;
            else                     Kb = stb + (long long)(c0 - SL_ - SEG_) * ld;
        }
        __syncthreads();
        #pragma unroll
        for (int i = 0; i < NK4; i++) {
            int f = tid + i * 256; int r = f / (DH/4); int c4 = (f % (DH/4)) << 2;
            float4 v = *(const float4*)(Kb + (long long)r * ld + koff + c4);
            *(uint4*)&Ks[r*KW + c4] = f2tf4(v);
        }
        #pragma unroll
        for (int i = 0; i < NK4; i++) {
            int f = tid + i * 256; int c = f / (DH/4); int d4 = (f % (DH/4)) << 2;
            float4 v = *(const float4*)(Kb + (long long)c * ld + voff + d4);
            Vs[(d4+0)*VW + c] = f2tf(v.x);
            Vs[(d4+1)*VW + c] = f2tf(v.y);
            Vs[(d4+2)*VW + c] = f2tf(v.z);
            Vs[(d4+3)*VW + c] = f2tf(v.w);
        }
        __syncthreads();

        float sfr[BC/8][4];
        #pragma unroll
        for (int j = 0; j < BC/8; j++)
            #pragma unroll
            for (int e = 0; e < 4; e++) sfr[j][e] = 0.f;
        #pragma unroll
        for (int s = 0; s < DH/8; s++) {
            uint32_t af[4];
            uint2 lo = *(const uint2*)&Qs[(wr+g  )*QW + 8*s + 2*q];
            uint2 hi = *(const uint2*)&Qs[(wr+g+8)*QW + 8*s + 2*q];
            af[0] = lo.x; af[1] = hi.x; af[2] = lo.y; af[3] = hi.y;
            #pragma unroll
            for (int j = 0; j < BC/8; j++) {
                uint2 bb = *(const uint2*)&Ks[(8*j+g)*KW + 8*s + 2*q];
                uint32_t bf[2] = {bb.x, bb.y};
                mma8(sfr[j], af, bf);
            }
        }

        bool needm = (c0 + BC - 1 > row0 + wr);
        float mb_a = -1e30f, mb_b = -1e30f;
        #pragma unroll
        for (int j = 0; j < BC/8; j++) {
            int col = c0 + 8*j + 2*q;
            float s0 = sfr[j][0]*0.125f, s1 = sfr[j][1]*0.125f;
            float s2 = sfr[j][2]*0.125f, s3 = sfr[j][3]*0.125f;
            if (needm) {
                if (col     > row_a) s0 = -1e30f;
                if (col + 1 > row_a) s1 = -1e30f;
                if (col     > row_b) s2 = -1e30f;
                if (col + 1 > row_b) s3 = -1e30f;
            }
            sfr[j][0]=s0; sfr[j][1]=s1; sfr[j][2]=s2; sfr[j][3]=s3;
            mb_a = fmaxf(mb_a, fmaxf(s0, s1));
            mb_b = fmaxf(mb_b, fmaxf(s2, s3));
        }
        mb_a = fmaxf(mb_a, __shfl_xor_sync(0xffffffffu, mb_a, 1));
        mb_a = fmaxf(mb_a, __shfl_xor_sync(0xffffffffu, mb_a, 2));
        mb_b = fmaxf(mb_b, __shfl_xor_sync(0xffffffffu, mb_b, 1));
        mb_b = fmaxf(mb_b, __shfl_xor_sync(0xffffffffu, mb_b, 2));
        float mn_a = fmaxf(m_a, mb_a), mn_b = fmaxf(m_b, mb_b);
        float ra = __expf(m_a - mn_a), rb2 = __expf(m_b - mn_b);
        float sa = 0.f, sb = 0.f;
        #pragma unroll
        for (int j = 0; j < BC/8; j++) {
            float p0 = __expf(sfr[j][0] - mn_a), p1 = __expf(sfr[j][1] - mn_a);
            float p2 = __expf(sfr[j][2] - mn_b), p3 = __expf(sfr[j][3] - mn_b);
            sa += p0 + p1; sb += p2 + p3;
            int cc = 8*j + 2*q;
            *(uint2*)&Ss[(wr+g  )*SW + cc] = make_uint2(f2tf(p0), f2tf(p1));
            *(uint2*)&Ss[(wr+g+8)*SW + cc] = make_uint2(f2tf(p2), f2tf(p3));
        }
        sa += __shfl_xor_sync(0xffffffffu, sa, 1);
        sa += __shfl_xor_sync(0xffffffffu, sa, 2);
        sb += __shfl_xor_sync(0xffffffffu, sb, 1);
        sb += __shfl_xor_sync(0xffffffffu, sb, 2);
        l_a = l_a * ra + sa; l_b = l_b * rb2 + sb;
        m_a = mn_a; m_b = mn_b;
        #pragma unroll
        for (int j2 = 0; j2 < DH/8; j2++) {
            Ofr[j2][0] *= ra; Ofr[j2][1] *= ra;
            Ofr[j2][2] *= rb2; Ofr[j2][3] *= rb2;
        }
        __syncwarp();

        #pragma unroll
        for (int s = 0; s < BC/8; s++) {
            uint32_t af[4];
            uint2 lo = *(const uint2*)&Ss[(wr+g  )*SW + 8*s + 2*q];
            uint2 hi = *(const uint2*)&Ss[(wr+g+8)*SW + 8*s + 2*q];
            af[0] = lo.x; af[1] = hi.x; af[2] = lo.y; af[3] = hi.y;
            #pragma unroll
            for (int j2 = 0; j2 < DH/8; j2++) {
                uint2 bb = *(const uint2*)&Vs[(8*j2+g)*VW + 8*s + 2*q];
                uint32_t bf[2] = {bb.x, bb.y};
                mma8(Ofr[j2], af, bf);
            }
        }
    }

    if (pO) {
        #pragma unroll
        for (int rr = 0; rr < 2; rr++) {
            int pr = ((rr == 0) ? row_a : row_b) - pSub;
            long long base = ((long long)blockIdx.z * (B_*H_) + bh) * pRows + pr;
            float* dst = pO + base * DH;
            #pragma unroll
            for (int j2 = 0; j2 < DH/8; j2++) {
                int col = 8*j2 + 2*q;
                *(float2*)(dst + col) =
                    make_float2(Ofr[j2][rr ? 2 : 0], Ofr[j2][rr ? 3 : 1]);
            }
            if (q == 0) {
                pm[base] = (rr == 0) ? m_a : m_b;
                pl[base] = (rr == 0) ? l_a : l_b;
            }
        }
        return;
    }

    float ia = 1.f / l_a, ib = 1.f / l_b;
    if (!GATHER) {
        float* oa = out0 + (long long)bh * L_ * DH + (long long)row_a * DH;
        float* ob = out0 + (long long)bh * L_ * DH + (long long)row_b * DH;
        #pragma unroll
        for (int j2 = 0; j2 < DH/8; j2++) {
            int col = 8*j2 + 2*q;
            *(float2*)(oa + col) = make_float2(Ofr[j2][0]*ia, Ofr[j2][1]*ia);
            *(float2*)(ob + col) = make_float2(Ofr[j2][2]*ib, Ofr[j2][3]*ib);
        }
    } else {
        #pragma unroll
        for (int rr = 0; rr < 2; rr++) {
            int s_abs = (rr == 0) ? row_a : row_b;
            float inv = (rr == 0) ? ia : ib;
            float* dst;
            if (s_abs < SL_ + SEG_) {
                int s = s_abs - SL_;
                dst = out0 + (long long)b * o0b
                    + (long long)((h << 5) + (s >> 4)) * 2048 + ((s & 15) << 7);
            } else {
                int s = s_abs - (SL_ + SEG_);
                dst = out1 + ((long long)b * SL_ + (h << 3) + (s >> 4)) * 2048
                    + ((s & 15) << 7);
            }
            #pragma unroll
            for (int j2 = 0; j2 < DH/8; j2++) {
                int col = 8*j2 + 2*q;
                float v0 = Ofr[j2][rr ? 2 : 0] * inv;
                float v1 = Ofr[j2][rr ? 3 : 1] * inv;
                *(float2*)(dst + col) = make_float2(v0, v1);
            }
        }
    }
}

// merge 4 split-KV partials (DH=128) -> gathered a2e layout
__global__ void mergeKV(float* __restrict__ a2e, const float* __restrict__ pO,
                        const float* __restrict__ pm, const float* __restrict__ pl)
{
    int idx = blockIdx.x * blockDim.x + threadIdx.x;
    const int tot = B_ * H_ * SL_ * 128;
    if (idx >= tot) return;
    int col = idx & 127;
    int r   = (idx >> 7) & 127;
    int bh  = idx >> 14;
    int b = bh / H_, h = bh - b * H_;
    const int P = B_ * H_ * SL_;
    float M = -1e30f;
    #pragma unroll
    for (int s = 0; s < 4; s++) M = fmaxf(M, pm[s*P + bh*SL_ + r]);
    float num = 0.f, den = 0.f;
    #pragma unroll
    for (int s = 0; s < 4; s++) {
        float wgt = __expf(pm[s*P + bh*SL_ + r] - M);
        den += wgt * pl[s*P + bh*SL_ + r];
        num += wgt * pO[((long long)s*P + (long long)bh*SL_ + r) * 128 + col];
    }
    a2e[((long long)(b * SL_ + (h << 3) + (r >> 4))) * 2048 + ((r & 15) << 7) + col]
        = num / den;
}

// merge 2 split-KV partials (DH=64) -> dense att1
__global__ void merge1(float* __restrict__ att1, const float* __restrict__ pO,
                       const float* __restrict__ pm, const float* __restrict__ pl)
{
    int idx = blockIdx.x * blockDim.x + threadIdx.x;
    const int tot = B_ * H_ * L_ * 64;
    if (idx >= tot) return;
    int col = idx & 63;
    int r   = (idx >> 6) % L_;
    int bh  = idx / (L_ * 64);
    const int P = B_ * H_ * L_;
    float m0 = pm[bh*L_ + r], m1 = pm[P + bh*L_ + r];
    float M = fmaxf(m0, m1);
    float w0 = __expf(m0 - M), w1 = __expf(m1 - M);
    float O0 = pO[((long long)bh*L_ + r) * 64 + col];
    float O1 = pO[((long long)P + (long long)bh*L_ + r) * 64 + col];
    att1[((long long)bh*L_ + r) * 64 + col]
        = (w0*O0 + w1*O1) / (w0*pl[bh*L_ + r] + w1*pl[P + bh*L_ + r]);
}

// generic split-K reduce
__global__ void reduceK(float* __restrict__ C, const float* __restrict__ part,
    int sk, long long chunk, int M, int N, int ldc,
    long long cSB, long long cSH, int Hd)
{
    long long idx = (long long)blockIdx.x * blockDim.x + threadIdx.x;
    if (idx >= chunk) return;
    int n = (int)(idx % N);
    long long t = idx / N;
    int m = (int)(t % M);
    int zz = (int)(t / M);
    int b = zz / Hd, h = zz - b * Hd;
    float s = 0.f;
    for (int i = 0; i < sk; i++) s += part[(long long)i * chunk + idx];
    C[(long long)b * cSB + (long long)h * cSH + (long long)m * ldc + n] = s;
}

__global__ void pack3(float* __restrict__ dst, const float* __restrict__ s0,
                      const float* __restrict__ s1, const float* __restrict__ s2,
                      int n, int w)
{
    int idx = blockIdx.x * blockDim.x + threadIdx.x;
    int tot = n * 3 * w;
    if (idx >= tot) return;
    int c = idx % w; int o = (idx / w) % 3; int i = idx / (3 * w);
    const float* s = (o == 0) ? s0 : ((o == 1) ? s1 : s2);
    dst[idx] = s[(size_t)i * w + c];
}

__global__ void bcast_state(float* __restrict__ st, const float* __restrict__ state)
{
    int idx = blockIdx.x * blockDim.x + threadIdx.x;
    const int total = B_ * SL_ * D_;
    if (idx >= total) return;
    st[idx] = state[idx % (SL_ * D_)];
}

__global__ void copy_f(float* __restrict__ dst, const float* __restrict__ src, int n)
{
    int idx = blockIdx.x * blockDim.x + threadIdx.x;
    if (idx < n) dst[idx] = src[idx];
}

// ---------------- host ----------------
static float* s_part = nullptr;

static void G(bool tb, const float* A, const float* Bm, float* C,
              int M, int N, int K, int lda, int ldb, int ldc,
              long long aSB, long long aSH, long long bSB, long long bSH,
              long long cSB, long long cSH, int Hd, int Z, int sk = 1,
              int useTab = 0, BTab tab = {}, cudaStream_t st = 0)
{
    int Kc = K / sk;
    long long pcs = 0;
    float* Cout = C;
    long long csb = cSB, csh = cSH;
    int ldc2 = ldc;
    if (sk > 1) {
        pcs = (long long)Z * M * N;
        Cout = s_part; ldc2 = N;
        csh = (long long)M * N;
        csb = (long long)Hd * M * N;
    }
    dim3 blk(256);
    if (N % 128 == 0) {
        dim3 grid(N / 128, (M + 127) / 128, Z * sk);
        if (tb) gemm_t<128,128,64,32,true ><<<grid, blk, 0, st>>>(A, Bm, Cout, M, N, K, lda, ldb, ldc2,
            aSB, aSH, bSB, bSH, csb, csh, Hd, Z, sk, Kc, pcs, useTab, tab);
        else    gemm_t<128,128,64,32,false><<<grid, blk, 0, st>>>(A, Bm, Cout, M, N, K, lda, ldb, ldc2,
            aSB, aSH, bSB, bSH, csb, csh, Hd, Z, sk, Kc, pcs, useTab, tab);
    } else {
        dim3 grid(N / 64, (M + 127) / 128, Z * sk);
        if (tb) gemm_t<128,64,32,32,true ><<<grid, blk, 0, st>>>(A, Bm, Cout, M, N, K, lda, ldb, ldc2,
            aSB, aSH, bSB, bSH, csb, csh, Hd, Z, sk, Kc, pcs, useTab, tab);
        else    gemm_t<128,64,32,32,false><<<grid, blk, 0, st>>>(A, Bm, Cout, M, N, K, lda, ldb, ldc2,
            aSB, aSH, bSB, bSH, csb, csh, Hd, Z, sk, Kc, pcs, useTab, tab);
    }
    if (sk > 1) {
        long long chunk = (long long)Z * M * N;
        reduceK<<<(unsigned)((chunk + 255) / 256), 256, 0, st>>>(C, s_part, sk, chunk,
            M, N, ldc, cSB, cSH, Hd);
    }
}

extern "C" void kernel_launch(void* const* d_in, const int* in_sizes, int n_in,
                              void* d_out, int out_size)
{
    const float* x       = (const float*)d_in[0];
    const float* state   = (const float*)d_in[1];
    const float* Wk      = (const float*)d_in[2];
    const float* Wq      = (const float*)d_in[3];
    const float* Wv      = (const float*)d_in[4];
    const float* W2k     = (const float*)d_in[5];
    const float* Wout    = (const float*)d_in[6];
    const float* Wk_st   = (const float*)d_in[7];
    const float* Wq_st   = (const float*)d_in[8];
    const float* Wv_st   = (const float*)d_in[9];
    const float* W2k_ss  = (const float*)d_in[10];
    const float* W2q_ss  = (const float*)d_in[11];
    const float* W2v_ss  = (const float*)d_in[12];
    const float* W2k_se  = (const float*)d_in[13];
    const float* W2q_se  = (const float*)d_in[14];
    const float* W2v_se  = (const float*)d_in[15];
    const float* Wout_st = (const float*)d_in[16];
    float* out = (float*)d_out;

    float *kqvf,*stp,*att1,*kqv2,*a2r,*a2e,*stA,*stB,*pO,*pm,*pl;
    float *WkqvF,*WstP,*W2ss,*W2mid,*W2se;
    cudaGetSymbolAddress((void**)&kqvf, g_kqvf);
    cudaGetSymbolAddress((void**)&stp,  g_stp);
    cudaGetSymbolAddress((void**)&att1, g_att1);
    cudaGetSymbolAddress((void**)&kqv2, g_kqv2);
    cudaGetSymbolAddress((void**)&a2r,  g_a2r);
    cudaGetSymbolAddress((void**)&a2e,  g_a2e);
    cudaGetSymbolAddress((void**)&stA,  g_stA);
    cudaGetSymbolAddress((void**)&stB,  g_stB);
    cudaGetSymbolAddress((void**)&s_part, g_part);
    cudaGetSymbolAddress((void**)&pO, g_pO);
    cudaGetSymbolAddress((void**)&pm, g_pm);
    cudaGetSymbolAddress((void**)&pl, g_pl);
    cudaGetSymbolAddress((void**)&WkqvF, g_WkqvF);
    cudaGetSymbolAddress((void**)&WstP,  g_WstP);
    cudaGetSymbolAddress((void**)&W2ss,  g_W2ss);
    cudaGetSymbolAddress((void**)&W2mid, g_W2mid);
    cudaGetSymbolAddress((void**)&W2se,  g_W2se);

    const int SM64  = (128*68 + 64*68 + 64*68 + 128*68) * 4;    // 104448
    const int SM128 = (128*132 + 64*132 + 128*68 + 128*68) * 4; // 171008
    cudaFuncSetAttribute(flash_k<64,false>,  cudaFuncAttributeMaxDynamicSharedMemorySize, SM64);
    cudaFuncSetAttribute(flash_k<128,true>,  cudaFuncAttributeMaxDynamicSharedMemorySize, SM128);

    static cudaStream_t s2 = nullptr;
    static cudaEvent_t evF[NSEG_];
    static cudaEvent_t evJ = nullptr;
    if (!s2) {
        cudaStreamCreateWithFlags(&s2, cudaStreamNonBlocking);
        for (int i = 0; i < NSEG_; i++)
            cudaEventCreateWithFlags(&evF[i], cudaEventDisableTiming);
        cudaEventCreateWithFlags(&evJ, cudaEventDisableTiming);
    }

    BTab tab2; // level-2 projections: rows 0-127 ss, 128-639 mid, 640-767 se
    tab2.p[0] = W2ss; tab2.p[1] = W2mid; tab2.p[2] = W2mid;
    tab2.p[3] = W2mid; tab2.p[4] = W2mid; tab2.p[5] = W2se;
    tab2.p[6] = W2mid; tab2.p[7] = W2mid;

    bool tailFits = (out_size >= B_*S_*D_ + B_*SL_*D_);
    const long long KQV2SEG = (long long)B_*H_*L_*384;

    // launches 0-4; index 5 = flash1 of seg 0 (ncu -s 5 -c 1 target)
    bcast_state<<<(B_*SL_*D_ + 255)/256, 256>>>(stA, state);
    pack3<<<(H_*D_*192 + 255)/256, 256>>>(WkqvF, Wk, Wq, Wv, H_*D_, 64);
    pack3<<<(H_*D_*192 + 255)/256, 256>>>(WstP, Wk_st, Wq_st, Wv_st, H_*D_, 64);
    G(false, x, WkqvF, kqvf, S_, 192, D_, D_, 192, 192,
      (long long)S_*D_, 0, 0, (long long)D_*192,
      (long long)H_*S_*192, (long long)S_*192, H_, B_*H_);

    for (int seg = 0; seg < NSEG_; seg++) {
        float* stc = (seg & 1) ? stB : stA;
        float* stn = (seg & 1) ? stA : stB;
        if (seg == NSEG_-1 && tailFits) stn = out + (size_t)B_*S_*D_;
        float* kqv2s = kqv2 + (long long)seg * KQV2SEG;

        // state K|Q|V projection -> stp
        G(false, stc, WstP, stp, SL_, 192, D_, D_, 192, 192,
          (long long)SL_*D_, 0, 0, (long long)D_*192,
          (long long)H_*SL_*192, (long long)SL_*192, H_, B_*H_);

        // attention 1: split-KV z=2 partial
        flash_k<64,false><<<dim3(L_/128, B_*H_, 2), 256, SM64>>>(
            stp, kqvf + (long long)seg*SEG_*192, 192,
            (long long)SL_*192, (long long)S_*192, 64, 0, 128,
            nullptr, 0, nullptr, 0, pO, pm, pl, 2, L_, 0);

        if (seg == 0) {
            pack3<<<(H_*64*384 + 255)/256, 256>>>(W2ss,  W2k_ss, W2q_ss, W2v_ss, H_*64, 128);
            pack3<<<(H_*64*384 + 255)/256, 256>>>(W2mid, W2k,    W2k,    W2k,    H_*64, 128);
            pack3<<<(H_*64*384 + 255)/256, 256>>>(W2se,  W2k_se, W2q_se, W2v_se, H_*64, 128);
        }

        merge1<<<(B_*H_*L_*64 + 255)/256, 256>>>(att1, pO, pm, pl);

        // level-2 projections into per-seg kqv2 buffer
        G(false, att1, nullptr, kqv2s, L_, 384, DV_, DV_, 384, 384,
          (long long)H_*L_*DV_, (long long)L_*DV_, 0, (long long)64*384,
          (long long)H_*L_*384, (long long)L_*384, H_, B_*H_, 1, 1, tab2);

        // fork: a2r row-blocks + out-GEMM on side stream
        cudaEventRecord(evF[seg], 0);
        cudaStreamWaitEvent(s2, evF[seg], 0);
        flash_k<128,true><<<dim3(4, B_*H_), 256, SM128, s2>>>(
            kqv2s, nullptr, 384, (long long)L_*384, 0, 128, 0, 256,
            a2r + (long long)seg*SEG_*2048, (long long)NSEG_*SEG_*2048, a2e,
            1, nullptr, nullptr, nullptr, 0, 0, 0);
        G(false, a2r + (long long)seg*SEG_*2048, Wout, out + (size_t)seg*SEG_*D_,
          SEG_, D_, 2048, 2048, D_, D_,
          (long long)NSEG_*SEG_*2048, 0, 0, 0, (long long)S_*D_, 0, 1, B_,
          1, 0, BTab{}, s2);

        // critical path: split-KV z=4 flash for a2e rows, then merge
        flash_k<128,true><<<dim3(1, B_*H_, 4), 256, SM128>>>(
            kqv2s, nullptr, 384, (long long)L_*384, 0, 128, 0, 256,
            a2r + (long long)seg*SEG_*2048, (long long)NSEG_*SEG_*2048, a2e,
            5, pO, pm, pl, 4, SL_, 640);
        mergeKV<<<(B_*H_*SL_*128 + 255)/256, 256>>>(a2e, pO, pm, pl);

        // next state (split-K x8)
        G(false, a2e, Wout_st, stn, SL_, D_, 2048, 2048, D_, D_,
          (long long)SL_*2048, 0, 0, 0, (long long)SL_*D_, 0, 1, B_, 8);
    }

    // join side stream back into origin stream
    cudaEventRecord(evJ, s2);
    cudaStreamWaitEvent(0, evJ, 0);

    if (!tailFits) {
        int st_elems = B_ * SL_ * D_;
        if (out_size >= B_*S_*D_ + st_elems) {
            copy_f<<<(st_elems + 255)/256, 256>>>(out + (size_t)B_*S_*D_, stA, st_elems);
        }
    }
}

// round 16
// speedup vs baseline: 1.5927x; 1.3215x over previous
#include <cuda_runtime.h>
#include <cstdint>

#define B_ 2
#define S_ 2048
#define D_ 1024
#define H_ 16
#define DK_ 64
#define DV_ 64
#define SEG_ 512
#define SL_ 128
#define L_ 768
#define NSEG_ 4

// ---------------- scratch (device globals: allocation-free) ----------------
__device__ float g_kqvf[(size_t)B_*H_*S_*192];
__device__ float g_stp [(size_t)B_*H_*SL_*192];
__device__ float g_att1[(size_t)B_*H_*L_*64];
__device__ float g_kqv2[(size_t)NSEG_*B_*H_*L_*384];
__device__ float g_a2r [(size_t)B_*NSEG_*SEG_*2048];
__device__ float g_a2e [(size_t)B_*SL_*2048];
__device__ float g_stA[(size_t)B_*SL_*D_];
__device__ float g_stB[(size_t)B_*SL_*D_];
__device__ float g_part[(size_t)4*1024*1024];
__device__ float g_pO [(size_t)4*1024*1024];
__device__ float g_pm [(size_t)64*1024];
__device__ float g_pl [(size_t)64*1024];
// transposed weights: [N][K] row-major
__device__ float g_WkqvFT[(size_t)3072*D_];
__device__ float g_WstPT [(size_t)3072*D_];
__device__ float g_W2ssT [(size_t)H_*384*64];
__device__ float g_W2midT[(size_t)H_*384*64];
__device__ float g_W2seT [(size_t)H_*384*64];
__device__ float g_WoutT  [(size_t)D_*2048];
__device__ float g_WoutStT[(size_t)D_*2048];

struct BTab { const float* p[8]; };

// ---------------- tf32 helpers ----------------
__device__ __forceinline__ uint32_t f2tf(float f) {
    uint32_t u;
    asm("cvt.rna.tf32.f32 %0, %1;" : "=r"(u) : "f"(f));
    return u;
}
__device__ __forceinline__ uint4 f2tf4(float4 v) {
    uint4 u;
    u.x = f2tf(v.x); u.y = f2tf(v.y); u.z = f2tf(v.z); u.w = f2tf(v.w);
    return u;
}
__device__ __forceinline__ void mma8(float* c, const uint32_t* a, const uint32_t* b) {
    asm volatile(
        "mma.sync.aligned.m16n8k8.row.col.f32.tf32.tf32.f32 "
        "{%0,%1,%2,%3}, {%4,%5,%6,%7}, {%8,%9}, {%0,%1,%2,%3};\n"
        : "+f"(c[0]), "+f"(c[1]), "+f"(c[2]), "+f"(c[3])
        : "r"(a[0]), "r"(a[1]), "r"(a[2]), "r"(a[3]), "r"(b[0]), "r"(b[1]));
}

// ---------------- batched strided tf32 tensor-core GEMM ----------------
// TB-only: C = A @ B^T with B stored [N][K] row-major (pre-transposed weights).
// Smem stride BK+8 = 24 words: fragment pairbank = (12g + q) mod 16 ->
// conflict-free LDS.64 fragment reads; all smem stores are uint4 row stores.
template<int BM, int BN, int WM, int WN>
__global__ void __launch_bounds__(256) gemm_t(
    const float* __restrict__ A, const float* __restrict__ Bm0, float* __restrict__ C,
    int M, int N, int K, int lda, int ldb, int ldc,
    long long aSB, long long aSH, long long bSB, long long bSH,
    long long cSB, long long cSH, int Hd, int Zr,
    int sk, int Kc, long long pcs, int useTab, BTab tab)
{
    constexpr int BK = 16;
    constexpr int ST = BK + 8;
    constexpr int KS = BK / 8;
    constexpr int MF = WM / 16;
    constexpr int NF = WN / 8;
    constexpr int WCOL = BN / WN;
    constexpr int NA4 = BM * BK / 1024;
    constexpr int NB4 = BN * BK / 1024;
    constexpr int KQ = BK / 4;

    int z = blockIdx.z;
    int ks = 0, zz = z;
    if (sk > 1) { ks = z / Zr; zz = z - ks * Zr; }
    int b = zz / Hd, h = zz - b * Hd;
    const float* Bm = useTab ? tab.p[blockIdx.y] : Bm0;
    A  += (long long)b * aSB + (long long)h * aSH;
    Bm += (long long)b * bSB + (long long)h * bSH;
    C  += (long long)ks * pcs + (long long)b * cSB + (long long)h * cSH;

    int row0 = blockIdx.y * BM;
    int col0 = blockIdx.x * BN;

    int kBeg = ks * Kc;
    int nk = Kc / BK;

    __shared__ uint32_t As[2][BM][ST];
    __shared__ uint32_t Bs[2][BN][ST];

    int tid = threadIdx.x;
    int w   = tid >> 5;
    int lane = tid & 31;
    int g = lane >> 2, q = lane & 3;
    int warpM = w / WCOL, warpN = w % WCOL;
    int wr = warpM * WM;
    int wc = warpN * WN;

    float4 ag[NA4], bg[NB4];

    {
        int kb = kBeg;
        #pragma unroll
        for (int i = 0; i < NA4; i++) {
            int f = tid + i * 256; int r = f / KQ; int c4 = (f % KQ) << 2;
            float4 v = *(const float4*)(A + (long long)(row0 + r) * lda + kb + c4);
            *(uint4*)&As[0][r][c4] = f2tf4(v);
        }
        #pragma unroll
        for (int i = 0; i < NB4; i++) {
            int f = tid + i * 256; int r = f / KQ; int c4 = (f % KQ) << 2;
            float4 v = *(const float4*)(Bm + (long long)(col0 + r) * ldb + kb + c4);
            *(uint4*)&Bs[0][r][c4] = f2tf4(v);
        }
    }
    __syncthreads();

    float acc[MF][NF][4];
    #pragma unroll
    for (int i = 0; i < MF; i++)
        #pragma unroll
        for (int j = 0; j < NF; j++)
            #pragma unroll
            for (int e = 0; e < 4; e++) acc[i][j][e] = 0.f;

    int cur = 0;
    for (int t = 0; t < nk; t++) {
        if (t + 1 < nk) {
            int kb = kBeg + (t + 1) * BK;
            #pragma unroll
            for (int i = 0; i < NA4; i++) {
                int f = tid + i * 256; int r = f / KQ; int c4 = (f % KQ) << 2;
                ag[i] = *(const float4*)(A + (long long)(row0 + r) * lda + kb + c4);
            }
            #pragma unroll
            for (int i = 0; i < NB4; i++) {
                int f = tid + i * 256; int r = f / KQ; int c4 = (f % KQ) << 2;
                bg[i] = *(const float4*)(Bm + (long long)(col0 + r) * ldb + kb + c4);
            }
        }
        #pragma unroll
        for (int s = 0; s < KS; s++) {
            uint32_t af[MF][4], bf[NF][2];
            #pragma unroll
            for (int i = 0; i < MF; i++) {
                uint2 lo = *(const uint2*)&As[cur][wr + 16*i + g    ][8*s + 2*q];
                uint2 hi = *(const uint2*)&As[cur][wr + 16*i + g + 8][8*s + 2*q];
                af[i][0] = lo.x; af[i][1] = hi.x; af[i][2] = lo.y; af[i][3] = hi.y;
            }
            #pragma unroll
            for (int j = 0; j < NF; j++) {
                uint2 bb = *(const uint2*)&Bs[cur][wc + 8*j + g][8*s + 2*q];
                bf[j][0] = bb.x; bf[j][1] = bb.y;
            }
            #pragma unroll
            for (int i = 0; i < MF; i++)
                #pragma unroll
                for (int j = 0; j < NF; j++)
                    mma8(acc[i][j], af[i], bf[j]);
        }
        if (t + 1 < nk) {
            int nxt = cur ^ 1;
            #pragma unroll
            for (int i = 0; i < NA4; i++) {
                int f = tid + i * 256; int r = f / KQ; int c4 = (f % KQ) << 2;
                *(uint4*)&As[nxt][r][c4] = f2tf4(ag[i]);
            }
            #pragma unroll
            for (int i = 0; i < NB4; i++) {
                int f = tid + i * 256; int r = f / KQ; int c4 = (f % KQ) << 2;
                *(uint4*)&Bs[nxt][r][c4] = f2tf4(bg[i]);
            }
            __syncthreads();
            cur = nxt;
        }
    }

    #pragma unroll
    for (int i = 0; i < MF; i++) {
        #pragma unroll
        for (int j = 0; j < NF; j++) {
            int r0 = row0 + wr + 16*i + g;
            int c0 = col0 + wc + 8*j + 2*q;
            *(float2*)(C + (long long)r0 * ldc + c0) = make_float2(acc[i][j][0], acc[i][j][1]);
            *(float2*)(C + (long long)(r0 + 8) * ldc + c0) = make_float2(acc[i][j][2], acc[i][j][3]);
        }
    }
}

// ---------------- fused flash attention (tf32 mma, online softmax) ----------
// QW/KW/SW widened to +24 words -> conflict-free Q/K/S fragment reads.
template<int DH, bool GATHER>
__global__ void __launch_bounds__(256) flash_k(
    const float* __restrict__ b1, const float* __restrict__ b2, int ld,
    long long b1S, long long b2S, int qoff, int koff, int voff,
    float* __restrict__ out0, long long o0b, float* __restrict__ out1,
    int rbOff, float* __restrict__ pO, float* __restrict__ pm, float* __restrict__ pl,
    int nSplit, int pRows, int pSub)
{
    constexpr int BR = 128, BC = 64;
    constexpr int QW = DH + 24, KW = DH + 24, VW = BC + 4, SW = BC + 24;
    extern __shared__ uint32_t sm[];
    uint32_t* Qs = sm;
    uint32_t* Ks = Qs + BR * QW;
    uint32_t* Vs = Ks + BC * KW;
    uint32_t* Ss = Vs + DH * VW;

    int bh = blockIdx.y;
    int b = bh / H_, h = bh - b * H_;

    const float* stb  = b1 + (long long)bh * b1S;
    const float* segb = GATHER ? stb : (b2 + (long long)bh * b2S);

    int row0 = (GATHER ? ((int)blockIdx.x + rbOff) : (int)blockIdx.x) * BR;

    const float* Qb;
    if (GATHER) {
        Qb = stb + (long long)row0 * ld;
    } else {
        if (row0 < SL_)            Qb = stb;
        else if (row0 < SL_+SEG_)  Qb = segb + (long long)(row0 - SL_) * ld;
        else                       Qb = stb;
    }

    int tid = threadIdx.x, w = tid >> 5, lane = tid & 31;
    int g = lane >> 2, q = lane & 3;
    int wr = w * 16;

    constexpr int NQ4 = BR * DH / 1024;
    #pragma unroll
    for (int i = 0; i < NQ4; i++) {
        int f = tid + i * 256; int r = f / (DH/4); int c4 = (f % (DH/4)) << 2;
        float4 v = *(const float4*)(Qb + (long long)r * ld + qoff + c4);
        *(uint4*)&Qs[r*QW + c4] = f2tf4(v);
    }

    float Ofr[DH/8][4];
    #pragma unroll
    for (int j = 0; j < DH/8; j++)
        #pragma unroll
        for (int e = 0; e < 4; e++) Ofr[j][e] = 0.f;
    float m_a = -1e30f, m_b = -1e30f, l_a = 0.f, l_b = 0.f;
    int row_a = row0 + wr + g, row_b = row_a + 8;

    int nb = row0 / BC + 2;
    int cb0 = 0, cb1 = nb;
    if (pO) {
        int half = (nb + nSplit - 1) / nSplit;
        cb0 = blockIdx.z * half;
        cb1 = cb0 + half; if (cb1 > nb) cb1 = nb;
    }
    constexpr int NK4 = BC * DH / 1024;

    for (int cb = cb0; cb < cb1; cb++) {
        int c0 = cb * BC;
        const float* Kb;
        if (GATHER) {
            Kb = stb + (long long)c0 * ld;
        } else {
            if (c0 < SL_)            Kb = stb + (long long)c0 * ld;
            else if (c0 < SL_+SEG_)  Kb = segb + (long long)(c0 - SL_) * ld;
            else                     Kb = stb + (long long)(c0 - SL_ - SEG_) * ld;
        }
        __syncthreads();
        #pragma unroll
        for (int i = 0; i < NK4; i++) {
            int f = tid + i * 256; int r = f / (DH/4); int c4 = (f % (DH/4)) << 2;
            float4 v = *(const float4*)(Kb + (long long)r * ld + koff + c4);
            *(uint4*)&Ks[r*KW + c4] = f2tf4(v);
        }
        #pragma unroll
        for (int i = 0; i < NK4; i++) {
            int f = tid + i * 256; int c = f / (DH/4); int d4 = (f % (DH/4)) << 2;
            float4 v = *(const float4*)(Kb + (long long)c * ld + voff + d4);
            Vs[(d4+0)*VW + c] = f2tf(v.x);
            Vs[(d4+1)*VW + c] = f2tf(v.y);
            Vs[(d4+2)*VW + c] = f2tf(v.z);
            Vs[(d4+3)*VW + c] = f2tf(v.w);
        }
        __syncthreads();

        float sfr[BC/8][4];
        #pragma unroll
        for (int j = 0; j < BC/8; j++)
            #pragma unroll
            for (int e = 0; e < 4; e++) sfr[j][e] = 0.f;
        #pragma unroll
        for (int s = 0; s < DH/8; s++) {
            uint32_t af[4];
            uint2 lo = *(const uint2*)&Qs[(wr+g  )*QW + 8*s + 2*q];
            uint2 hi = *(const uint2*)&Qs[(wr+g+8)*QW + 8*s + 2*q];
            af[0] = lo.x; af[1] = hi.x; af[2] = lo.y; af[3] = hi.y;
            #pragma unroll
            for (int j = 0; j < BC/8; j++) {
                uint2 bb = *(const uint2*)&Ks[(8*j+g)*KW + 8*s + 2*q];
                uint32_t bf[2] = {bb.x, bb.y};
                mma8(sfr[j], af, bf);
            }
        }

        bool needm = (c0 + BC - 1 > row0 + wr);
        float mb_a = -1e30f, mb_b = -1e30f;
        #pragma unroll
        for (int j = 0; j < BC/8; j++) {
            int col = c0 + 8*j + 2*q;
            float s0 = sfr[j][0]*0.125f, s1 = sfr[j][1]*0.125f;
            float s2 = sfr[j][2]*0.125f, s3 = sfr[j][3]*0.125f;
            if (needm) {
                if (col     > row_a) s0 = -1e30f;
                if (col + 1 > row_a) s1 = -1e30f;
                if (col     > row_b) s2 = -1e30f;
                if (col + 1 > row_b) s3 = -1e30f;
            }
            sfr[j][0]=s0; sfr[j][1]=s1; sfr[j][2]=s2; sfr[j][3]=s3;
            mb_a = fmaxf(mb_a, fmaxf(s0, s1));
            mb_b = fmaxf(mb_b, fmaxf(s2, s3));
        }
        mb_a = fmaxf(mb_a, __shfl_xor_sync(0xffffffffu, mb_a, 1));
        mb_a = fmaxf(mb_a, __shfl_xor_sync(0xffffffffu, mb_a, 2));
        mb_b = fmaxf(mb_b, __shfl_xor_sync(0xffffffffu, mb_b, 1));
        mb_b = fmaxf(mb_b, __shfl_xor_sync(0xffffffffu, mb_b, 2));
        float mn_a = fmaxf(m_a, mb_a), mn_b = fmaxf(m_b, mb_b);
        float ra = __expf(m_a - mn_a), rb2 = __expf(m_b - mn_b);
        float sa = 0.f, sb = 0.f;
        #pragma unroll
        for (int j = 0; j < BC/8; j++) {
            float p0 = __expf(sfr[j][0] - mn_a), p1 = __expf(sfr[j][1] - mn_a);
            float p2 = __expf(sfr[j][2] - mn_b), p3 = __expf(sfr[j][3] - mn_b);
            sa += p0 + p1; sb += p2 + p3;
            int cc = 8*j + 2*q;
            *(uint2*)&Ss[(wr+g  )*SW + cc] = make_uint2(f2tf(p0), f2tf(p1));
            *(uint2*)&Ss[(wr+g+8)*SW + cc] = make_uint2(f2tf(p2), f2tf(p3));
        }
        sa += __shfl_xor_sync(0xffffffffu, sa, 1);
        sa += __shfl_xor_sync(0xffffffffu, sa, 2);
        sb += __shfl_xor_sync(0xffffffffu, sb, 1);
        sb += __shfl_xor_sync(0xffffffffu, sb, 2);
        l_a = l_a * ra + sa; l_b = l_b * rb2 + sb;
        m_a = mn_a; m_b = mn_b;
        #pragma unroll
        for (int j2 = 0; j2 < DH/8; j2++) {
            Ofr[j2][0] *= ra; Ofr[j2][1] *= ra;
            Ofr[j2][2] *= rb2; Ofr[j2][3] *= rb2;
        }
        __syncwarp();

        #pragma unroll
        for (int s = 0; s < BC/8; s++) {
            uint32_t af[4];
            uint2 lo = *(const uint2*)&Ss[(wr+g  )*SW + 8*s + 2*q];
            uint2 hi = *(const uint2*)&Ss[(wr+g+8)*SW + 8*s + 2*q];
            af[0] = lo.x; af[1] = hi.x; af[2] = lo.y; af[3] = hi.y;
            #pragma unroll
            for (int j2 = 0; j2 < DH/8; j2++) {
                uint2 bb = *(const uint2*)&Vs[(8*j2+g)*VW + 8*s + 2*q];
                uint32_t bf[2] = {bb.x, bb.y};
                mma8(Ofr[j2], af, bf);
            }
        }
    }

    if (pO) {
        #pragma unroll
        for (int rr = 0; rr < 2; rr++) {
            int pr = ((rr == 0) ? row_a : row_b) - pSub;
            long long base = ((long long)blockIdx.z * (B_*H_) + bh) * pRows + pr;
            float* dst = pO + base * DH;
            #pragma unroll
            for (int j2 = 0; j2 < DH/8; j2++) {
                int col = 8*j2 + 2*q;
                *(float2*)(dst + col) =
                    make_float2(Ofr[j2][rr ? 2 : 0], Ofr[j2][rr ? 3 : 1]);
            }
            if (q == 0) {
                pm[base] = (rr == 0) ? m_a : m_b;
                pl[base] = (rr == 0) ? l_a : l_b;
            }
        }
        return;
    }

    float ia = 1.f / l_a, ib = 1.f / l_b;
    if (!GATHER) {
        float* oa = out0 + (long long)bh * L_ * DH + (long long)row_a * DH;
        float* ob = out0 + (long long)bh * L_ * DH + (long long)row_b * DH;
        #pragma unroll
        for (int j2 = 0; j2 < DH/8; j2++) {
            int col = 8*j2 + 2*q;
            *(float2*)(oa + col) = make_float2(Ofr[j2][0]*ia, Ofr[j2][1]*ia);
            *(float2*)(ob + col) = make_float2(Ofr[j2][2]*ib, Ofr[j2][3]*ib);
        }
    } else {
        #pragma unroll
        for (int rr = 0; rr < 2; rr++) {
            int s_abs = (rr == 0) ? row_a : row_b;
            float inv = (rr == 0) ? ia : ib;
            float* dst;
            if (s_abs < SL_ + SEG_) {
                int s = s_abs - SL_;
                dst = out0 + (long long)b * o0b
                    + (long long)((h << 5) + (s >> 4)) * 2048 + ((s & 15) << 7);
            } else {
                int s = s_abs - (SL_ + SEG_);
                dst = out1 + ((long long)b * SL_ + (h << 3) + (s >> 4)) * 2048
                    + ((s & 15) << 7);
            }
            #pragma unroll
            for (int j2 = 0; j2 < DH/8; j2++) {
                int col = 8*j2 + 2*q;
                float v0 = Ofr[j2][rr ? 2 : 0] * inv;
                float v1 = Ofr[j2][rr ? 3 : 1] * inv;
                *(float2*)(dst + col) = make_float2(v0, v1);
            }
        }
    }
}

// merge 4 split-KV partials (DH=128) -> gathered a2e layout
__global__ void mergeKV(float* __restrict__ a2e, const float* __restrict__ pO,
                        const float* __restrict__ pm, const float* __restrict__ pl)
{
    int idx = blockIdx.x * blockDim.x + threadIdx.x;
    const int tot = B_ * H_ * SL_ * 128;
    if (idx >= tot) return;
    int col = idx & 127;
    int r   = (idx >> 7) & 127;
    int bh  = idx >> 14;
    int b = bh / H_, h = bh - b * H_;
    const int P = B_ * H_ * SL_;
    float M = -1e30f;
    #pragma unroll
    for (int s = 0; s < 4; s++) M = fmaxf(M, pm[s*P + bh*SL_ + r]);
    float num = 0.f, den = 0.f;
    #pragma unroll
    for (int s = 0; s < 4; s++) {
        float wgt = __expf(pm[s*P + bh*SL_ + r] - M);
        den += wgt * pl[s*P + bh*SL_ + r];
        num += wgt * pO[((long long)s*P + (long long)bh*SL_ + r) * 128 + col];
    }
    a2e[((long long)(b * SL_ + (h << 3) + (r >> 4))) * 2048 + ((r & 15) << 7) + col]
        = num / den;
}

// merge 2 split-KV partials (DH=64) -> dense att1
__global__ void merge1(float* __restrict__ att1, const float* __restrict__ pO,
                       const float* __restrict__ pm, const float* __restrict__ pl)
{
    int idx = blockIdx.x * blockDim.x + threadIdx.x;
    const int tot = B_ * H_ * L_ * 64;
    if (idx >= tot) return;
    int col = idx & 63;
    int r   = (idx >> 6) % L_;
    int bh  = idx / (L_ * 64);
    const int P = B_ * H_ * L_;
    float m0 = pm[bh*L_ + r], m1 = pm[P + bh*L_ + r];
    float M = fmaxf(m0, m1);
    float w0 = __expf(m0 - M), w1 = __expf(m1 - M);
    float O0 = pO[((long long)bh*L_ + r) * 64 + col];
    float O1 = pO[((long long)P + (long long)bh*L_ + r) * 64 + col];
    att1[((long long)bh*L_ + r) * 64 + col]
        = (w0*O0 + w1*O1) / (w0*pl[bh*L_ + r] + w1*pl[P + bh*L_ + r]);
}

// generic split-K reduce
__global__ void reduceK(float* __restrict__ C, const float* __restrict__ part,
    int sk, long long chunk, int M, int N, int ldc,
    long long cSB, long long cSH, int Hd)
{
    long long idx = (long long)blockIdx.x * blockDim.x + threadIdx.x;
    if (idx >= chunk) return;
    int n = (int)(idx % N);
    long long t = idx / N;
    int m = (int)(t % M);
    int zz = (int)(t / M);
    int b = zz / Hd, h = zz - b * Hd;
    float s = 0.f;
    for (int i = 0; i < sk; i++) s += part[(long long)i * chunk + idx];
    C[(long long)b * cSB + (long long)h * cSH + (long long)m * ldc + n] = s;
}

// transposed packs: dst is [N][K] row-major
// full/state proj: dst[(h*192 + o*64 + c)][d] = W_o[h][d][c]
__global__ void packHT(float* __restrict__ dst, const float* __restrict__ s0,
                       const float* __restrict__ s1, const float* __restrict__ s2)
{
    int idx = blockIdx.x * blockDim.x + threadIdx.x;
    const int tot = 3072 * D_;
    if (idx >= tot) return;
    int d = idx & 1023;
    int n = idx >> 10;
    int c = n & 63;
    int o = (n >> 6) % 3;
    int h = n / 192;
    const float* s = (o == 0) ? s0 : ((o == 1) ? s1 : s2);
    dst[idx] = s[((size_t)h * D_ + d) * 64 + c];
}

// lvl2: dst[h][(o*128 + c)][d] = W2_o[h][d][c]  (d < 64, c < 128)
__global__ void packW2T(float* __restrict__ dst, const float* __restrict__ s0,
                        const float* __restrict__ s1, const float* __restrict__ s2)
{
    int idx = blockIdx.x * blockDim.x + threadIdx.x;
    const int tot = H_ * 384 * 64;
    if (idx >= tot) return;
    int d = idx & 63;
    int n = (idx >> 6) % 384;
    int h = idx / (384 * 64);
    int c = n & 127;
    int o = n >> 7;
    const float* s = (o == 0) ? s0 : ((o == 1) ? s1 : s2);
    dst[idx] = s[((size_t)h * 64 + d) * 128 + c];
}

// out/state: dst[n][k] = W[k][n]  (W is [2048][1024])
__global__ void packOT(float* __restrict__ dst, const float* __restrict__ src)
{
    int idx = blockIdx.x * blockDim.x + threadIdx.x;
    const int tot = D_ * 2048;
    if (idx >= tot) return;
    int k = idx & 2047;
    int n = idx >> 11;
    dst[idx] = src[(size_t)k * D_ + n];
}

__global__ void bcast_state(float* __restrict__ st, const float* __restrict__ state)
{
    int idx = blockIdx.x * blockDim.x + threadIdx.x;
    const int total = B_ * SL_ * D_;
    if (idx >= total) return;
    st[idx] = state[idx % (SL_ * D_)];
}

__global__ void copy_f(float* __restrict__ dst, const float* __restrict__ src, int n)
{
    int idx = blockIdx.x * blockDim.x + threadIdx.x;
    if (idx < n) dst[idx] = src[idx];
}

// ---------------- host ----------------
static float* s_part = nullptr;

static void G(const float* A, const float* Bm, float* C,
              int M, int N, int K, int lda, int ldb, int ldc,
              long long aSB, long long aSH, long long bSB, long long bSH,
              long long cSB, long long cSH, int Hd, int Z, int sk = 1,
              int useTab = 0, BTab tab = {}, cudaStream_t st = 0)
{
    int Kc = K / sk;
    long long pcs = 0;
    float* Cout = C;
    long long csb = cSB, csh = cSH;
    int ldc2 = ldc;
    if (sk > 1) {
        pcs = (long long)Z * M * N;
        Cout = s_part; ldc2 = N;
        csh = (long long)M * N;
        csb = (long long)Hd * M * N;
    }
    dim3 blk(256);
    if (N % 128 == 0) {
        dim3 grid(N / 128, (M + 127) / 128, Z * sk);
        gemm_t<128,128,64,32><<<grid, blk, 0, st>>>(A, Bm, Cout, M, N, K, lda, ldb, ldc2,
            aSB, aSH, bSB, bSH, csb, csh, Hd, Z, sk, Kc, pcs, useTab, tab);
    } else {
        dim3 grid(N / 64, (M + 127) / 128, Z * sk);
        gemm_t<128,64,32,32><<<grid, blk, 0, st>>>(A, Bm, Cout, M, N, K, lda, ldb, ldc2,
            aSB, aSH, bSB, bSH, csb, csh, Hd, Z, sk, Kc, pcs, useTab, tab);
    }
    if (sk > 1) {
        long long chunk = (long long)Z * M * N;
        reduceK<<<(unsigned)((chunk + 255) / 256), 256, 0, st>>>(C, s_part, sk, chunk,
            M, N, ldc, cSB, cSH, Hd);
    }
}

extern "C" void kernel_launch(void* const* d_in, const int* in_sizes, int n_in,
                              void* d_out, int out_size)
{
    const float* x       = (const float*)d_in[0];
    const float* state   = (const float*)d_in[1];
    const float* Wk      = (const float*)d_in[2];
    const float* Wq      = (const float*)d_in[3];
    const float* Wv      = (const float*)d_in[4];
    const float* W2k     = (const float*)d_in[5];
    const float* Wout    = (const float*)d_in[6];
    const float* Wk_st   = (const float*)d_in[7];
    const float* Wq_st   = (const float*)d_in[8];
    const float* Wv_st   = (const float*)d_in[9];
    const float* W2k_ss  = (const float*)d_in[10];
    const float* W2q_ss  = (const float*)d_in[11];
    const float* W2v_ss  = (const float*)d_in[12];
    const float* W2k_se  = (const float*)d_in[13];
    const float* W2q_se  = (const float*)d_in[14];
    const float* W2v_se  = (const float*)d_in[15];
    const float* Wout_st = (const float*)d_in[16];
    float* out = (float*)d_out;

    float *kqvf,*stp,*att1,*kqv2,*a2r,*a2e,*stA,*stB,*pO,*pm,*pl;
    float *WkqvFT,*WstPT,*W2ssT,*W2midT,*W2seT,*WoutT,*WoutStT;
    cudaGetSymbolAddress((void**)&kqvf, g_kqvf);
    cudaGetSymbolAddress((void**)&stp,  g_stp);
    cudaGetSymbolAddress((void**)&att1, g_att1);
    cudaGetSymbolAddress((void**)&kqv2, g_kqv2);
    cudaGetSymbolAddress((void**)&a2r,  g_a2r);
    cudaGetSymbolAddress((void**)&a2e,  g_a2e);
    cudaGetSymbolAddress((void**)&stA,  g_stA);
    cudaGetSymbolAddress((void**)&stB,  g_stB);
    cudaGetSymbolAddress((void**)&s_part, g_part);
    cudaGetSymbolAddress((void**)&pO, g_pO);
    cudaGetSymbolAddress((void**)&pm, g_pm);
    cudaGetSymbolAddress((void**)&pl, g_pl);
    cudaGetSymbolAddress((void**)&WkqvFT, g_WkqvFT);
    cudaGetSymbolAddress((void**)&WstPT,  g_WstPT);
    cudaGetSymbolAddress((void**)&W2ssT,  g_W2ssT);
    cudaGetSymbolAddress((void**)&W2midT, g_W2midT);
    cudaGetSymbolAddress((void**)&W2seT,  g_W2seT);
    cudaGetSymbolAddress((void**)&WoutT,  g_WoutT);
    cudaGetSymbolAddress((void**)&WoutStT,g_WoutStT);

    const int SM64  = (128*(64+24) + 64*(64+24) + 64*(64+4) + 128*(64+24)) * 4;
    const int SM128 = (128*(128+24) + 64*(128+24) + 128*(64+4) + 128*(64+24)) * 4;
    cudaFuncSetAttribute(flash_k<64,false>,  cudaFuncAttributeMaxDynamicSharedMemorySize, SM64);
    cudaFuncSetAttribute(flash_k<128,true>,  cudaFuncAttributeMaxDynamicSharedMemorySize, SM128);

    static cudaStream_t s2 = nullptr;
    static cudaEvent_t evF[NSEG_];
    static cudaEvent_t evJ = nullptr;
    if (!s2) {
        cudaStreamCreateWithFlags(&s2, cudaStreamNonBlocking);
        for (int i = 0; i < NSEG_; i++)
            cudaEventCreateWithFlags(&evF[i], cudaEventDisableTiming);
        cudaEventCreateWithFlags(&evJ, cudaEventDisableTiming);
    }

    BTab tab2; // level-2 projections: rows 0-127 ss, 128-639 mid, 640-767 se
    tab2.p[0] = W2ssT; tab2.p[1] = W2midT; tab2.p[2] = W2midT;
    tab2.p[3] = W2midT; tab2.p[4] = W2midT; tab2.p[5] = W2seT;
    tab2.p[6] = W2midT; tab2.p[7] = W2midT;

    bool tailFits = (out_size >= B_*S_*D_ + B_*SL_*D_);
    const long long KQV2SEG = (long long)B_*H_*L_*384;

    // launches 0-4; index 5 = flash1 of seg 0 (ncu -s 5 -c 1 target)
    bcast_state<<<(B_*SL_*D_ + 255)/256, 256>>>(stA, state);
    packHT<<<(3072*D_ + 255)/256, 256>>>(WkqvFT, Wk, Wq, Wv);
    packHT<<<(3072*D_ + 255)/256, 256>>>(WstPT, Wk_st, Wq_st, Wv_st);
    G(x, WkqvFT, kqvf, S_, 192, D_, D_, D_, 192,
      (long long)S_*D_, 0, 0, (long long)192*D_,
      (long long)H_*S_*192, (long long)S_*192, H_, B_*H_);

    for (int seg = 0; seg < NSEG_; seg++) {
        float* stc = (seg & 1) ? stB : stA;
        float* stn = (seg & 1) ? stA : stB;
        if (seg == NSEG_-1 && tailFits) stn = out + (size_t)B_*S_*D_;
        float* kqv2s = kqv2 + (long long)seg * KQV2SEG;

        // state K|Q|V projection -> stp
        G(stc, WstPT, stp, SL_, 192, D_, D_, D_, 192,
          (long long)SL_*D_, 0, 0, (long long)192*D_,
          (long long)H_*SL_*192, (long long)SL_*192, H_, B_*H_);

        // attention 1: split-KV z=2 partial
        flash_k<64,false><<<dim3(L_/128, B_*H_, 2), 256, SM64>>>(
            stp, kqvf + (long long)seg*SEG_*192, 192,
            (long long)SL_*192, (long long)S_*192, 64, 0, 128,
            nullptr, 0, nullptr, 0, pO, pm, pl, 2, L_, 0);

        if (seg == 0) {  // one-time transposed packs (ordered before first use)
            packW2T<<<(H_*384*64 + 255)/256, 256>>>(W2ssT,  W2k_ss, W2q_ss, W2v_ss);
            packW2T<<<(H_*384*64 + 255)/256, 256>>>(W2midT, W2k,    W2k,    W2k);
            packW2T<<<(H_*384*64 + 255)/256, 256>>>(W2seT,  W2k_se, W2q_se, W2v_se);
            packOT<<<(D_*2048 + 255)/256, 256>>>(WoutT,   Wout);
            packOT<<<(D_*2048 + 255)/256, 256>>>(WoutStT, Wout_st);
        }

        merge1<<<(B_*H_*L_*64 + 255)/256, 256>>>(att1, pO, pm, pl);

        // level-2 projections into per-seg kqv2 buffer
        G(att1, nullptr, kqv2s, L_, 384, DV_, DV_, 64, 384,
          (long long)H_*L_*DV_, (long long)L_*DV_, 0, (long long)384*64,
          (long long)H_*L_*384, (long long)L_*384, H_, B_*H_, 1, 1, tab2);

        // fork: a2r row-blocks + out-GEMM on side stream
        cudaEventRecord(evF[seg], 0);
        cudaStreamWaitEvent(s2, evF[seg], 0);
        flash_k<128,true><<<dim3(4, B_*H_), 256, SM128, s2>>>(
            kqv2s, nullptr, 384, (long long)L_*384, 0, 128, 0, 256,
            a2r + (long long)seg*SEG_*2048, (long long)NSEG_*SEG_*2048, a2e,
            1, nullptr, nullptr, nullptr, 0, 0, 0);
        G(a2r + (long long)seg*SEG_*2048, WoutT, out + (size_t)seg*SEG_*D_,
          SEG_, D_, 2048, 2048, 2048, D_,
          (long long)NSEG_*SEG_*2048, 0, 0, 0, (long long)S_*D_, 0, 1, B_,
          1, 0, BTab{}, s2);

        // critical path: split-KV z=4 flash for a2e rows, then merge
        flash_k<128,true><<<dim3(1, B_*H_, 4), 256, SM128>>>(
            kqv2s, nullptr, 384, (long long)L_*384, 0, 128, 0, 256,
            a2r + (long long)seg*SEG_*2048, (long long)NSEG_*SEG_*2048, a2e,
            5, pO, pm, pl, 4, SL_, 640);
        mergeKV<<<(B_*H_*SL_*128 + 255)/256, 256>>>(a2e, pO, pm, pl);

        // next state (split-K x8)
        G(a2e, WoutStT, stn, SL_, D_, 2048, 2048, 2048, D_,
          (long long)SL_*2048, 0, 0, 0, (long long)SL_*D_, 0, 1, B_, 8);
    }

    // join side stream back into origin stream
    cudaEventRecord(evJ, s2);
    cudaStreamWaitEvent(0, evJ, 0);

    if (!tailFits) {
        int st_elems = B_ * SL_ * D_;
        if (out_size >= B_*S_*D_ + st_elems) {
            copy_f<<<(st_elems + 255)/256, 256>>>(out + (size_t)B_*S_*D_, stA, st_elems);
        }
    }
}

// round 17
// speedup vs baseline: 1.6331x; 1.0253x over previous
#include <cuda_runtime.h>
#include <cstdint>

#define B_ 2
#define S_ 2048
#define D_ 1024
#define H_ 16
#define DK_ 64
#define DV_ 64
#define SEG_ 512
#define SL_ 128
#define L_ 768
#define NSEG_ 4

// ---------------- scratch (device globals: allocation-free) ----------------
__device__ float g_kqvf[(size_t)B_*H_*S_*192];
__device__ float g_stp [(size_t)B_*H_*SL_*192];
__device__ float g_att1[(size_t)B_*H_*L_*64];
__device__ float g_kqv2[(size_t)NSEG_*B_*H_*L_*384];
__device__ float g_a2r [(size_t)B_*NSEG_*SEG_*2048];
__device__ float g_a2e [(size_t)B_*SL_*2048];
__device__ float g_stA[(size_t)B_*SL_*D_];
__device__ float g_stB[(size_t)B_*SL_*D_];
__device__ float g_part[(size_t)4*1024*1024];
__device__ float g_pO [(size_t)4*1024*1024];
__device__ float g_pm [(size_t)64*1024];
__device__ float g_pl [(size_t)64*1024];
// transposed weights: [N][K] row-major
__device__ float g_WkqvFT[(size_t)3072*D_];
__device__ float g_WstPT [(size_t)3072*D_];
__device__ float g_W2ssT [(size_t)H_*384*64];
__device__ float g_W2midT[(size_t)H_*384*64];
__device__ float g_W2seT [(size_t)H_*384*64];
__device__ float g_WoutT  [(size_t)D_*2048];
__device__ float g_WoutStT[(size_t)D_*2048];

struct BTab { const float* p[8]; };

// ---------------- tf32 helpers ----------------
__device__ __forceinline__ uint32_t f2tf(float f) {
    uint32_t u;
    asm("cvt.rna.tf32.f32 %0, %1;" : "=r"(u) : "f"(f));
    return u;
}
__device__ __forceinline__ uint4 f2tf4(float4 v) {
    uint4 u;
    u.x = f2tf(v.x); u.y = f2tf(v.y); u.z = f2tf(v.z); u.w = f2tf(v.w);
    return u;
}
__device__ __forceinline__ void mma8(float* c, const uint32_t* a, const uint32_t* b) {
    asm volatile(
        "mma.sync.aligned.m16n8k8.row.col.f32.tf32.tf32.f32 "
        "{%0,%1,%2,%3}, {%4,%5,%6,%7}, {%8,%9}, {%0,%1,%2,%3};\n"
        : "+f"(c[0]), "+f"(c[1]), "+f"(c[2]), "+f"(c[3])
        : "r"(a[0]), "r"(a[1]), "r"(a[2]), "r"(a[3]), "r"(b[0]), "r"(b[1]));
}

// ---------------- batched strided tf32 tensor-core GEMM ----------------
// TB-only: C = A @ B^T with B stored [N][K] row-major (pre-transposed weights).
// Smem stride BK+8 = 24 words -> conflict-free LDS.64 fragment reads.
// Templated on thread count NT: skinny-N path uses 128 threads with fat
// WM=64 warp tiles (12 LDS.64 : 16 MMA, same ratio as the BN=128 path).
template<int BM, int BN, int WM, int WN, int NT>
__global__ void __launch_bounds__(NT) gemm_t(
    const float* __restrict__ A, const float* __restrict__ Bm0, float* __restrict__ C,
    int M, int N, int K, int lda, int ldb, int ldc,
    long long aSB, long long aSH, long long bSB, long long bSH,
    long long cSB, long long cSH, int Hd, int Zr,
    int sk, int Kc, long long pcs, int useTab, BTab tab)
{
    constexpr int BK = 16;
    constexpr int ST = BK + 8;
    constexpr int KS = BK / 8;
    constexpr int MF = WM / 16;
    constexpr int NF = WN / 8;
    constexpr int WCOL = BN / WN;
    constexpr int NA4 = BM * BK / (NT * 4);
    constexpr int NB4 = BN * BK / (NT * 4);
    constexpr int KQ = BK / 4;

    int z = blockIdx.z;
    int ks = 0, zz = z;
    if (sk > 1) { ks = z / Zr; zz = z - ks * Zr; }
    int b = zz / Hd, h = zz - b * Hd;
    const float* Bm = useTab ? tab.p[blockIdx.y] : Bm0;
    A  += (long long)b * aSB + (long long)h * aSH;
    Bm += (long long)b * bSB + (long long)h * bSH;
    C  += (long long)ks * pcs + (long long)b * cSB + (long long)h * cSH;

    int row0 = blockIdx.y * BM;
    int col0 = blockIdx.x * BN;

    int kBeg = ks * Kc;
    int nk = Kc / BK;

    __shared__ uint32_t As[2][BM][ST];
    __shared__ uint32_t Bs[2][BN][ST];

    int tid = threadIdx.x;
    int w   = tid >> 5;
    int lane = tid & 31;
    int g = lane >> 2, q = lane & 3;
    int warpM = w / WCOL, warpN = w % WCOL;
    int wr = warpM * WM;
    int wc = warpN * WN;

    float4 ag[NA4], bg[NB4];

    {
        int kb = kBeg;
        #pragma unroll
        for (int i = 0; i < NA4; i++) {
            int f = tid + i * NT; int r = f / KQ; int c4 = (f % KQ) << 2;
            float4 v = *(const float4*)(A + (long long)(row0 + r) * lda + kb + c4);
            *(uint4*)&As[0][r][c4] = f2tf4(v);
        }
        #pragma unroll
        for (int i = 0; i < NB4; i++) {
            int f = tid + i * NT; int r = f / KQ; int c4 = (f % KQ) << 2;
            float4 v = *(const float4*)(Bm + (long long)(col0 + r) * ldb + kb + c4);
            *(uint4*)&Bs[0][r][c4] = f2tf4(v);
        }
    }
    __syncthreads();

    float acc[MF][NF][4];
    #pragma unroll
    for (int i = 0; i < MF; i++)
        #pragma unroll
        for (int j = 0; j < NF; j++)
            #pragma unroll
            for (int e = 0; e < 4; e++) acc[i][j][e] = 0.f;

    int cur = 0;
    for (int t = 0; t < nk; t++) {
        if (t + 1 < nk) {
            int kb = kBeg + (t + 1) * BK;
            #pragma unroll
            for (int i = 0; i < NA4; i++) {
                int f = tid + i * NT; int r = f / KQ; int c4 = (f % KQ) << 2;
                ag[i] = *(const float4*)(A + (long long)(row0 + r) * lda + kb + c4);
            }
            #pragma unroll
            for (int i = 0; i < NB4; i++) {
                int f = tid + i * NT; int r = f / KQ; int c4 = (f % KQ) << 2;
                bg[i] = *(const float4*)(Bm + (long long)(col0 + r) * ldb + kb + c4);
            }
        }
        #pragma unroll
        for (int s = 0; s < KS; s++) {
            uint32_t af[MF][4], bf[NF][2];
            #pragma unroll
            for (int i = 0; i < MF; i++) {
                uint2 lo = *(const uint2*)&As[cur][wr + 16*i + g    ][8*s + 2*q];
                uint2 hi = *(const uint2*)&As[cur][wr + 16*i + g + 8][8*s + 2*q];
                af[i][0] = lo.x; af[i][1] = hi.x; af[i][2] = lo.y; af[i][3] = hi.y;
            }
            #pragma unroll
            for (int j = 0; j < NF; j++) {
                uint2 bb = *(const uint2*)&Bs[cur][wc + 8*j + g][8*s + 2*q];
                bf[j][0] = bb.x; bf[j][1] = bb.y;
            }
            #pragma unroll
            for (int i = 0; i < MF; i++)
                #pragma unroll
                for (int j = 0; j < NF; j++)
                    mma8(acc[i][j], af[i], bf[j]);
        }
        if (t + 1 < nk) {
            int nxt = cur ^ 1;
            #pragma unroll
            for (int i = 0; i < NA4; i++) {
                int f = tid + i * NT; int r = f / KQ; int c4 = (f % KQ) << 2;
                *(uint4*)&As[nxt][r][c4] = f2tf4(ag[i]);
            }
            #pragma unroll
            for (int i = 0; i < NB4; i++) {
                int f = tid + i * NT; int r = f / KQ; int c4 = (f % KQ) << 2;
                *(uint4*)&Bs[nxt][r][c4] = f2tf4(bg[i]);
            }
            __syncthreads();
            cur = nxt;
        }
    }

    #pragma unroll
    for (int i = 0; i < MF; i++) {
        #pragma unroll
        for (int j = 0; j < NF; j++) {
            int r0 = row0 + wr + 16*i + g;
            int c0 = col0 + wc + 8*j + 2*q;
            *(float2*)(C + (long long)r0 * ldc + c0) = make_float2(acc[i][j][0], acc[i][j][1]);
            *(float2*)(C + (long long)(r0 + 8) * ldc + c0) = make_float2(acc[i][j][2], acc[i][j][3]);
        }
    }
}

// ---------------- fused flash attention (tf32 mma, online softmax) ----------
template<int DH, bool GATHER>
__global__ void __launch_bounds__(256) flash_k(
    const float* __restrict__ b1, const float* __restrict__ b2, int ld,
    long long b1S, long long b2S, int qoff, int koff, int voff,
    float* __restrict__ out0, long long o0b, float* __restrict__ out1,
    int rbOff, float* __restrict__ pO, float* __restrict__ pm, float* __restrict__ pl,
    int nSplit, int pRows, int pSub)
{
    constexpr int BR = 128, BC = 64;
    constexpr int QW = DH + 24, KW = DH + 24, VW = BC + 4, SW = BC + 24;
    extern __shared__ uint32_t sm[];
    uint32_t* Qs = sm;
    uint32_t* Ks = Qs + BR * QW;
    uint32_t* Vs = Ks + BC * KW;
    uint32_t* Ss = Vs + DH * VW;

    int bh = blockIdx.y;
    int b = bh / H_, h = bh - b * H_;

    const float* stb  = b1 + (long long)bh * b1S;
    const float* segb = GATHER ? stb : (b2 + (long long)bh * b2S);

    int row0 = (GATHER ? ((int)blockIdx.x + rbOff) : (int)blockIdx.x) * BR;

    const float* Qb;
    if (GATHER) {
        Qb = stb + (long long)row0 * ld;
    } else {
        if (row0 < SL_)            Qb = stb;
        else if (row0 < SL_+SEG_)  Qb = segb + (long long)(row0 - SL_) * ld;
        else                       Qb = stb;
    }

    int tid = threadIdx.x, w = tid >> 5, lane = tid & 31;
    int g = lane >> 2, q = lane & 3;
    int wr = w * 16;

    constexpr int NQ4 = BR * DH / 1024;
    #pragma unroll
    for (int i = 0; i < NQ4; i++) {
        int f = tid + i * 256; int r = f / (DH/4); int c4 = (f % (DH/4)) << 2;
        float4 v = *(const float4*)(Qb + (long long)r * ld + qoff + c4);
        *(uint4*)&Qs[r*QW + c4] = f2tf4(v);
    }

    float Ofr[DH/8][4];
    #pragma unroll
    for (int j = 0; j < DH/8; j++)
        #pragma unroll
        for (int e = 0; e < 4; e++) Ofr[j][e] = 0.f;
    float m_a = -1e30f, m_b = -1e30f, l_a = 0.f, l_b = 0.f;
    int row_a = row0 + wr + g, row_b = row_a + 8;

    int nb = row0 / BC + 2;
    int cb0 = 0, cb1 = nb;
    if (pO) {
        int half = (nb + nSplit - 1) / nSplit;
        cb0 = blockIdx.z * half;
        cb1 = cb0 + half; if (cb1 > nb) cb1 = nb;
    }
    constexpr int NK4 = BC * DH / 1024;

    for (int cb = cb0; cb < cb1; cb++) {
        int c0 = cb * BC;
        const float* Kb;
        if (GATHER) {
            Kb = stb + (long long)c0 * ld;
        } else {
            if (c0 < SL_)            Kb = stb + (long long)c0 * ld;
            else if (c0 < SL_+SEG_)  Kb = segb + (long long)(c0 - SL_) * ld;
            else                     Kb = stb + (long long)(c0 - SL_ - SEG_) * ld;
        }
        __syncthreads();
        #pragma unroll
        for (int i = 0; i < NK4; i++) {
            int f = tid + i * 256; int r = f / (DH/4); int c4 = (f % (DH/4)) << 2;
            float4 v = *(const float4*)(Kb + (long long)r * ld + koff + c4);
            *(uint4*)&Ks[r*KW + c4] = f2tf4(v);
        }
        #pragma unroll
        for (int i = 0; i < NK4; i++) {
            int f = tid + i * 256; int c = f / (DH/4); int d4 = (f % (DH/4)) << 2;
            float4 v = *(const float4*)(Kb + (long long)c * ld + voff + d4);
            Vs[(d4+0)*VW + c] = f2tf(v.x);
            Vs[(d4+1)*VW + c] = f2tf(v.y);
            Vs[(d4+2)*VW + c] = f2tf(v.z);
            Vs[(d4+3)*VW + c] = f2tf(v.w);
        }
        __syncthreads();

        float sfr[BC/8][4];
        #pragma unroll
        for (int j = 0; j < BC/8; j++)
            #pragma unroll
            for (int e = 0; e < 4; e++) sfr[j][e] = 0.f;
        #pragma unroll
        for (int s = 0; s < DH/8; s++) {
            uint32_t af[4];
            uint2 lo = *(const uint2*)&Qs[(wr+g  )*QW + 8*s + 2*q];
            uint2 hi = *(const uint2*)&Qs[(wr+g+8)*QW + 8*s + 2*q];
            af[0] = lo.x; af[1] = hi.x; af[2] = lo.y; af[3] = hi.y;
            #pragma unroll
            for (int j = 0; j < BC/8; j++) {
                uint2 bb = *(const uint2*)&Ks[(8*j+g)*KW + 8*s + 2*q];
                uint32_t bf[2] = {bb.x, bb.y};
                mma8(sfr[j], af, bf);
            }
        }

        bool needm = (c0 + BC - 1 > row0 + wr);
        float mb_a = -1e30f, mb_b = -1e30f;
        #pragma unroll
        for (int j = 0; j < BC/8; j++) {
            int col = c0 + 8*j + 2*q;
            float s0 = sfr[j][0]*0.125f, s1 = sfr[j][1]*0.125f;
            float s2 = sfr[j][2]*0.125f, s3 = sfr[j][3]*0.125f;
            if (needm) {
                if (col     > row_a) s0 = -1e30f;
                if (col + 1 > row_a) s1 = -1e30f;
                if (col     > row_b) s2 = -1e30f;
                if (col + 1 > row_b) s3 = -1e30f;
            }
            sfr[j][0]=s0; sfr[j][1]=s1; sfr[j][2]=s2; sfr[j][3]=s3;
            mb_a = fmaxf(mb_a, fmaxf(s0, s1));
            mb_b = fmaxf(mb_b, fmaxf(s2, s3));
        }
        mb_a = fmaxf(mb_a, __shfl_xor_sync(0xffffffffu, mb_a, 1));
        mb_a = fmaxf(mb_a, __shfl_xor_sync(0xffffffffu, mb_a, 2));
        mb_b = fmaxf(mb_b, __shfl_xor_sync(0xffffffffu, mb_b, 1));
        mb_b = fmaxf(mb_b, __shfl_xor_sync(0xffffffffu, mb_b, 2));
        float mn_a = fmaxf(m_a, mb_a), mn_b = fmaxf(m_b, mb_b);
        float ra = __expf(m_a - mn_a), rb2 = __expf(m_b - mn_b);
        float sa = 0.f, sb = 0.f;
        #pragma unroll
        for (int j = 0; j < BC/8; j++) {
            float p0 = __expf(sfr[j][0] - mn_a), p1 = __expf(sfr[j][1] - mn_a);
            float p2 = __expf(sfr[j][2] - mn_b), p3 = __expf(sfr[j][3] - mn_b);
            sa += p0 + p1; sb += p2 + p3;
            int cc = 8*j + 2*q;
            *(uint2*)&Ss[(wr+g  )*SW + cc] = make_uint2(f2tf(p0), f2tf(p1));
            *(uint2*)&Ss[(wr+g+8)*SW + cc] = make_uint2(f2tf(p2), f2tf(p3));
        }
        sa += __shfl_xor_sync(0xffffffffu, sa, 1);
        sa += __shfl_xor_sync(0xffffffffu, sa, 2);
        sb += __shfl_xor_sync(0xffffffffu, sb, 1);
        sb += __shfl_xor_sync(0xffffffffu, sb, 2);
        l_a = l_a * ra + sa; l_b = l_b * rb2 + sb;
        m_a = mn_a; m_b = mn_b;
        #pragma unroll
        for (int j2 = 0; j2 < DH/8; j2++) {
            Ofr[j2][0] *= ra; Ofr[j2][1] *= ra;
            Ofr[j2][2] *= rb2; Ofr[j2][3] *= rb2;
        }
        __syncwarp();

        #pragma unroll
        for (int s = 0; s < BC/8; s++) {
            uint32_t af[4];
            uint2 lo = *(const uint2*)&Ss[(wr+g  )*SW + 8*s + 2*q];
            uint2 hi = *(const uint2*)&Ss[(wr+g+8)*SW + 8*s + 2*q];
            af[0] = lo.x; af[1] = hi.x; af[2] = lo.y; af[3] = hi.y;
            #pragma unroll
            for (int j2 = 0; j2 < DH/8; j2++) {
                uint2 bb = *(const uint2*)&Vs[(8*j2+g)*VW + 8*s + 2*q];
                uint32_t bf[2] = {bb.x, bb.y};
                mma8(Ofr[j2], af, bf);
            }
        }
    }

    if (pO) {
        #pragma unroll
        for (int rr = 0; rr < 2; rr++) {
            int pr = ((rr == 0) ? row_a : row_b) - pSub;
            long long base = ((long long)blockIdx.z * (B_*H_) + bh) * pRows + pr;
            float* dst = pO + base * DH;
            #pragma unroll
            for (int j2 = 0; j2 < DH/8; j2++) {
                int col = 8*j2 + 2*q;
                *(float2*)(dst + col) =
                    make_float2(Ofr[j2][rr ? 2 : 0], Ofr[j2][rr ? 3 : 1]);
            }
            if (q == 0) {
                pm[base] = (rr == 0) ? m_a : m_b;
                pl[base] = (rr == 0) ? l_a : l_b;
            }
        }
        return;
    }

    float ia = 1.f / l_a, ib = 1.f / l_b;
    if (!GATHER) {
        float* oa = out0 + (long long)bh * L_ * DH + (long long)row_a * DH;
        float* ob = out0 + (long long)bh * L_ * DH + (long long)row_b * DH;
        #pragma unroll
        for (int j2 = 0; j2 < DH/8; j2++) {
            int col = 8*j2 + 2*q;
            *(float2*)(oa + col) = make_float2(Ofr[j2][0]*ia, Ofr[j2][1]*ia);
            *(float2*)(ob + col) = make_float2(Ofr[j2][2]*ib, Ofr[j2][3]*ib);
        }
    } else {
        #pragma unroll
        for (int rr = 0; rr < 2; rr++) {
            int s_abs = (rr == 0) ? row_a : row_b;
            float inv = (rr == 0) ? ia : ib;
            float* dst;
            if (s_abs < SL_ + SEG_) {
                int s = s_abs - SL_;
                dst = out0 + (long long)b * o0b
                    + (long long)((h << 5) + (s >> 4)) * 2048 + ((s & 15) << 7);
            } else {
                int s = s_abs - (SL_ + SEG_);
                dst = out1 + ((long long)b * SL_ + (h << 3) + (s >> 4)) * 2048
                    + ((s & 15) << 7);
            }
            #pragma unroll
            for (int j2 = 0; j2 < DH/8; j2++) {
                int col = 8*j2 + 2*q;
                float v0 = Ofr[j2][rr ? 2 : 0] * inv;
                float v1 = Ofr[j2][rr ? 3 : 1] * inv;
                *(float2*)(dst + col) = make_float2(v0, v1);
            }
        }
    }
}

// merge 4 split-KV partials (DH=128) -> gathered a2e layout
__global__ void mergeKV(float* __restrict__ a2e, const float* __restrict__ pO,
                        const float* __restrict__ pm, const float* __restrict__ pl)
{
    int idx = blockIdx.x * blockDim.x + threadIdx.x;
    const int tot = B_ * H_ * SL_ * 128;
    if (idx >= tot) return;
    int col = idx & 127;
    int r   = (idx >> 7) & 127;
    int bh  = idx >> 14;
    int b = bh / H_, h = bh - b * H_;
    const int P = B_ * H_ * SL_;
    float M = -1e30f;
    #pragma unroll
    for (int s = 0; s < 4; s++) M = fmaxf(M, pm[s*P + bh*SL_ + r]);
    float num = 0.f, den = 0.f;
    #pragma unroll
    for (int s = 0; s < 4; s++) {
        float wgt = __expf(pm[s*P + bh*SL_ + r] - M);
        den += wgt * pl[s*P + bh*SL_ + r];
        num += wgt * pO[((long long)s*P + (long long)bh*SL_ + r) * 128 + col];
    }
    a2e[((long long)(b * SL_ + (h << 3) + (r >> 4))) * 2048 + ((r & 15) << 7) + col]
        = num / den;
}

// merge 2 split-KV partials (DH=64) -> dense att1
__global__ void merge1(float* __restrict__ att1, const float* __restrict__ pO,
                       const float* __restrict__ pm, const float* __restrict__ pl)
{
    int idx = blockIdx.x * blockDim.x + threadIdx.x;
    const int tot = B_ * H_ * L_ * 64;
    if (idx >= tot) return;
    int col = idx & 63;
    int r   = (idx >> 6) % L_;
    int bh  = idx / (L_ * 64);
    const int P = B_ * H_ * L_;
    float m0 = pm[bh*L_ + r], m1 = pm[P + bh*L_ + r];
    float M = fmaxf(m0, m1);
    float w0 = __expf(m0 - M), w1 = __expf(m1 - M);
    float O0 = pO[((long long)bh*L_ + r) * 64 + col];
    float O1 = pO[((long long)P + (long long)bh*L_ + r) * 64 + col];
    att1[((long long)bh*L_ + r) * 64 + col]
        = (w0*O0 + w1*O1) / (w0*pl[bh*L_ + r] + w1*pl[P + bh*L_ + r]);
}

// generic split-K reduce
__global__ void reduceK(float* __restrict__ C, const float* __restrict__ part,
    int sk, long long chunk, int M, int N, int ldc,
    long long cSB, long long cSH, int Hd)
{
    long long idx = (long long)blockIdx.x * blockDim.x + threadIdx.x;
    if (idx >= chunk) return;
    int n = (int)(idx % N);
    long long t = idx / N;
    int m = (int)(t % M);
    int zz = (int)(t / M);
    int b = zz / Hd, h = zz - b * Hd;
    float s = 0.f;
    for (int i = 0; i < sk; i++) s += part[(long long)i * chunk + idx];
    C[(long long)b * cSB + (long long)h * cSH + (long long)m * ldc + n] = s;
}

// transposed packs: dst is [N][K] row-major
__global__ void packHT(float* __restrict__ dst, const float* __restrict__ s0,
                       const float* __restrict__ s1, const float* __restrict__ s2)
{
    int idx = blockIdx.x * blockDim.x + threadIdx.x;
    const int tot = 3072 * D_;
    if (idx >= tot) return;
    int d = idx & 1023;
    int n = idx >> 10;
    int c = n & 63;
    int o = (n >> 6) % 3;
    int h = n / 192;
    const float* s = (o == 0) ? s0 : ((o == 1) ? s1 : s2);
    dst[idx] = s[((size_t)h * D_ + d) * 64 + c];
}

__global__ void packW2T(float* __restrict__ dst, const float* __restrict__ s0,
                        const float* __restrict__ s1, const float* __restrict__ s2)
{
    int idx = blockIdx.x * blockDim.x + threadIdx.x;
    const int tot = H_ * 384 * 64;
    if (idx >= tot) return;
    int d = idx & 63;
    int n = (idx >> 6) % 384;
    int h = idx / (384 * 64);
    int c = n & 127;
    int o = n >> 7;
    const float* s = (o == 0) ? s0 : ((o == 1) ? s1 : s2);
    dst[idx] = s[((size_t)h * 64 + d) * 128 + c];
}

__global__ void packOT(float* __restrict__ dst, const float* __restrict__ src)
{
    int idx = blockIdx.x * blockDim.x + threadIdx.x;
    const int tot = D_ * 2048;
    if (idx >= tot) return;
    int k = idx & 2047;
    int n = idx >> 11;
    dst[idx] = src[(size_t)k * D_ + n];
}

__global__ void bcast_state(float* __restrict__ st, const float* __restrict__ state)
{
    int idx = blockIdx.x * blockDim.x + threadIdx.x;
    const int total = B_ * SL_ * D_;
    if (idx >= total) return;
    st[idx] = state[idx % (SL_ * D_)];
}

__global__ void copy_f(float* __restrict__ dst, const float* __restrict__ src, int n)
{
    int idx = blockIdx.x * blockDim.x + threadIdx.x;
    if (idx < n) dst[idx] = src[idx];
}

// ---------------- host ----------------
static float* s_part = nullptr;

static void G(const float* A, const float* Bm, float* C,
              int M, int N, int K, int lda, int ldb, int ldc,
              long long aSB, long long aSH, long long bSB, long long bSH,
              long long cSB, long long cSH, int Hd, int Z, int sk = 1,
              int useTab = 0, BTab tab = {}, cudaStream_t st = 0)
{
    int Kc = K / sk;
    long long pcs = 0;
    float* Cout = C;
    long long csb = cSB, csh = cSH;
    int ldc2 = ldc;
    if (sk > 1) {
        pcs = (long long)Z * M * N;
        Cout = s_part; ldc2 = N;
        csh = (long long)M * N;
        csb = (long long)Hd * M * N;
    }
    if (N % 128 == 0) {
        dim3 grid(N / 128, (M + 127) / 128, Z * sk);
        gemm_t<128,128,64,32,256><<<grid, 256, 0, st>>>(A, Bm, Cout, M, N, K, lda, ldb, ldc2,
            aSB, aSH, bSB, bSH, csb, csh, Hd, Z, sk, Kc, pcs, useTab, tab);
    } else {
        dim3 grid(N / 64, (M + 127) / 128, Z * sk);
        gemm_t<128,64,64,32,128><<<grid, 128, 0, st>>>(A, Bm, Cout, M, N, K, lda, ldb, ldc2,
            aSB, aSH, bSB, bSH, csb, csh, Hd, Z, sk, Kc, pcs, useTab, tab);
    }
    if (sk > 1) {
        long long chunk = (long long)Z * M * N;
        reduceK<<<(unsigned)((chunk + 255) / 256), 256, 0, st>>>(C, s_part, sk, chunk,
            M, N, ldc, cSB, cSH, Hd);
    }
}

extern "C" void kernel_launch(void* const* d_in, const int* in_sizes, int n_in,
                              void* d_out, int out_size)
{
    const float* x       = (const float*)d_in[0];
    const float* state   = (const float*)d_in[1];
    const float* Wk      = (const float*)d_in[2];
    const float* Wq      = (const float*)d_in[3];
    const float* Wv      = (const float*)d_in[4];
    const float* W2k     = (const float*)d_in[5];
    const float* Wout    = (const float*)d_in[6];
    const float* Wk_st   = (const float*)d_in[7];
    const float* Wq_st   = (const float*)d_in[8];
    const float* Wv_st   = (const float*)d_in[9];
    const float* W2k_ss  = (const float*)d_in[10];
    const float* W2q_ss  = (const float*)d_in[11];
    const float* W2v_ss  = (const float*)d_in[12];
    const float* W2k_se  = (const float*)d_in[13];
    const float* W2q_se  = (const float*)d_in[14];
    const float* W2v_se  = (const float*)d_in[15];
    const float* Wout_st = (const float*)d_in[16];
    float* out = (float*)d_out;

    float *kqvf,*stp,*att1,*kqv2,*a2r,*a2e,*stA,*stB,*pO,*pm,*pl;
    float *WkqvFT,*WstPT,*W2ssT,*W2midT,*W2seT,*WoutT,*WoutStT;
    cudaGetSymbolAddress((void**)&kqvf, g_kqvf);
    cudaGetSymbolAddress((void**)&stp,  g_stp);
    cudaGetSymbolAddress((void**)&att1, g_att1);
    cudaGetSymbolAddress((void**)&kqv2, g_kqv2);
    cudaGetSymbolAddress((void**)&a2r,  g_a2r);
    cudaGetSymbolAddress((void**)&a2e,  g_a2e);
    cudaGetSymbolAddress((void**)&stA,  g_stA);
    cudaGetSymbolAddress((void**)&stB,  g_stB);
    cudaGetSymbolAddress((void**)&s_part, g_part);
    cudaGetSymbolAddress((void**)&pO, g_pO);
    cudaGetSymbolAddress((void**)&pm, g_pm);
    cudaGetSymbolAddress((void**)&pl, g_pl);
    cudaGetSymbolAddress((void**)&WkqvFT, g_WkqvFT);
    cudaGetSymbolAddress((void**)&WstPT,  g_WstPT);
    cudaGetSymbolAddress((void**)&W2ssT,  g_W2ssT);
    cudaGetSymbolAddress((void**)&W2midT, g_W2midT);
    cudaGetSymbolAddress((void**)&W2seT,  g_W2seT);
    cudaGetSymbolAddress((void**)&WoutT,  g_WoutT);
    cudaGetSymbolAddress((void**)&WoutStT,g_WoutStT);

    const int SM64  = (128*(64+24) + 64*(64+24) + 64*(64+4) + 128*(64+24)) * 4;
    const int SM128 = (128*(128+24) + 64*(128+24) + 128*(64+4) + 128*(64+24)) * 4;
    cudaFuncSetAttribute(flash_k<64,false>,  cudaFuncAttributeMaxDynamicSharedMemorySize, SM64);
    cudaFuncSetAttribute(flash_k<128,true>,  cudaFuncAttributeMaxDynamicSharedMemorySize, SM128);

    static cudaStream_t s2 = nullptr;
    static cudaEvent_t evF[NSEG_];
    static cudaEvent_t evJ = nullptr;
    if (!s2) {
        cudaStreamCreateWithFlags(&s2, cudaStreamNonBlocking);
        for (int i = 0; i < NSEG_; i++)
            cudaEventCreateWithFlags(&evF[i], cudaEventDisableTiming);
        cudaEventCreateWithFlags(&evJ, cudaEventDisableTiming);
    }

    BTab tab2; // level-2 projections: rows 0-127 ss, 128-639 mid, 640-767 se
    tab2.p[0] = W2ssT; tab2.p[1] = W2midT; tab2.p[2] = W2midT;
    tab2.p[3] = W2midT; tab2.p[4] = W2midT; tab2.p[5] = W2seT;
    tab2.p[6] = W2midT; tab2.p[7] = W2midT;

    bool tailFits = (out_size >= B_*S_*D_ + B_*SL_*D_);
    const long long KQV2SEG = (long long)B_*H_*L_*384;

    bcast_state<<<(B_*SL_*D_ + 255)/256, 256>>>(stA, state);
    packHT<<<(3072*D_ + 255)/256, 256>>>(WkqvFT, Wk, Wq, Wv);
    packHT<<<(3072*D_ + 255)/256, 256>>>(WstPT, Wk_st, Wq_st, Wv_st);
    G(x, WkqvFT, kqvf, S_, 192, D_, D_, D_, 192,
      (long long)S_*D_, 0, 0, (long long)192*D_,
      (long long)H_*S_*192, (long long)S_*192, H_, B_*H_);

    for (int seg = 0; seg < NSEG_; seg++) {
        float* stc = (seg & 1) ? stB : stA;
        float* stn = (seg & 1) ? stA : stB;
        if (seg == NSEG_-1 && tailFits) stn = out + (size_t)B_*S_*D_;
        float* kqv2s = kqv2 + (long long)seg * KQV2SEG;

        // state K|Q|V projection -> stp
        G(stc, WstPT, stp, SL_, 192, D_, D_, D_, 192,
          (long long)SL_*D_, 0, 0, (long long)192*D_,
          (long long)H_*SL_*192, (long long)SL_*192, H_, B_*H_);

        // attention 1: split-KV z=2 partial
        flash_k<64,false><<<dim3(L_/128, B_*H_, 2), 256, SM64>>>(
            stp, kqvf + (long long)seg*SEG_*192, 192,
            (long long)SL_*192, (long long)S_*192, 64, 0, 128,
            nullptr, 0, nullptr, 0, pO, pm, pl, 2, L_, 0);

        if (seg == 0) {  // one-time transposed packs (ordered before first use)
            packW2T<<<(H_*384*64 + 255)/256, 256>>>(W2ssT,  W2k_ss, W2q_ss, W2v_ss);
            packW2T<<<(H_*384*64 + 255)/256, 256>>>(W2midT, W2k,    W2k,    W2k);
            packW2T<<<(H_*384*64 + 255)/256, 256>>>(W2seT,  W2k_se, W2q_se, W2v_se);
            packOT<<<(D_*2048 + 255)/256, 256>>>(WoutT,   Wout);
            packOT<<<(D_*2048 + 255)/256, 256>>>(WoutStT, Wout_st);
        }

        merge1<<<(B_*H_*L_*64 + 255)/256, 256>>>(att1, pO, pm, pl);

        // level-2 projections into per-seg kqv2 buffer
        G(att1, nullptr, kqv2s, L_, 384, DV_, DV_, 64, 384,
          (long long)H_*L_*DV_, (long long)L_*DV_, 0, (long long)384*64,
          (long long)H_*L_*384, (long long)L_*384, H_, B_*H_, 1, 1, tab2);

        // fork: a2r row-blocks + out-GEMM on side stream
        cudaEventRecord(evF[seg], 0);
        cudaStreamWaitEvent(s2, evF[seg], 0);
        flash_k<128,true><<<dim3(4, B_*H_), 256, SM128, s2>>>(
            kqv2s, nullptr, 384, (long long)L_*384, 0, 128, 0, 256,
            a2r + (long long)seg*SEG_*2048, (long long)NSEG_*SEG_*2048, a2e,
            1, nullptr, nullptr, nullptr, 0, 0, 0);
        G(a2r + (long long)seg*SEG_*2048, WoutT, out + (size_t)seg*SEG_*D_,
          SEG_, D_, 2048, 2048, 2048, D_,
          (long long)NSEG_*SEG_*2048, 0, 0, 0, (long long)S_*D_, 0, 1, B_,
          1, 0, BTab{}, s2);

        // critical path: split-KV z=4 flash for a2e rows, then merge
        flash_k<128,true><<<dim3(1, B_*H_, 4), 256, SM128>>>(
            kqv2s, nullptr, 384, (long long)L_*384, 0, 128, 0, 256,
            a2r + (long long)seg*SEG_*2048, (long long)NSEG_*SEG_*2048, a2e,
            5, pO, pm, pl, 4, SL_, 640);
        mergeKV<<<(B_*H_*SL_*128 + 255)/256, 256>>>(a2e, pO, pm, pl);

        // next state (split-K x8)
        G(a2e, WoutStT, stn, SL_, D_, 2048, 2048, 2048, D_,
          (long long)SL_*2048, 0, 0, 0, (long long)SL_*D_, 0, 1, B_, 8);
    }

    // join side stream back into origin stream
    cudaEventRecord(evJ, s2);
    cudaStreamWaitEvent(0, evJ, 0);

    if (!tailFits) {
        int st_elems = B_ * SL_ * D_;
        if (out_size >= B_*S_*D_ + st_elems) {
            copy_f<<<(st_elems + 255)/256, 256>>>(out + (size_t)B_*S_*D_, stA, st_elems);
        }
    }
}